// round 1
// baseline (speedup 1.0000x reference)
#include <cuda_runtime.h>
#include <math.h>

// Problem constants
#define Bb 2
#define Cc 768
#define Tt 2048
#define Ii 768
#define Hh 12
#define Dh 64
#define Ss 16
#define Cx 512
#define Fi 3072
#define Dd 2
#define Ksz 9

// ---------------- scratch (static device globals; no allocation) ----------------
__device__ float g_gn [(long long)Bb*Cc*Tt];
__device__ float g_h  [(long long)Bb*Tt*Ii];
__device__ float g_y  [(long long)Bb*Tt*Ii];
__device__ float g_q  [(long long)Bb*Tt*Ii];
__device__ float g_k  [(long long)Bb*Tt*Ii];
__device__ float g_v  [(long long)Bb*Tt*Ii];
__device__ float g_att[(long long)Bb*Tt*Ii];
__device__ float g_sc [(long long)Bb*Hh*Tt*Tt];   // 400 MB attention scores
__device__ float g_ffa[(long long)Bb*Fi*Tt];      // conv1 output
__device__ float g_yT [(long long)Bb*Ii*Tt];
__device__ float g_ffb[(long long)Bb*Ii*Tt];
__device__ float g_kc [(long long)Bb*Ss*Ii];
__device__ float g_vc [(long long)Bb*Ss*Ii];

// ---------------- reductions ----------------
__device__ __forceinline__ float blockReduceSum(float v) {
    __shared__ float sm[32];
    int lane = threadIdx.x & 31, wid = threadIdx.x >> 5;
    #pragma unroll
    for (int o = 16; o; o >>= 1) v += __shfl_xor_sync(0xffffffffu, v, o);
    if (lane == 0) sm[wid] = v;
    __syncthreads();
    if (wid == 0) {
        int nw = (blockDim.x + 31) >> 5;
        v = (lane < nw) ? sm[lane] : 0.f;
        #pragma unroll
        for (int o = 16; o; o >>= 1) v += __shfl_xor_sync(0xffffffffu, v, o);
        if (lane == 0) sm[0] = v;
    }
    __syncthreads();
    float r = sm[0];
    __syncthreads();
    return r;
}

__device__ __forceinline__ float blockReduceMax(float v) {
    __shared__ float sm[32];
    int lane = threadIdx.x & 31, wid = threadIdx.x >> 5;
    #pragma unroll
    for (int o = 16; o; o >>= 1) v = fmaxf(v, __shfl_xor_sync(0xffffffffu, v, o));
    if (lane == 0) sm[wid] = v;
    __syncthreads();
    if (wid == 0) {
        int nw = (blockDim.x + 31) >> 5;
        v = (lane < nw) ? sm[lane] : -INFINITY;
        #pragma unroll
        for (int o = 16; o; o >>= 1) v = fmaxf(v, __shfl_xor_sync(0xffffffffu, v, o));
        if (lane == 0) sm[0] = v;
    }
    __syncthreads();
    float r = sm[0];
    __syncthreads();
    return r;
}

// ---------------- groupnorm ----------------
__global__ void groupnorm_kernel(const float* __restrict__ x, const float* __restrict__ sc,
                                 const float* __restrict__ bi, float* __restrict__ out) {
    const int CPG = Cc / 32;                // 24
    int b = blockIdx.x >> 5, g = blockIdx.x & 31;
    const long long base = ((long long)b * Cc + (long long)g * CPG) * Tt;
    const float* xp = x + base;
    float* op = out + base;
    const int n = CPG * Tt;
    float s = 0.f, ss = 0.f;
    for (int i = threadIdx.x; i < n; i += blockDim.x) {
        float v = xp[i]; s += v; ss = fmaf(v, v, ss);
    }
    s  = blockReduceSum(s);
    ss = blockReduceSum(ss);
    float mean = s / n;
    float inv  = rsqrtf(ss / n - mean * mean + 1e-6f);
    for (int i = threadIdx.x; i < n; i += blockDim.x) {
        int c = g * CPG + i / Tt;
        op[i] = (xp[i] - mean) * inv * sc[c] + bi[c];
    }
}

// ---------------- layernorm ----------------
__global__ void layernorm_kernel(const float* __restrict__ x, const float* __restrict__ sc,
                                 const float* __restrict__ bi, float* __restrict__ out) {
    const float* row = x + (long long)blockIdx.x * Ii;
    float* orow = out + (long long)blockIdx.x * Ii;
    float s = 0.f, ss = 0.f;
    for (int i = threadIdx.x; i < Ii; i += blockDim.x) {
        float v = row[i]; s += v; ss = fmaf(v, v, ss);
    }
    s  = blockReduceSum(s);
    ss = blockReduceSum(ss);
    float mean = s / (float)Ii;
    float inv  = rsqrtf(ss / (float)Ii - mean * mean + 1e-5f);
    for (int i = threadIdx.x; i < Ii; i += blockDim.x)
        orow[i] = (row[i] - mean) * inv * sc[i] + bi[i];
}

// ---------------- generic tiled GEMM ----------------
// C = alpha*op(A)*op(B) + bias + beta*C  (beta in {0,1})
// tA: A stored [K,M] (use A[k*lda+m]); else [M,K]. tB: B stored [N,K]; else [K,N].
// biasMode: 0 none, 1 per-n, 2 per-m. Two-level batch: z1 = bz/b2, z2 = bz%b2.
__global__ void __launch_bounds__(256) gemm_kernel(
    const float* __restrict__ A, const float* __restrict__ B,
    const float* __restrict__ bias, float* __restrict__ Cp,
    int M, int N, int K, int lda, int ldb, int ldc,
    int tA, int tB, int biasMode, float alpha, float beta,
    int b2, long long sA1, long long sA2, long long sB1, long long sB2,
    long long sC1, long long sC2)
{
    int bz = blockIdx.z;
    int z1 = bz / b2, z2 = bz % b2;
    A  += z1 * sA1 + z2 * sA2;
    B  += z1 * sB1 + z2 * sB2;
    Cp += z1 * sC1 + z2 * sC2;
    __shared__ float As[16][65];
    __shared__ float Bs[16][65];
    int n0 = blockIdx.x * 64, m0 = blockIdx.y * 64;
    int tid = threadIdx.x;
    int tx = tid & 15, ty = tid >> 4;
    float acc[4][4] = {};
    for (int k0 = 0; k0 < K; k0 += 16) {
        #pragma unroll
        for (int u = 0; u < 4; ++u) {
            int i = tid + u * 256;
            int mm, kk;
            if (!tA) { mm = i >> 4; kk = i & 15; }
            else     { kk = i >> 6; mm = i & 63; }
            int m = m0 + mm, k = k0 + kk;
            float v = 0.f;
            if (m < M && k < K)
                v = tA ? A[(long long)k * lda + m] : A[(long long)m * lda + k];
            As[kk][mm] = v;
        }
        #pragma unroll
        for (int u = 0; u < 4; ++u) {
            int i = tid + u * 256;
            int kk, nn;
            if (!tB) { kk = i >> 6; nn = i & 63; }
            else     { nn = i >> 4; kk = i & 15; }
            int k = k0 + kk, n = n0 + nn;
            float v = 0.f;
            if (k < K && n < N)
                v = tB ? B[(long long)n * ldb + k] : B[(long long)k * ldb + n];
            Bs[kk][nn] = v;
        }
        __syncthreads();
        #pragma unroll
        for (int kk = 0; kk < 16; ++kk) {
            float a[4], bb[4];
            #pragma unroll
            for (int i = 0; i < 4; ++i) a[i] = As[kk][ty * 4 + i];
            #pragma unroll
            for (int j = 0; j < 4; ++j) bb[j] = Bs[kk][tx * 4 + j];
            #pragma unroll
            for (int i = 0; i < 4; ++i)
                #pragma unroll
                for (int j = 0; j < 4; ++j)
                    acc[i][j] = fmaf(a[i], bb[j], acc[i][j]);
        }
        __syncthreads();
    }
    #pragma unroll
    for (int i = 0; i < 4; ++i) {
        int m = m0 + ty * 4 + i;
        if (m >= M) continue;
        #pragma unroll
        for (int j = 0; j < 4; ++j) {
            int n = n0 + tx * 4 + j;
            if (n >= N) continue;
            float v = alpha * acc[i][j];
            if (biasMode == 1) v += bias[n];
            else if (biasMode == 2) v += bias[m];
            long long idx = (long long)m * ldc + n;
            if (beta != 0.f) v += Cp[idx];
            Cp[idx] = v;
        }
    }
}

// ---------------- softmax (rows of 2048, register-cached) ----------------
__global__ void softmax_kernel(float* __restrict__ s) {
    float* row = s + (long long)blockIdx.x * Tt;
    int tid = threadIdx.x;
    float v[8];
    float mx = -INFINITY;
    #pragma unroll
    for (int i = 0; i < 8; ++i) { v[i] = row[tid + (i << 8)]; mx = fmaxf(mx, v[i]); }
    mx = blockReduceMax(mx);
    float sum = 0.f;
    #pragma unroll
    for (int i = 0; i < 8; ++i) { v[i] = expf(v[i] - mx); sum += v[i]; }
    sum = blockReduceSum(sum);
    float inv = 1.f / sum;
    #pragma unroll
    for (int i = 0; i < 8; ++i) row[tid + (i << 8)] = v[i] * inv;
}

// ---------------- cross attention (16 keys): one warp per (b,h,t) ----------------
__global__ void crossattn_kernel(const float* __restrict__ q, const float* __restrict__ kc,
                                 const float* __restrict__ vc, float* __restrict__ out) {
    int gw = blockIdx.x * (blockDim.x >> 5) + (threadIdx.x >> 5);
    int lane = threadIdx.x & 31;
    int t = gw % Tt;
    int rem = gw / Tt;
    int h = rem % Hh;
    int b = rem / Hh;
    const float* qp = q + ((long long)(b * Tt + t)) * Ii + h * Dh;
    const float* kb = kc + (long long)b * Ss * Ii + h * Dh;
    const float* vb = vc + (long long)b * Ss * Ii + h * Dh;
    float sj = -INFINITY;
    if (lane < Ss) {
        const float* kp = kb + lane * Ii;
        float acc = 0.f;
        #pragma unroll
        for (int d2 = 0; d2 < Dh; ++d2) acc = fmaf(qp[d2], kp[d2], acc);
        sj = acc * 0.125f;   // dh^-0.5
    }
    float mx = sj;
    #pragma unroll
    for (int o = 16; o; o >>= 1) mx = fmaxf(mx, __shfl_xor_sync(0xffffffffu, mx, o));
    float p = (lane < Ss) ? expf(sj - mx) : 0.f;
    float sum = p;
    #pragma unroll
    for (int o = 16; o; o >>= 1) sum += __shfl_xor_sync(0xffffffffu, sum, o);
    p /= sum;
    float o0 = 0.f, o1 = 0.f;
    #pragma unroll
    for (int j = 0; j < Ss; ++j) {
        float pj = __shfl_sync(0xffffffffu, p, j);
        const float* vp = vb + j * Ii;
        o0 = fmaf(pj, vp[lane], o0);
        o1 = fmaf(pj, vp[lane + 32], o1);
    }
    float* op = out + ((long long)(b * Tt + t)) * Ii + h * Dh;
    op[lane] = o0;
    op[lane + 32] = o1;
}

// ---------------- transpose (and transpose+add) ----------------
// in: [R, Ccol] per batch, out: [Ccol, R] per batch, batch stride R*Ccol both sides.
template <bool ADD>
__global__ void transpose_kernel(const float* __restrict__ in, float* __restrict__ out,
                                 int R, int Ccol) {
    __shared__ float tile[32][33];
    long long bo = (long long)blockIdx.z * R * Ccol;
    const float* ip = in + bo;
    float* op = out + bo;
    int r0 = blockIdx.x * 32, c0 = blockIdx.y * 32;
    #pragma unroll
    for (int i = 0; i < 32; i += 8)
        tile[threadIdx.y + i][threadIdx.x] =
            ip[(long long)(r0 + threadIdx.y + i) * Ccol + c0 + threadIdx.x];
    __syncthreads();
    #pragma unroll
    for (int i = 0; i < 32; i += 8) {
        long long idx = (long long)(c0 + threadIdx.y + i) * R + r0 + threadIdx.x;
        float v = tile[threadIdx.x][threadIdx.y + i];
        if (ADD) op[idx] += v; else op[idx] = v;
    }
}

// ---------------- conv1d (implicit GEMM, K=9, pad=4) ----------------
// x: [Cin, T] per batch, w: [Cout, Cin, 9], out: [Cout, T] per batch.
__global__ void __launch_bounds__(256) conv1d_kernel(
    const float* __restrict__ x, const float* __restrict__ w,
    const float* __restrict__ bias, float* __restrict__ out,
    int Cin, int Cout, int applyGelu)
{
    int b = blockIdx.z;
    x   += (long long)b * Cin * Tt;
    out += (long long)b * Cout * Tt;
    int t0 = blockIdx.x * 64, o0 = blockIdx.y * 64;
    __shared__ float xs[8][76];    // 72 used (64 + 8 halo)
    __shared__ float ws[64][73];   // 72 used (8c * 9k)
    int tid = threadIdx.x;
    int tx = tid & 15, ty = tid >> 4;
    int ty4 = ty * 4;
    float acc[4][4] = {};
    for (int c0 = 0; c0 < Cin; c0 += 8) {
        for (int i = tid; i < 8 * 72; i += 256) {
            int c = i / 72, j = i % 72;
            int t = t0 + j - 4;
            xs[c][j] = (t >= 0 && t < Tt) ? x[(long long)(c0 + c) * Tt + t] : 0.f;
        }
        for (int i = tid; i < 64 * 72; i += 256) {
            int o = i / 72, r = i % 72;
            ws[o][r] = w[(long long)(o0 + o) * Cin * 9 + (long long)c0 * 9 + r];
        }
        __syncthreads();
        #pragma unroll
        for (int c = 0; c < 8; ++c) {
            float xr[12];
            #pragma unroll
            for (int j = 0; j < 12; ++j) xr[j] = xs[c][tx * 4 + j];
            #pragma unroll
            for (int k = 0; k < 9; ++k) {
                float w0 = ws[ty4 + 0][c * 9 + k];
                float w1 = ws[ty4 + 1][c * 9 + k];
                float w2 = ws[ty4 + 2][c * 9 + k];
                float w3 = ws[ty4 + 3][c * 9 + k];
                #pragma unroll
                for (int j = 0; j < 4; ++j) {
                    float xv = xr[k + j];
                    acc[0][j] = fmaf(w0, xv, acc[0][j]);
                    acc[1][j] = fmaf(w1, xv, acc[1][j]);
                    acc[2][j] = fmaf(w2, xv, acc[2][j]);
                    acc[3][j] = fmaf(w3, xv, acc[3][j]);
                }
            }
        }
        __syncthreads();
    }
    #pragma unroll
    for (int i = 0; i < 4; ++i) {
        int o = o0 + ty4 + i;
        float bv = bias[o];
        #pragma unroll
        for (int j = 0; j < 4; ++j) {
            int t = t0 + tx * 4 + j;
            float v = acc[i][j] + bv;
            if (applyGelu) v = 0.5f * v * (1.f + erff(v * 0.70710678118654752f));
            out[(long long)o * Tt + t] = v;
        }
    }
}

// ---------------- host-side GEMM wrapper ----------------
static void launch_gemm(const float* A, const float* B, const float* bias, float* C,
                        int M, int N, int K, int lda, int ldb, int ldc,
                        int tA, int tB, int biasMode, float alpha, float beta,
                        int nz, int b2,
                        long long sA1, long long sA2, long long sB1, long long sB2,
                        long long sC1, long long sC2)
{
    dim3 grid((N + 63) / 64, (M + 63) / 64, nz);
    gemm_kernel<<<grid, 256>>>(A, B, bias, C, M, N, K, lda, ldb, ldc,
                               tA, tB, biasMode, alpha, beta,
                               b2, sA1, sA2, sB1, sB2, sC1, sC2);
}

extern "C" void kernel_launch(void* const* d_in, const int* in_sizes, int n_in,
                              void* d_out, int out_size) {
    const float* x      = (const float*)d_in[0];
    const float* ctx    = (const float*)d_in[1];
    const float* gn_s   = (const float*)d_in[2];
    const float* gn_b   = (const float*)d_in[3];
    const float* pin_w  = (const float*)d_in[4];
    const float* pin_b  = (const float*)d_in[5];
    const float* n1_s   = (const float*)d_in[6];
    const float* n1_b   = (const float*)d_in[7];
    const float* a1_wq  = (const float*)d_in[8];
    const float* a1_wk  = (const float*)d_in[9];
    const float* a1_wv  = (const float*)d_in[10];
    const float* a1_wo  = (const float*)d_in[11];
    const float* a1_bo  = (const float*)d_in[12];
    const float* n2_s   = (const float*)d_in[13];
    const float* n2_b   = (const float*)d_in[14];
    const float* a2_wq  = (const float*)d_in[15];
    const float* a2_wk  = (const float*)d_in[16];
    const float* a2_wv  = (const float*)d_in[17];
    const float* a2_wo  = (const float*)d_in[18];
    const float* a2_bo  = (const float*)d_in[19];
    const float* n3_s   = (const float*)d_in[20];
    const float* n3_b   = (const float*)d_in[21];
    const float* ff1_w  = (const float*)d_in[22];
    const float* ff1_b  = (const float*)d_in[23];
    const float* ff2_w  = (const float*)d_in[24];
    const float* ff2_b  = (const float*)d_in[25];
    const float* pout_w = (const float*)d_in[26];
    const float* pout_b = (const float*)d_in[27];
    float* out = (float*)d_out;

    float *gn, *h, *y, *q, *k, *v, *att, *sc, *ffa, *yT, *ffb, *kcb, *vcb;
    cudaGetSymbolAddress((void**)&gn,  g_gn);
    cudaGetSymbolAddress((void**)&h,   g_h);
    cudaGetSymbolAddress((void**)&y,   g_y);
    cudaGetSymbolAddress((void**)&q,   g_q);
    cudaGetSymbolAddress((void**)&k,   g_k);
    cudaGetSymbolAddress((void**)&v,   g_v);
    cudaGetSymbolAddress((void**)&att, g_att);
    cudaGetSymbolAddress((void**)&sc,  g_sc);
    cudaGetSymbolAddress((void**)&ffa, g_ffa);
    cudaGetSymbolAddress((void**)&yT,  g_yT);
    cudaGetSymbolAddress((void**)&ffb, g_ffb);
    cudaGetSymbolAddress((void**)&kcb, g_kc);
    cudaGetSymbolAddress((void**)&vcb, g_vc);

    // 1) GroupNorm
    groupnorm_kernel<<<Bb * 32, 256>>>(x, gn_s, gn_b, gn);

    // 2) proj_in: h[b,t,i] = sum_c pin_w[i,c] * gn[b,c,t] + pin_b[i]
    launch_gemm(gn, pin_w, pin_b, h,
                Tt, Ii, Cc, Tt, Cc, Ii, /*tA=*/1, /*tB=*/1, /*bias n*/1, 1.f, 0.f,
                Bb, 1, (long long)Cc * Tt, 0, 0, 0, (long long)Tt * Ii, 0);

    for (int d = 0; d < Dd; ++d) {
        long long wofs = (long long)d * Ii * Ii;

        // --- self attention ---
        layernorm_kernel<<<Bb * Tt, 256>>>(h, n1_s + d * Ii, n1_b + d * Ii, y);
        launch_gemm(y, a1_wq + wofs, nullptr, q, Bb * Tt, Ii, Ii, Ii, Ii, Ii,
                    0, 0, 0, 1.f, 0.f, 1, 1, 0, 0, 0, 0, 0, 0);
        launch_gemm(y, a1_wk + wofs, nullptr, k, Bb * Tt, Ii, Ii, Ii, Ii, Ii,
                    0, 0, 0, 1.f, 0.f, 1, 1, 0, 0, 0, 0, 0, 0);
        launch_gemm(y, a1_wv + wofs, nullptr, v, Bb * Tt, Ii, Ii, Ii, Ii, Ii,
                    0, 0, 0, 1.f, 0.f, 1, 1, 0, 0, 0, 0, 0, 0);
        // scores[b,h] = 0.125 * q_head @ k_head^T
        launch_gemm(q, k, nullptr, sc, Tt, Tt, Dh, Ii, Ii, Tt, 0, 1, 0, 0.125f, 0.f,
                    Bb * Hh, Hh,
                    (long long)Tt * Ii, Dh, (long long)Tt * Ii, Dh,
                    (long long)Hh * Tt * Tt, (long long)Tt * Tt);
        softmax_kernel<<<Bb * Hh * Tt, 256>>>(sc);
        // att_head = scores @ v_head
        launch_gemm(sc, v, nullptr, att, Tt, Dh, Tt, Tt, Ii, Ii, 0, 0, 0, 1.f, 0.f,
                    Bb * Hh, Hh,
                    (long long)Hh * Tt * Tt, (long long)Tt * Tt,
                    (long long)Tt * Ii, Dh, (long long)Tt * Ii, Dh);
        // h += att @ wo + bo
        launch_gemm(att, a1_wo + wofs, a1_bo + d * Ii, h,
                    Bb * Tt, Ii, Ii, Ii, Ii, Ii, 0, 0, 1, 1.f, 1.f,
                    1, 1, 0, 0, 0, 0, 0, 0);

        // --- cross attention ---
        layernorm_kernel<<<Bb * Tt, 256>>>(h, n2_s + d * Ii, n2_b + d * Ii, y);
        launch_gemm(y, a2_wq + wofs, nullptr, q, Bb * Tt, Ii, Ii, Ii, Ii, Ii,
                    0, 0, 0, 1.f, 0.f, 1, 1, 0, 0, 0, 0, 0, 0);
        launch_gemm(ctx, a2_wk + (long long)d * Cx * Ii, nullptr, kcb,
                    Bb * Ss, Ii, Cx, Cx, Ii, Ii, 0, 0, 0, 1.f, 0.f,
                    1, 1, 0, 0, 0, 0, 0, 0);
        launch_gemm(ctx, a2_wv + (long long)d * Cx * Ii, nullptr, vcb,
                    Bb * Ss, Ii, Cx, Cx, Ii, Ii, 0, 0, 0, 1.f, 0.f,
                    1, 1, 0, 0, 0, 0, 0, 0);
        crossattn_kernel<<<Bb * Hh * Tt / 8, 256>>>(q, kcb, vcb, att);
        launch_gemm(att, a2_wo + wofs, a2_bo + d * Ii, h,
                    Bb * Tt, Ii, Ii, Ii, Ii, Ii, 0, 0, 1, 1.f, 1.f,
                    1, 1, 0, 0, 0, 0, 0, 0);

        // --- feed-forward (conv1d / gelu / conv1d) ---
        layernorm_kernel<<<Bb * Tt, 256>>>(h, n3_s + d * Ii, n3_b + d * Ii, y);
        {
            dim3 g(Tt / 32, Ii / 32, Bb);
            transpose_kernel<false><<<g, dim3(32, 8)>>>(y, yT, Tt, Ii);
        }
        {
            dim3 g(Tt / 64, Fi / 64, Bb);
            conv1d_kernel<<<g, 256>>>(yT, ff1_w + (long long)d * Fi * Ii * Ksz,
                                      ff1_b + d * Fi, ffa, Ii, Fi, 1);
        }
        {
            dim3 g(Tt / 64, Ii / 64, Bb);
            conv1d_kernel<<<g, 256>>>(ffa, ff2_w + (long long)d * Ii * Fi * Ksz,
                                      ff2_b + d * Ii, ffb, Fi, Ii, 0);
        }
        {
            dim3 g(Ii / 32, Tt / 32, Bb);
            transpose_kernel<true><<<g, dim3(32, 8)>>>(ffb, h, Ii, Tt);
        }
    }

    // 3) out = pout_w @ h^T + pout_b + x
    cudaMemcpyAsync(out, x, (size_t)Bb * Cc * Tt * sizeof(float),
                    cudaMemcpyDeviceToDevice);
    launch_gemm(pout_w, h, pout_b, out,
                Cc, Tt, Ii, Ii, Ii, Tt, /*tA=*/0, /*tB=*/1, /*bias m*/2, 1.f, 1.f,
                Bb, 1, 0, 0, (long long)Tt * Ii, 0, (long long)Cc * Tt, 0);
}

// round 2
// speedup vs baseline: 1.0005x; 1.0005x over previous
#include <cuda_runtime.h>
#include <math.h>

// Problem constants
#define Bb 2
#define Cc 768
#define Tt 2048
#define Ii 768
#define Hh 12
#define Dh 64
#define Ss 16
#define Cx 512
#define Fi 3072
#define Dd 2
#define Ksz 9

// ---------------- scratch (static device globals; no allocation) ----------------
__device__ float g_gn [(long long)Bb*Cc*Tt];
__device__ float g_h  [(long long)Bb*Tt*Ii];
__device__ float g_y  [(long long)Bb*Tt*Ii];
__device__ float g_q  [(long long)Bb*Tt*Ii];
__device__ float g_k  [(long long)Bb*Tt*Ii];
__device__ float g_v  [(long long)Bb*Tt*Ii];
__device__ float g_att[(long long)Bb*Tt*Ii];
__device__ float g_sc [(long long)Bb*Hh*Tt*Tt];   // 400 MB attention scores
__device__ float g_ffa[(long long)Bb*Fi*Tt];      // conv1 output
__device__ float g_yT [(long long)Bb*Ii*Tt];
__device__ float g_ffb[(long long)Bb*Ii*Tt];
__device__ float g_kc [(long long)Bb*Ss*Ii];
__device__ float g_vc [(long long)Bb*Ss*Ii];

// ---------------- reductions ----------------
__device__ __forceinline__ float blockReduceSum(float v) {
    __shared__ float sm[32];
    int lane = threadIdx.x & 31, wid = threadIdx.x >> 5;
    #pragma unroll
    for (int o = 16; o; o >>= 1) v += __shfl_xor_sync(0xffffffffu, v, o);
    if (lane == 0) sm[wid] = v;
    __syncthreads();
    if (wid == 0) {
        int nw = (blockDim.x + 31) >> 5;
        v = (lane < nw) ? sm[lane] : 0.f;
        #pragma unroll
        for (int o = 16; o; o >>= 1) v += __shfl_xor_sync(0xffffffffu, v, o);
        if (lane == 0) sm[0] = v;
    }
    __syncthreads();
    float r = sm[0];
    __syncthreads();
    return r;
}

__device__ __forceinline__ float blockReduceMax(float v) {
    __shared__ float sm[32];
    int lane = threadIdx.x & 31, wid = threadIdx.x >> 5;
    #pragma unroll
    for (int o = 16; o; o >>= 1) v = fmaxf(v, __shfl_xor_sync(0xffffffffu, v, o));
    if (lane == 0) sm[wid] = v;
    __syncthreads();
    if (wid == 0) {
        int nw = (blockDim.x + 31) >> 5;
        v = (lane < nw) ? sm[lane] : -INFINITY;
        #pragma unroll
        for (int o = 16; o; o >>= 1) v = fmaxf(v, __shfl_xor_sync(0xffffffffu, v, o));
        if (lane == 0) sm[0] = v;
    }
    __syncthreads();
    float r = sm[0];
    __syncthreads();
    return r;
}

// ---------------- groupnorm ----------------
__global__ void groupnorm_kernel(const float* __restrict__ x, const float* __restrict__ sc,
                                 const float* __restrict__ bi, float* __restrict__ out) {
    const int CPG = Cc / 32;                // 24
    int b = blockIdx.x >> 5, g = blockIdx.x & 31;
    const long long base = ((long long)b * Cc + (long long)g * CPG) * Tt;
    const float* xp = x + base;
    float* op = out + base;
    const int n = CPG * Tt;
    float s = 0.f, ss = 0.f;
    for (int i = threadIdx.x; i < n; i += blockDim.x) {
        float v = xp[i]; s += v; ss = fmaf(v, v, ss);
    }
    s  = blockReduceSum(s);
    ss = blockReduceSum(ss);
    float mean = s / n;
    float inv  = rsqrtf(ss / n - mean * mean + 1e-6f);
    for (int i = threadIdx.x; i < n; i += blockDim.x) {
        int c = g * CPG + i / Tt;
        op[i] = (xp[i] - mean) * inv * sc[c] + bi[c];
    }
}

// ---------------- layernorm ----------------
__global__ void layernorm_kernel(const float* __restrict__ x, const float* __restrict__ sc,
                                 const float* __restrict__ bi, float* __restrict__ out) {
    const float* row = x + (long long)blockIdx.x * Ii;
    float* orow = out + (long long)blockIdx.x * Ii;
    float s = 0.f, ss = 0.f;
    for (int i = threadIdx.x; i < Ii; i += blockDim.x) {
        float v = row[i]; s += v; ss = fmaf(v, v, ss);
    }
    s  = blockReduceSum(s);
    ss = blockReduceSum(ss);
    float mean = s / (float)Ii;
    float inv  = rsqrtf(ss / (float)Ii - mean * mean + 1e-5f);
    for (int i = threadIdx.x; i < Ii; i += blockDim.x)
        orow[i] = (row[i] - mean) * inv * sc[i] + bi[i];
}

// ---------------- generic tiled GEMM ----------------
// C = alpha*op(A)*op(B) + bias + beta*C  (beta in {0,1})
// tA: A stored [K,M] (use A[k*lda+m]); else [M,K]. tB: B stored [N,K]; else [K,N].
// biasMode: 0 none, 1 per-n, 2 per-m. Two-level batch: z1 = bz/b2, z2 = bz%b2.
__global__ void __launch_bounds__(256) gemm_kernel(
    const float* __restrict__ A, const float* __restrict__ B,
    const float* __restrict__ bias, float* __restrict__ Cp,
    int M, int N, int K, int lda, int ldb, int ldc,
    int tA, int tB, int biasMode, float alpha, float beta,
    int b2, long long sA1, long long sA2, long long sB1, long long sB2,
    long long sC1, long long sC2)
{
    int bz = blockIdx.z;
    int z1 = bz / b2, z2 = bz % b2;
    A  += z1 * sA1 + z2 * sA2;
    B  += z1 * sB1 + z2 * sB2;
    Cp += z1 * sC1 + z2 * sC2;
    __shared__ float As[16][65];
    __shared__ float Bs[16][65];
    int n0 = blockIdx.x * 64, m0 = blockIdx.y * 64;
    int tid = threadIdx.x;
    int tx = tid & 15, ty = tid >> 4;
    float acc[4][4] = {};
    for (int k0 = 0; k0 < K; k0 += 16) {
        #pragma unroll
        for (int u = 0; u < 4; ++u) {
            int i = tid + u * 256;
            int mm, kk;
            if (!tA) { mm = i >> 4; kk = i & 15; }
            else     { kk = i >> 6; mm = i & 63; }
            int m = m0 + mm, k = k0 + kk;
            float v = 0.f;
            if (m < M && k < K)
                v = tA ? A[(long long)k * lda + m] : A[(long long)m * lda + k];
            As[kk][mm] = v;
        }
        #pragma unroll
        for (int u = 0; u < 4; ++u) {
            int i = tid + u * 256;
            int kk, nn;
            if (!tB) { kk = i >> 6; nn = i & 63; }
            else     { nn = i >> 4; kk = i & 15; }
            int k = k0 + kk, n = n0 + nn;
            float v = 0.f;
            if (k < K && n < N)
                v = tB ? B[(long long)n * ldb + k] : B[(long long)k * ldb + n];
            Bs[kk][nn] = v;
        }
        __syncthreads();
        #pragma unroll
        for (int kk = 0; kk < 16; ++kk) {
            float a[4], bb[4];
            #pragma unroll
            for (int i = 0; i < 4; ++i) a[i] = As[kk][ty * 4 + i];
            #pragma unroll
            for (int j = 0; j < 4; ++j) bb[j] = Bs[kk][tx * 4 + j];
            #pragma unroll
            for (int i = 0; i < 4; ++i)
                #pragma unroll
                for (int j = 0; j < 4; ++j)
                    acc[i][j] = fmaf(a[i], bb[j], acc[i][j]);
        }
        __syncthreads();
    }
    #pragma unroll
    for (int i = 0; i < 4; ++i) {
        int m = m0 + ty * 4 + i;
        if (m >= M) continue;
        #pragma unroll
        for (int j = 0; j < 4; ++j) {
            int n = n0 + tx * 4 + j;
            if (n >= N) continue;
            float v = alpha * acc[i][j];
            if (biasMode == 1) v += bias[n];
            else if (biasMode == 2) v += bias[m];
            long long idx = (long long)m * ldc + n;
            if (beta != 0.f) v += Cp[idx];
            Cp[idx] = v;
        }
    }
}

// ---------------- softmax (rows of 2048, register-cached) ----------------
__global__ void softmax_kernel(float* __restrict__ s) {
    float* row = s + (long long)blockIdx.x * Tt;
    int tid = threadIdx.x;
    float v[8];
    float mx = -INFINITY;
    #pragma unroll
    for (int i = 0; i < 8; ++i) { v[i] = row[tid + (i << 8)]; mx = fmaxf(mx, v[i]); }
    mx = blockReduceMax(mx);
    float sum = 0.f;
    #pragma unroll
    for (int i = 0; i < 8; ++i) { v[i] = expf(v[i] - mx); sum += v[i]; }
    sum = blockReduceSum(sum);
    float inv = 1.f / sum;
    #pragma unroll
    for (int i = 0; i < 8; ++i) row[tid + (i << 8)] = v[i] * inv;
}

// ---------------- cross attention (16 keys): one warp per (b,h,t) ----------------
__global__ void crossattn_kernel(const float* __restrict__ q, const float* __restrict__ kc,
                                 const float* __restrict__ vc, float* __restrict__ out) {
    int gw = blockIdx.x * (blockDim.x >> 5) + (threadIdx.x >> 5);
    int lane = threadIdx.x & 31;
    int t = gw % Tt;
    int rem = gw / Tt;
    int h = rem % Hh;
    int b = rem / Hh;
    const float* qp = q + ((long long)(b * Tt + t)) * Ii + h * Dh;
    const float* kb = kc + (long long)b * Ss * Ii + h * Dh;
    const float* vb = vc + (long long)b * Ss * Ii + h * Dh;
    float sj = -INFINITY;
    if (lane < Ss) {
        const float* kp = kb + lane * Ii;
        float acc = 0.f;
        #pragma unroll
        for (int d2 = 0; d2 < Dh; ++d2) acc = fmaf(qp[d2], kp[d2], acc);
        sj = acc * 0.125f;   // dh^-0.5
    }
    float mx = sj;
    #pragma unroll
    for (int o = 16; o; o >>= 1) mx = fmaxf(mx, __shfl_xor_sync(0xffffffffu, mx, o));
    float p = (lane < Ss) ? expf(sj - mx) : 0.f;
    float sum = p;
    #pragma unroll
    for (int o = 16; o; o >>= 1) sum += __shfl_xor_sync(0xffffffffu, sum, o);
    p /= sum;
    float o0 = 0.f, o1 = 0.f;
    #pragma unroll
    for (int j = 0; j < Ss; ++j) {
        float pj = __shfl_sync(0xffffffffu, p, j);
        const float* vp = vb + j * Ii;
        o0 = fmaf(pj, vp[lane], o0);
        o1 = fmaf(pj, vp[lane + 32], o1);
    }
    float* op = out + ((long long)(b * Tt + t)) * Ii + h * Dh;
    op[lane] = o0;
    op[lane + 32] = o1;
}

// ---------------- transpose (and transpose+add) ----------------
// in: [R, Ccol] per batch, out: [Ccol, R] per batch, batch stride R*Ccol both sides.
template <bool ADD>
__global__ void transpose_kernel(const float* __restrict__ in, float* __restrict__ out,
                                 int R, int Ccol) {
    __shared__ float tile[32][33];
    long long bo = (long long)blockIdx.z * R * Ccol;
    const float* ip = in + bo;
    float* op = out + bo;
    int r0 = blockIdx.x * 32, c0 = blockIdx.y * 32;
    #pragma unroll
    for (int i = 0; i < 32; i += 8)
        tile[threadIdx.y + i][threadIdx.x] =
            ip[(long long)(r0 + threadIdx.y + i) * Ccol + c0 + threadIdx.x];
    __syncthreads();
    #pragma unroll
    for (int i = 0; i < 32; i += 8) {
        long long idx = (long long)(c0 + threadIdx.y + i) * R + r0 + threadIdx.x;
        float v = tile[threadIdx.x][threadIdx.y + i];
        if (ADD) op[idx] += v; else op[idx] = v;
    }
}

// ---------------- conv1d (implicit GEMM, K=9, pad=4) ----------------
// x: [Cin, T] per batch, w: [Cout, Cin, 9], out: [Cout, T] per batch.
__global__ void __launch_bounds__(256) conv1d_kernel(
    const float* __restrict__ x, const float* __restrict__ w,
    const float* __restrict__ bias, float* __restrict__ out,
    int Cin, int Cout, int applyGelu)
{
    int b = blockIdx.z;
    x   += (long long)b * Cin * Tt;
    out += (long long)b * Cout * Tt;
    int t0 = blockIdx.x * 64, o0 = blockIdx.y * 64;
    __shared__ float xs[8][76];    // 72 used (64 + 8 halo)
    __shared__ float ws[64][73];   // 72 used (8c * 9k)
    int tid = threadIdx.x;
    int tx = tid & 15, ty = tid >> 4;
    int ty4 = ty * 4;
    float acc[4][4] = {};
    for (int c0 = 0; c0 < Cin; c0 += 8) {
        for (int i = tid; i < 8 * 72; i += 256) {
            int c = i / 72, j = i % 72;
            int t = t0 + j - 4;
            xs[c][j] = (t >= 0 && t < Tt) ? x[(long long)(c0 + c) * Tt + t] : 0.f;
        }
        for (int i = tid; i < 64 * 72; i += 256) {
            int o = i / 72, r = i % 72;
            ws[o][r] = w[(long long)(o0 + o) * Cin * 9 + (long long)c0 * 9 + r];
        }
        __syncthreads();
        #pragma unroll
        for (int c = 0; c < 8; ++c) {
            float xr[12];
            #pragma unroll
            for (int j = 0; j < 12; ++j) xr[j] = xs[c][tx * 4 + j];
            #pragma unroll
            for (int k = 0; k < 9; ++k) {
                float w0 = ws[ty4 + 0][c * 9 + k];
                float w1 = ws[ty4 + 1][c * 9 + k];
                float w2 = ws[ty4 + 2][c * 9 + k];
                float w3 = ws[ty4 + 3][c * 9 + k];
                #pragma unroll
                for (int j = 0; j < 4; ++j) {
                    float xv = xr[k + j];
                    acc[0][j] = fmaf(w0, xv, acc[0][j]);
                    acc[1][j] = fmaf(w1, xv, acc[1][j]);
                    acc[2][j] = fmaf(w2, xv, acc[2][j]);
                    acc[3][j] = fmaf(w3, xv, acc[3][j]);
                }
            }
        }
        __syncthreads();
    }
    #pragma unroll
    for (int i = 0; i < 4; ++i) {
        int o = o0 + ty4 + i;
        float bv = bias[o];
        #pragma unroll
        for (int j = 0; j < 4; ++j) {
            int t = t0 + tx * 4 + j;
            float v = acc[i][j] + bv;
            if (applyGelu) v = 0.5f * v * (1.f + erff(v * 0.70710678118654752f));
            out[(long long)o * Tt + t] = v;
        }
    }
}

// ---------------- host-side GEMM wrapper ----------------
static void launch_gemm(const float* A, const float* B, const float* bias, float* C,
                        int M, int N, int K, int lda, int ldb, int ldc,
                        int tA, int tB, int biasMode, float alpha, float beta,
                        int nz, int b2,
                        long long sA1, long long sA2, long long sB1, long long sB2,
                        long long sC1, long long sC2)
{
    dim3 grid((N + 63) / 64, (M + 63) / 64, nz);
    gemm_kernel<<<grid, 256>>>(A, B, bias, C, M, N, K, lda, ldb, ldc,
                               tA, tB, biasMode, alpha, beta,
                               b2, sA1, sA2, sB1, sB2, sC1, sC2);
}

extern "C" void kernel_launch(void* const* d_in, const int* in_sizes, int n_in,
                              void* d_out, int out_size) {
    const float* x      = (const float*)d_in[0];
    const float* ctx    = (const float*)d_in[1];
    const float* gn_s   = (const float*)d_in[2];
    const float* gn_b   = (const float*)d_in[3];
    const float* pin_w  = (const float*)d_in[4];
    const float* pin_b  = (const float*)d_in[5];
    const float* n1_s   = (const float*)d_in[6];
    const float* n1_b   = (const float*)d_in[7];
    const float* a1_wq  = (const float*)d_in[8];
    const float* a1_wk  = (const float*)d_in[9];
    const float* a1_wv  = (const float*)d_in[10];
    const float* a1_wo  = (const float*)d_in[11];
    const float* a1_bo  = (const float*)d_in[12];
    const float* n2_s   = (const float*)d_in[13];
    const float* n2_b   = (const float*)d_in[14];
    const float* a2_wq  = (const float*)d_in[15];
    const float* a2_wk  = (const float*)d_in[16];
    const float* a2_wv  = (const float*)d_in[17];
    const float* a2_wo  = (const float*)d_in[18];
    const float* a2_bo  = (const float*)d_in[19];
    const float* n3_s   = (const float*)d_in[20];
    const float* n3_b   = (const float*)d_in[21];
    const float* ff1_w  = (const float*)d_in[22];
    const float* ff1_b  = (const float*)d_in[23];
    const float* ff2_w  = (const float*)d_in[24];
    const float* ff2_b  = (const float*)d_in[25];
    const float* pout_w = (const float*)d_in[26];
    const float* pout_b = (const float*)d_in[27];
    float* out = (float*)d_out;

    float *gn, *h, *y, *q, *k, *v, *att, *sc, *ffa, *yT, *ffb, *kcb, *vcb;
    cudaGetSymbolAddress((void**)&gn,  g_gn);
    cudaGetSymbolAddress((void**)&h,   g_h);
    cudaGetSymbolAddress((void**)&y,   g_y);
    cudaGetSymbolAddress((void**)&q,   g_q);
    cudaGetSymbolAddress((void**)&k,   g_k);
    cudaGetSymbolAddress((void**)&v,   g_v);
    cudaGetSymbolAddress((void**)&att, g_att);
    cudaGetSymbolAddress((void**)&sc,  g_sc);
    cudaGetSymbolAddress((void**)&ffa, g_ffa);
    cudaGetSymbolAddress((void**)&yT,  g_yT);
    cudaGetSymbolAddress((void**)&ffb, g_ffb);
    cudaGetSymbolAddress((void**)&kcb, g_kc);
    cudaGetSymbolAddress((void**)&vcb, g_vc);

    // 1) GroupNorm
    groupnorm_kernel<<<Bb * 32, 256>>>(x, gn_s, gn_b, gn);

    // 2) proj_in: h[b,t,i] = sum_c pin_w[i,c] * gn[b,c,t] + pin_b[i]
    launch_gemm(gn, pin_w, pin_b, h,
                Tt, Ii, Cc, Tt, Cc, Ii, /*tA=*/1, /*tB=*/1, /*bias n*/1, 1.f, 0.f,
                Bb, 1, (long long)Cc * Tt, 0, 0, 0, (long long)Tt * Ii, 0);

    for (int d = 0; d < Dd; ++d) {
        long long wofs = (long long)d * Ii * Ii;

        // --- self attention ---
        layernorm_kernel<<<Bb * Tt, 256>>>(h, n1_s + d * Ii, n1_b + d * Ii, y);
        launch_gemm(y, a1_wq + wofs, nullptr, q, Bb * Tt, Ii, Ii, Ii, Ii, Ii,
                    0, 0, 0, 1.f, 0.f, 1, 1, 0, 0, 0, 0, 0, 0);
        launch_gemm(y, a1_wk + wofs, nullptr, k, Bb * Tt, Ii, Ii, Ii, Ii, Ii,
                    0, 0, 0, 1.f, 0.f, 1, 1, 0, 0, 0, 0, 0, 0);
        launch_gemm(y, a1_wv + wofs, nullptr, v, Bb * Tt, Ii, Ii, Ii, Ii, Ii,
                    0, 0, 0, 1.f, 0.f, 1, 1, 0, 0, 0, 0, 0, 0);
        // scores[b,h] = 0.125 * q_head @ k_head^T
        launch_gemm(q, k, nullptr, sc, Tt, Tt, Dh, Ii, Ii, Tt, 0, 1, 0, 0.125f, 0.f,
                    Bb * Hh, Hh,
                    (long long)Tt * Ii, Dh, (long long)Tt * Ii, Dh,
                    (long long)Hh * Tt * Tt, (long long)Tt * Tt);
        softmax_kernel<<<Bb * Hh * Tt, 256>>>(sc);
        // att_head = scores @ v_head
        launch_gemm(sc, v, nullptr, att, Tt, Dh, Tt, Tt, Ii, Ii, 0, 0, 0, 1.f, 0.f,
                    Bb * Hh, Hh,
                    (long long)Hh * Tt * Tt, (long long)Tt * Tt,
                    (long long)Tt * Ii, Dh, (long long)Tt * Ii, Dh);
        // h += att @ wo + bo
        launch_gemm(att, a1_wo + wofs, a1_bo + d * Ii, h,
                    Bb * Tt, Ii, Ii, Ii, Ii, Ii, 0, 0, 1, 1.f, 1.f,
                    1, 1, 0, 0, 0, 0, 0, 0);

        // --- cross attention ---
        layernorm_kernel<<<Bb * Tt, 256>>>(h, n2_s + d * Ii, n2_b + d * Ii, y);
        launch_gemm(y, a2_wq + wofs, nullptr, q, Bb * Tt, Ii, Ii, Ii, Ii, Ii,
                    0, 0, 0, 1.f, 0.f, 1, 1, 0, 0, 0, 0, 0, 0);
        launch_gemm(ctx, a2_wk + (long long)d * Cx * Ii, nullptr, kcb,
                    Bb * Ss, Ii, Cx, Cx, Ii, Ii, 0, 0, 0, 1.f, 0.f,
                    1, 1, 0, 0, 0, 0, 0, 0);
        launch_gemm(ctx, a2_wv + (long long)d * Cx * Ii, nullptr, vcb,
                    Bb * Ss, Ii, Cx, Cx, Ii, Ii, 0, 0, 0, 1.f, 0.f,
                    1, 1, 0, 0, 0, 0, 0, 0);
        crossattn_kernel<<<Bb * Hh * Tt / 8, 256>>>(q, kcb, vcb, att);
        launch_gemm(att, a2_wo + wofs, a2_bo + d * Ii, h,
                    Bb * Tt, Ii, Ii, Ii, Ii, Ii, 0, 0, 1, 1.f, 1.f,
                    1, 1, 0, 0, 0, 0, 0, 0);

        // --- feed-forward (conv1d / gelu / conv1d) ---
        layernorm_kernel<<<Bb * Tt, 256>>>(h, n3_s + d * Ii, n3_b + d * Ii, y);
        {
            dim3 g(Tt / 32, Ii / 32, Bb);
            transpose_kernel<false><<<g, dim3(32, 8)>>>(y, yT, Tt, Ii);
        }
        {
            dim3 g(Tt / 64, Fi / 64, Bb);
            conv1d_kernel<<<g, 256>>>(yT, ff1_w + (long long)d * Fi * Ii * Ksz,
                                      ff1_b + d * Fi, ffa, Ii, Fi, 1);
        }
        {
            dim3 g(Tt / 64, Ii / 64, Bb);
            conv1d_kernel<<<g, 256>>>(ffa, ff2_w + (long long)d * Ii * Fi * Ksz,
                                      ff2_b + d * Ii, ffb, Fi, Ii, 0);
        }
        {
            dim3 g(Ii / 32, Tt / 32, Bb);
            transpose_kernel<true><<<g, dim3(32, 8)>>>(ffb, h, Ii, Tt);
        }
    }

    // 3) out = pout_w @ h^T + pout_b + x
    cudaMemcpyAsync(out, x, (size_t)Bb * Cc * Tt * sizeof(float),
                    cudaMemcpyDeviceToDevice);
    launch_gemm(pout_w, h, pout_b, out,
                Cc, Tt, Ii, Ii, Ii, Tt, /*tA=*/0, /*tB=*/1, /*bias m*/2, 1.f, 1.f,
                Bb, 1, 0, 0, (long long)Tt * Ii, 0, (long long)Cc * Tt, 0);
}

// round 5
// speedup vs baseline: 1.4453x; 1.4446x over previous
#include <cuda_runtime.h>
#include <cuda_bf16.h>
#include <math.h>
#include <stdint.h>

#define Bb 2
#define Cc 768
#define Tt 2048
#define Ii 768
#define Hh 12
#define Dh 64
#define Ss 16
#define Cx 512
#define Fi 3072
#define Dd 2
#define Ksz 9

typedef __nv_bfloat16 bf16;

// ---------------- scratch ----------------
__device__ float g_gn [(long long)Bb*Cc*Tt];
__device__ float g_h  [(long long)Bb*Tt*Ii];
__device__ float g_y  [(long long)Bb*Tt*Ii];
__device__ float g_q  [(long long)Bb*Tt*Ii];
__device__ float g_k  [(long long)Bb*Tt*Ii];
__device__ float g_v  [(long long)Bb*Tt*Ii];
__device__ float g_att[(long long)Bb*Tt*Ii];
__device__ float g_sc [(long long)Bb*Hh*Tt*Tt];
__device__ float g_ffa[(long long)Bb*Tt*Fi];
__device__ float g_w1r[(long long)Fi*Ii*Ksz];
__device__ float g_w2r[(long long)Ii*Fi*Ksz];
__device__ float g_kc [(long long)Bb*Ss*Ii];
__device__ float g_vc [(long long)Bb*Ss*Ii];

// ---------------- helpers ----------------
__device__ __forceinline__ uint32_t smem_u32(const void* p) {
    uint32_t a;
    asm("{ .reg .u64 t; cvta.to.shared.u64 t, %1; cvt.u32.u64 %0, t; }" : "=r"(a) : "l"(p));
    return a;
}
#define SWZ(x) ((x) ^ ((((uint32_t)(x)) >> 3) & 0x70))

__device__ __forceinline__ void ldsm4(uint32_t* r, uint32_t addr) {
    asm volatile("ldmatrix.sync.aligned.m8n8.x4.shared.b16 {%0,%1,%2,%3}, [%4];"
        : "=r"(r[0]), "=r"(r[1]), "=r"(r[2]), "=r"(r[3]) : "r"(addr));
}
__device__ __forceinline__ void mma16816(float* c, const uint32_t* a, const uint32_t* b) {
    asm volatile("mma.sync.aligned.m16n8k16.row.col.f32.bf16.bf16.f32 "
        "{%0,%1,%2,%3}, {%4,%5,%6,%7}, {%8,%9}, {%0,%1,%2,%3};"
        : "+f"(c[0]), "+f"(c[1]), "+f"(c[2]), "+f"(c[3])
        : "r"(a[0]), "r"(a[1]), "r"(a[2]), "r"(a[3]), "r"(b[0]), "r"(b[1]));
}

__device__ __forceinline__ void split2(float x0, float x1, uint32_t& hp, uint32_t& lp) {
    bf16 h0 = __float2bfloat16(x0), h1 = __float2bfloat16(x1);
    bf16 l0 = __float2bfloat16(x0 - __bfloat162float(h0));
    bf16 l1 = __float2bfloat16(x1 - __bfloat162float(h1));
    hp = ((uint32_t)__bfloat16_as_ushort(h1) << 16) | __bfloat16_as_ushort(h0);
    lp = ((uint32_t)__bfloat16_as_ushort(l1) << 16) | __bfloat16_as_ushort(l0);
}

// stage one operand tile (up to 128 rows x 64 k) into swizzled hi/lo smem
__device__ __forceinline__ void stage_op(const float* __restrict__ P,
                                         long long off0, long long flim,
                                         int ld, int k0, int trans, int brows,
                                         char* hiB, char* loB) {
    #pragma unroll 2
    for (int idx = threadIdx.x; idx < 128 * 32; idx += 256) {
        int row, kp;
        if (trans) { row = idx & 127; kp = idx >> 7; }
        else       { row = idx >> 5;  kp = idx & 31; }
        if (row >= brows) continue;
        long long kk = (long long)k0 + kp * 2;
        float x0, x1;
        if (trans) {
            long long f0 = off0 + kk * (long long)ld + row;
            long long f1 = f0 + ld;
            x0 = (f0 >= 0 && f0 < flim) ? P[f0] : 0.f;
            x1 = (f1 >= 0 && f1 < flim) ? P[f1] : 0.f;
        } else {
            long long f0 = off0 + (long long)row * ld + kk;
            x0 = (f0 >= 0 && f0 < flim) ? P[f0] : 0.f;
            x1 = (f0 + 1 >= 0 && f0 + 1 < flim) ? P[f0 + 1] : 0.f;
        }
        uint32_t hp, lp;
        split2(x0, x1, hp, lp);
        uint32_t a = SWZ((uint32_t)(row * 128 + kp * 4));
        *(uint32_t*)(hiB + a) = hp;
        *(uint32_t*)(loB + a) = lp;
    }
}

// flags
#define FTA   1
#define FTB   2
#define FBN   4
#define FBM   8
#define FGELU 16
#define FADD  32

#define TC_SMEM (64*1024 + 128)

// ======================= tensor-core GEMM (mma.sync bf16, hi/lo split) ===========
// C[M=128/blk, NT/blk] = alpha * A @ B^T(+layout flags) + bias/gelu/add
template<int NT>
__global__ void __launch_bounds__(256, 2)
tc_gemm(const float* __restrict__ A, const float* __restrict__ B,
        const float* __restrict__ bias, float* __restrict__ out,
        int K, int lda, int ldb, long long ldo, int flags, float alpha,
        long long offA, long long flimA, int b2,
        long long sA1, long long sA2, long long sB1, long long sB2,
        long long sC1, long long sC2)
{
    extern __shared__ char dynsm[];
    long long z1 = blockIdx.z / b2, z2 = blockIdx.z % b2;
    A   += z1 * sA1 + z2 * sA2;
    B   += z1 * sB1 + z2 * sB2;
    out += z1 * sC1 + z2 * sC2;

    const int tid = threadIdx.x;
    const int lane = tid & 31;
    const int wid = tid >> 5;
    const int wm = (wid & 3) * 32;              // warp M offset (rows)
    const int wn = (wid >> 2) * (NT / 2);       // warp N offset (cols)
    const int m0 = blockIdx.y * 128;
    const int n0 = blockIdx.x * NT;
    constexpr int NTW = NT / 16;                // n8 tiles per warp (8 or 4)

    char* sb = dynsm + ((128 - (smem_u32(dynsm) & 127)) & 127);
    char* Ahi = sb;
    char* Alo = sb + 16384;
    char* Bhi = sb + 32768;
    char* Blo = sb + 49152;
    const uint32_t aHi = smem_u32(Ahi), aLo = smem_u32(Alo);
    const uint32_t bHi = smem_u32(Bhi), bLo = smem_u32(Blo);

    const int tAf = flags & FTA, tBf = flags & FTB;
    const long long aoff = offA + (tAf ? (long long)m0 : (long long)m0 * lda);
    const long long boff = (tBf ? (long long)n0 : (long long)n0 * ldb);
    const long long flimB = 1LL << 62;
    const int nc = K / 64;

    float acc[2][NTW][4];
    #pragma unroll
    for (int i = 0; i < 2; ++i)
        #pragma unroll
        for (int j = 0; j < NTW; ++j)
            #pragma unroll
            for (int l = 0; l < 4; ++l) acc[i][j][l] = 0.f;

    // precomputed ldmatrix lane offsets
    const uint32_t aRow = wm + (lane & 15);
    const uint32_t aKof = (lane >> 4) << 3;
    const int bi = lane >> 3;
    const uint32_t bRowBase = wn + ((bi >> 1) << 3) + (lane & 7);
    const uint32_t bKof = (bi & 1) << 3;

    for (int c = 0; c < nc; ++c) {
        __syncthreads();
        stage_op(A, aoff, flimA, lda, c * 64, tAf, 128, Ahi, Alo);
        stage_op(B, boff, flimB, ldb, c * 64, tBf, NT, Bhi, Blo);
        __syncthreads();
        #pragma unroll
        for (int ks = 0; ks < 4; ++ks) {
            const uint32_t kb = ks * 16;
            uint32_t ah[2][4], al[2][4];
            #pragma unroll
            for (int mt = 0; mt < 2; ++mt) {
                uint32_t off = SWZ((aRow + mt * 16) * 128 + (kb + aKof) * 2);
                ldsm4(ah[mt], aHi + off);
                ldsm4(al[mt], aLo + off);
            }
            #pragma unroll
            for (int bp = 0; bp < NTW / 2; ++bp) {
                uint32_t off = SWZ((bRowBase + bp * 16) * 128 + (kb + bKof) * 2);
                uint32_t bh[4], bl[4];
                ldsm4(bh, bHi + off);
                ldsm4(bl, bLo + off);
                #pragma unroll
                for (int mt = 0; mt < 2; ++mt) {
                    mma16816(acc[mt][2 * bp], ah[mt], bh);
                    mma16816(acc[mt][2 * bp], al[mt], bh);
                    mma16816(acc[mt][2 * bp], ah[mt], bl);
                    mma16816(acc[mt][2 * bp + 1], ah[mt], bh + 2);
                    mma16816(acc[mt][2 * bp + 1], al[mt], bh + 2);
                    mma16816(acc[mt][2 * bp + 1], ah[mt], bl + 2);
                }
            }
        }
    }

    // epilogue
    const int g = lane >> 2, tg = lane & 3;
    #pragma unroll
    for (int mt = 0; mt < 2; ++mt) {
        #pragma unroll
        for (int hf = 0; hf < 2; ++hf) {
            int m = m0 + wm + mt * 16 + g + hf * 8;
            float bm = (flags & FBM) ? bias[m] : 0.f;
            float* rowp = out + (long long)m * ldo;
            #pragma unroll
            for (int nt = 0; nt < NTW; ++nt) {
                int n = n0 + wn + nt * 8 + tg * 2;
                float v0 = alpha * acc[mt][nt][hf * 2 + 0];
                float v1 = alpha * acc[mt][nt][hf * 2 + 1];
                if (flags & FBN) { v0 += bias[n]; v1 += bias[n + 1]; }
                else if (flags & FBM) { v0 += bm; v1 += bm; }
                if (flags & FGELU) {
                    v0 = 0.5f * v0 * (1.f + erff(v0 * 0.70710678118654752f));
                    v1 = 0.5f * v1 * (1.f + erff(v1 * 0.70710678118654752f));
                }
                if (flags & FADD) { v0 += rowp[n]; v1 += rowp[n + 1]; }
                rowp[n] = v0;
                rowp[n + 1] = v1;
            }
        }
    }
}

// ---------------- reductions ----------------
__device__ __forceinline__ float blockReduceSum(float v) {
    __shared__ float sm[32];
    int lane = threadIdx.x & 31, wid = threadIdx.x >> 5;
    #pragma unroll
    for (int o = 16; o; o >>= 1) v += __shfl_xor_sync(0xffffffffu, v, o);
    if (lane == 0) sm[wid] = v;
    __syncthreads();
    if (wid == 0) {
        int nw = (blockDim.x + 31) >> 5;
        v = (lane < nw) ? sm[lane] : 0.f;
        #pragma unroll
        for (int o = 16; o; o >>= 1) v += __shfl_xor_sync(0xffffffffu, v, o);
        if (lane == 0) sm[0] = v;
    }
    __syncthreads();
    float r = sm[0];
    __syncthreads();
    return r;
}
__device__ __forceinline__ float blockReduceMax(float v) {
    __shared__ float sm[32];
    int lane = threadIdx.x & 31, wid = threadIdx.x >> 5;
    #pragma unroll
    for (int o = 16; o; o >>= 1) v = fmaxf(v, __shfl_xor_sync(0xffffffffu, v, o));
    if (lane == 0) sm[wid] = v;
    __syncthreads();
    if (wid == 0) {
        int nw = (blockDim.x + 31) >> 5;
        v = (lane < nw) ? sm[lane] : -INFINITY;
        #pragma unroll
        for (int o = 16; o; o >>= 1) v = fmaxf(v, __shfl_xor_sync(0xffffffffu, v, o));
        if (lane == 0) sm[0] = v;
    }
    __syncthreads();
    float r = sm[0];
    __syncthreads();
    return r;
}

__global__ void groupnorm_kernel(const float* __restrict__ x, const float* __restrict__ sc,
                                 const float* __restrict__ bi, float* __restrict__ out) {
    const int CPG = Cc / 32;
    int b = blockIdx.x >> 5, g = blockIdx.x & 31;
    const long long base = ((long long)b * Cc + (long long)g * CPG) * Tt;
    const float* xp = x + base;
    float* op = out + base;
    const int n = CPG * Tt;
    float s = 0.f, ss = 0.f;
    for (int i = threadIdx.x; i < n; i += blockDim.x) {
        float v = xp[i]; s += v; ss = fmaf(v, v, ss);
    }
    s = blockReduceSum(s); ss = blockReduceSum(ss);
    float mean = s / n;
    float inv = rsqrtf(ss / n - mean * mean + 1e-6f);
    for (int i = threadIdx.x; i < n; i += blockDim.x) {
        int c = g * CPG + i / Tt;
        op[i] = (xp[i] - mean) * inv * sc[c] + bi[c];
    }
}

__global__ void layernorm_kernel(const float* __restrict__ x, const float* __restrict__ sc,
                                 const float* __restrict__ bi, float* __restrict__ out) {
    const float* row = x + (long long)blockIdx.x * Ii;
    float* orow = out + (long long)blockIdx.x * Ii;
    float s = 0.f, ss = 0.f;
    for (int i = threadIdx.x; i < Ii; i += blockDim.x) {
        float v = row[i]; s += v; ss = fmaf(v, v, ss);
    }
    s = blockReduceSum(s); ss = blockReduceSum(ss);
    float mean = s / (float)Ii;
    float inv = rsqrtf(ss / (float)Ii - mean * mean + 1e-5f);
    for (int i = threadIdx.x; i < Ii; i += blockDim.x)
        orow[i] = (row[i] - mean) * inv * sc[i] + bi[i];
}

// small fp32 gemm for tiny cross-attn K/V projections (M=32)
__global__ void __launch_bounds__(256) gemm_kernel(
    const float* __restrict__ A, const float* __restrict__ B, float* __restrict__ Cp,
    int M, int N, int K, int lda, int ldb, int ldc)
{
    __shared__ float As[16][65];
    __shared__ float Bs[16][65];
    int n0 = blockIdx.x * 64, m0 = blockIdx.y * 64;
    int tid = threadIdx.x;
    int tx = tid & 15, ty = tid >> 4;
    float acc[4][4] = {};
    for (int k0 = 0; k0 < K; k0 += 16) {
        #pragma unroll
        for (int u = 0; u < 4; ++u) {
            int i = tid + u * 256;
            int mm = i >> 4, kk = i & 15;
            int m = m0 + mm, k = k0 + kk;
            As[kk][mm] = (m < M && k < K) ? A[(long long)m * lda + k] : 0.f;
        }
        #pragma unroll
        for (int u = 0; u < 4; ++u) {
            int i = tid + u * 256;
            int kk = i >> 6, nn = i & 63;
            int k = k0 + kk, n = n0 + nn;
            Bs[kk][nn] = (k < K && n < N) ? B[(long long)k * ldb + n] : 0.f;
        }
        __syncthreads();
        #pragma unroll
        for (int kk = 0; kk < 16; ++kk) {
            float a[4], bb[4];
            #pragma unroll
            for (int i = 0; i < 4; ++i) a[i] = As[kk][ty * 4 + i];
            #pragma unroll
            for (int j = 0; j < 4; ++j) bb[j] = Bs[kk][tx * 4 + j];
            #pragma unroll
            for (int i = 0; i < 4; ++i)
                #pragma unroll
                for (int j = 0; j < 4; ++j)
                    acc[i][j] = fmaf(a[i], bb[j], acc[i][j]);
        }
        __syncthreads();
    }
    #pragma unroll
    for (int i = 0; i < 4; ++i) {
        int m = m0 + ty * 4 + i;
        if (m >= M) continue;
        #pragma unroll
        for (int j = 0; j < 4; ++j) {
            int n = n0 + tx * 4 + j;
            if (n < N) Cp[(long long)m * ldc + n] = acc[i][j];
        }
    }
}

__global__ void softmax_kernel(float* __restrict__ s) {
    float* row = s + (long long)blockIdx.x * Tt;
    int tid = threadIdx.x;
    float v[8];
    float mx = -INFINITY;
    #pragma unroll
    for (int i = 0; i < 8; ++i) { v[i] = row[tid + (i << 8)]; mx = fmaxf(mx, v[i]); }
    mx = blockReduceMax(mx);
    float sum = 0.f;
    #pragma unroll
    for (int i = 0; i < 8; ++i) { v[i] = expf(v[i] - mx); sum += v[i]; }
    sum = blockReduceSum(sum);
    float inv = 1.f / sum;
    #pragma unroll
    for (int i = 0; i < 8; ++i) row[tid + (i << 8)] = v[i] * inv;
}

__global__ void crossattn_kernel(const float* __restrict__ q, const float* __restrict__ kc,
                                 const float* __restrict__ vc, float* __restrict__ out) {
    int gw = blockIdx.x * (blockDim.x >> 5) + (threadIdx.x >> 5);
    int lane = threadIdx.x & 31;
    int t = gw % Tt;
    int rem = gw / Tt;
    int h = rem % Hh;
    int b = rem / Hh;
    const float* qp = q + ((long long)(b * Tt + t)) * Ii + h * Dh;
    const float* kb = kc + (long long)b * Ss * Ii + h * Dh;
    const float* vb = vc + (long long)b * Ss * Ii + h * Dh;
    float sj = -INFINITY;
    if (lane < Ss) {
        const float* kp = kb + lane * Ii;
        float acc = 0.f;
        #pragma unroll
        for (int d2 = 0; d2 < Dh; ++d2) acc = fmaf(qp[d2], kp[d2], acc);
        sj = acc * 0.125f;
    }
    float mx = sj;
    #pragma unroll
    for (int o = 16; o; o >>= 1) mx = fmaxf(mx, __shfl_xor_sync(0xffffffffu, mx, o));
    float p = (lane < Ss) ? expf(sj - mx) : 0.f;
    float sum = p;
    #pragma unroll
    for (int o = 16; o; o >>= 1) sum += __shfl_xor_sync(0xffffffffu, sum, o);
    p /= sum;
    float o0 = 0.f, o1 = 0.f;
    #pragma unroll
    for (int j = 0; j < Ss; ++j) {
        float pj = __shfl_sync(0xffffffffu, p, j);
        const float* vp = vb + j * Ii;
        o0 = fmaf(pj, vp[lane], o0);
        o1 = fmaf(pj, vp[lane + 32], o1);
    }
    float* op = out + ((long long)(b * Tt + t)) * Ii + h * Dh;
    op[lane] = o0;
    op[lane + 32] = o1;
}

// reorder conv weight: out[o][k*Cin+c] = in[o][c*Ksz+k]
__global__ void reorder_w(const float* __restrict__ w, float* __restrict__ o,
                          long long total, int Cin) {
    long long i = (long long)blockIdx.x * 256 + threadIdx.x;
    if (i >= total) return;
    int rk = Cin * Ksz;
    long long oc = i / rk;
    int r = (int)(i - oc * rk);
    int k = r / Cin, c = r - k * Cin;
    o[i] = w[oc * rk + (long long)c * Ksz + k];
}

// ---------------- host wrapper ----------------
static void tc(const float* A, const float* B, const float* bias, float* out,
               int gx, int gy, int gz, int K, int lda, int ldb, long long ldo,
               int ntile, int flags, float alpha, long long offA, long long flimA,
               int b2, long long sA1, long long sA2, long long sB1, long long sB2,
               long long sC1, long long sC2)
{
    dim3 g(gx, gy, gz);
    if (ntile == 64)
        tc_gemm<64><<<g, 256, TC_SMEM>>>(A, B, bias, out, K, lda, ldb, ldo, flags,
            alpha, offA, flimA, b2, sA1, sA2, sB1, sB2, sC1, sC2);
    else
        tc_gemm<128><<<g, 256, TC_SMEM>>>(A, B, bias, out, K, lda, ldb, ldo, flags,
            alpha, offA, flimA, b2, sA1, sA2, sB1, sB2, sC1, sC2);
}

extern "C" void kernel_launch(void* const* d_in, const int* in_sizes, int n_in,
                              void* d_out, int out_size) {
    const float* x      = (const float*)d_in[0];
    const float* ctx    = (const float*)d_in[1];
    const float* gn_s   = (const float*)d_in[2];
    const float* gn_b   = (const float*)d_in[3];
    const float* pin_w  = (const float*)d_in[4];
    const float* pin_b  = (const float*)d_in[5];
    const float* n1_s   = (const float*)d_in[6];
    const float* n1_b   = (const float*)d_in[7];
    const float* a1_wq  = (const float*)d_in[8];
    const float* a1_wk  = (const float*)d_in[9];
    const float* a1_wv  = (const float*)d_in[10];
    const float* a1_wo  = (const float*)d_in[11];
    const float* a1_bo  = (const float*)d_in[12];
    const float* n2_s   = (const float*)d_in[13];
    const float* n2_b   = (const float*)d_in[14];
    const float* a2_wq  = (const float*)d_in[15];
    const float* a2_wk  = (const float*)d_in[16];
    const float* a2_wv  = (const float*)d_in[17];
    const float* a2_wo  = (const float*)d_in[18];
    const float* a2_bo  = (const float*)d_in[19];
    const float* n3_s   = (const float*)d_in[20];
    const float* n3_b   = (const float*)d_in[21];
    const float* ff1_w  = (const float*)d_in[22];
    const float* ff1_b  = (const float*)d_in[23];
    const float* ff2_w  = (const float*)d_in[24];
    const float* ff2_b  = (const float*)d_in[25];
    const float* pout_w = (const float*)d_in[26];
    const float* pout_b = (const float*)d_in[27];
    float* out = (float*)d_out;

    cudaFuncSetAttribute(tc_gemm<128>, cudaFuncAttributeMaxDynamicSharedMemorySize, TC_SMEM);
    cudaFuncSetAttribute(tc_gemm<64>,  cudaFuncAttributeMaxDynamicSharedMemorySize, TC_SMEM);

    float *gn, *h, *y, *q, *k, *v, *att, *sc, *ffa, *w1r, *w2r, *kcb, *vcb;
    cudaGetSymbolAddress((void**)&gn,  g_gn);
    cudaGetSymbolAddress((void**)&h,   g_h);
    cudaGetSymbolAddress((void**)&y,   g_y);
    cudaGetSymbolAddress((void**)&q,   g_q);
    cudaGetSymbolAddress((void**)&k,   g_k);
    cudaGetSymbolAddress((void**)&v,   g_v);
    cudaGetSymbolAddress((void**)&att, g_att);
    cudaGetSymbolAddress((void**)&sc,  g_sc);
    cudaGetSymbolAddress((void**)&ffa, g_ffa);
    cudaGetSymbolAddress((void**)&w1r, g_w1r);
    cudaGetSymbolAddress((void**)&w2r, g_w2r);
    cudaGetSymbolAddress((void**)&kcb, g_kc);
    cudaGetSymbolAddress((void**)&vcb, g_vc);

    const long long BIG = 1LL << 62;
    const long long TI = (long long)Tt * Ii;

    // GroupNorm
    groupnorm_kernel<<<Bb * 32, 256>>>(x, gn_s, gn_b, gn);

    // proj_in: h[b,t,i] = pin_w[i,:] . gn[b,:,t] + pin_b  (A trans)
    tc(gn, pin_w, pin_b, h, Ii / 128, Tt / 128, Bb, Cc, Tt, Cc, Ii, 128,
       FTA | FBN, 1.f, 0, (long long)Cc * Tt, 1,
       (long long)Cc * Tt, 0, 0, 0, TI, 0);

    for (int d = 0; d < Dd; ++d) {
        long long wofs = (long long)d * Ii * Ii;

        // --- self attention ---
        layernorm_kernel<<<Bb * Tt, 256>>>(h, n1_s + d * Ii, n1_b + d * Ii, y);
        tc(y, a1_wq + wofs, 0, q, Ii / 128, (Bb * Tt) / 128, 1, Ii, Ii, Ii, Ii, 128,
           FTB, 1.f, 0, BIG, 1, 0, 0, 0, 0, 0, 0);
        tc(y, a1_wk + wofs, 0, k, Ii / 128, (Bb * Tt) / 128, 1, Ii, Ii, Ii, Ii, 128,
           FTB, 1.f, 0, BIG, 1, 0, 0, 0, 0, 0, 0);
        tc(y, a1_wv + wofs, 0, v, Ii / 128, (Bb * Tt) / 128, 1, Ii, Ii, Ii, Ii, 128,
           FTB, 1.f, 0, BIG, 1, 0, 0, 0, 0, 0, 0);
        // scores = 0.125 q k^T  per (b,h)
        tc(q, k, 0, sc, Tt / 128, Tt / 128, Bb * Hh, Dh, Ii, Ii, Tt, 128,
           0, 0.125f, 0, BIG, Hh, TI, Dh, TI, Dh,
           (long long)Hh * Tt * Tt, (long long)Tt * Tt);
        softmax_kernel<<<Bb * Hh * Tt, 256>>>(sc);
        // att = P @ V per (b,h)
        tc(sc, v, 0, att, 1, Tt / 128, Bb * Hh, Tt, Tt, Ii, Ii, 64,
           FTB, 1.f, 0, BIG, Hh,
           (long long)Hh * Tt * Tt, (long long)Tt * Tt, TI, Dh, TI, Dh);
        // h += att @ wo + bo
        tc(att, a1_wo + wofs, a1_bo + d * Ii, h, Ii / 128, (Bb * Tt) / 128, 1,
           Ii, Ii, Ii, Ii, 128, FTB | FBN | FADD, 1.f, 0, BIG, 1, 0, 0, 0, 0, 0, 0);

        // --- cross attention ---
        layernorm_kernel<<<Bb * Tt, 256>>>(h, n2_s + d * Ii, n2_b + d * Ii, y);
        tc(y, a2_wq + wofs, 0, q, Ii / 128, (Bb * Tt) / 128, 1, Ii, Ii, Ii, Ii, 128,
           FTB, 1.f, 0, BIG, 1, 0, 0, 0, 0, 0, 0);
        {
            dim3 g((Ii + 63) / 64, (Bb * Ss + 63) / 64);
            gemm_kernel<<<g, 256>>>(ctx, a2_wk + (long long)d * Cx * Ii, kcb,
                                    Bb * Ss, Ii, Cx, Cx, Ii, Ii);
            gemm_kernel<<<g, 256>>>(ctx, a2_wv + (long long)d * Cx * Ii, vcb,
                                    Bb * Ss, Ii, Cx, Cx, Ii, Ii);
        }
        crossattn_kernel<<<Bb * Hh * Tt / 8, 256>>>(q, kcb, vcb, att);
        tc(att, a2_wo + wofs, a2_bo + d * Ii, h, Ii / 128, (Bb * Tt) / 128, 1,
           Ii, Ii, Ii, Ii, 128, FTB | FBN | FADD, 1.f, 0, BIG, 1, 0, 0, 0, 0, 0, 0);

        // --- feed-forward: conv1d(K=9) -> gelu -> conv1d(K=9), residual ---
        layernorm_kernel<<<Bb * Tt, 256>>>(h, n3_s + d * Ii, n3_b + d * Ii, y);
        {
            long long t1 = (long long)Fi * Ii * Ksz;
            reorder_w<<<(unsigned)((t1 + 255) / 256), 256>>>(ff1_w + d * t1, w1r, t1, Ii);
            long long t2 = (long long)Ii * Fi * Ksz;
            reorder_w<<<(unsigned)((t2 + 255) / 256), 256>>>(ff2_w + d * t2, w2r, t2, Fi);
        }
        // conv1: A = y flattened im2col window (contiguous), clamp [0, T*Ii)
        tc(y, w1r, ff1_b + d * Fi, ffa, Fi / 128, Tt / 128, Bb,
           Ii * Ksz, Ii, Ii * Ksz, Fi, 128, FBN | FGELU, 1.f,
           -(long long)4 * Ii, TI, 1, TI, 0, 0, 0, (long long)Tt * Fi, 0);
        // conv2: h += conv(ffa)
        tc(ffa, w2r, ff2_b + d * Ii, h, Ii / 128, Tt / 128, Bb,
           Fi * Ksz, Fi, Fi * Ksz, Ii, 128, FBN | FADD, 1.f,
           -(long long)4 * Fi, (long long)Tt * Fi, 1,
           (long long)Tt * Fi, 0, 0, 0, TI, 0);
    }

    // out = x + pout_w @ h^T + pout_b
    cudaMemcpyAsync(out, x, (size_t)Bb * Cc * Tt * sizeof(float),
                    cudaMemcpyDeviceToDevice);
    tc(pout_w, h, pout_b, out, Tt / 128, Cc / 128, Bb, Ii, Ii, Ii, Tt, 128,
       FBM | FADD, 1.f, 0, BIG, 1, 0, 0, TI, 0, (long long)Cc * Tt, 0);
}

// round 6
// speedup vs baseline: 2.6515x; 1.8346x over previous
#include <cuda_runtime.h>
#include <cuda_bf16.h>
#include <math.h>
#include <stdint.h>

#define Bb 2
#define Cc 768
#define Tt 2048
#define Ii 768
#define Hh 12
#define Dh 64
#define Ss 16
#define Cx 512
#define Fi 3072
#define Dd 2
#define Ksz 9

typedef __nv_bfloat16 bf16;
typedef unsigned short u16;

// ---------------- scratch ----------------
__device__ float g_h  [(long long)Bb*Tt*Ii];
__device__ float g_q  [(long long)Bb*Tt*Ii];
__device__ float g_sc [(long long)Bb*Hh*Tt*Tt];
__device__ float g_kc [(long long)Bb*Ss*Ii];
__device__ float g_vc [(long long)Bb*Ss*Ii];

__device__ u16 g_gnh[(long long)Bb*Cc*Tt], g_gnl[(long long)Bb*Cc*Tt];
__device__ u16 g_yh [(long long)Bb*Tt*Ii], g_yl [(long long)Bb*Tt*Ii];
__device__ u16 g_qh [(long long)Bb*Tt*Ii], g_ql [(long long)Bb*Tt*Ii];
__device__ u16 g_kh [(long long)Bb*Tt*Ii], g_kl [(long long)Bb*Tt*Ii];
__device__ u16 g_vh [(long long)Bb*Tt*Ii], g_vl [(long long)Bb*Tt*Ii];
__device__ u16 g_ath[(long long)Bb*Tt*Ii], g_atl[(long long)Bb*Tt*Ii];
__device__ u16 g_hh [(long long)Bb*Tt*Ii], g_hl [(long long)Bb*Tt*Ii];
__device__ u16 g_ph [(long long)Bb*Hh*Tt*Tt], g_pl [(long long)Bb*Hh*Tt*Tt];
__device__ u16 g_ffh[(long long)Bb*Tt*Fi], g_ffl[(long long)Bb*Tt*Fi];
__device__ u16 g_w1h[(long long)Fi*Ii*Ksz], g_w1l[(long long)Fi*Ii*Ksz];
__device__ u16 g_w2h[(long long)Ii*Fi*Ksz], g_w2l[(long long)Ii*Fi*Ksz];
__device__ u16 g_wth[8ll*Ii*Ii], g_wtl[8ll*Ii*Ii];

// ---------------- helpers ----------------
__device__ __forceinline__ uint32_t smem_u32(const void* p) {
    uint32_t a;
    asm("{ .reg .u64 t; cvta.to.shared.u64 t, %1; cvt.u32.u64 %0, t; }" : "=r"(a) : "l"(p));
    return a;
}
#define SWZ(x) ((x) ^ ((((uint32_t)(x)) >> 3) & 0x70))
#define CP16(dst, src) asm volatile("cp.async.cg.shared.global [%0], [%1], 16;" :: "r"(dst), "l"(src))
#define CPCOMMIT() asm volatile("cp.async.commit_group;" ::: "memory")
#define CPWAIT1() asm volatile("cp.async.wait_group 1;" ::: "memory")
#define CPWAIT0() asm volatile("cp.async.wait_group 0;" ::: "memory")

__device__ __forceinline__ void ldsm4(uint32_t* r, uint32_t addr) {
    asm volatile("ldmatrix.sync.aligned.m8n8.x4.shared.b16 {%0,%1,%2,%3}, [%4];"
        : "=r"(r[0]), "=r"(r[1]), "=r"(r[2]), "=r"(r[3]) : "r"(addr));
}
__device__ __forceinline__ void mma16816(float* c, const uint32_t* a, const uint32_t* b) {
    asm volatile("mma.sync.aligned.m16n8k16.row.col.f32.bf16.bf16.f32 "
        "{%0,%1,%2,%3}, {%4,%5,%6,%7}, {%8,%9}, {%0,%1,%2,%3};"
        : "+f"(c[0]), "+f"(c[1]), "+f"(c[2]), "+f"(c[3])
        : "r"(a[0]), "r"(a[1]), "r"(a[2]), "r"(a[3]), "r"(b[0]), "r"(b[1]));
}
__device__ __forceinline__ void splitf(float x, u16& h, u16& l) {
    bf16 hb = __float2bfloat16(x);
    bf16 lb = __float2bfloat16(x - __bfloat162float(hb));
    h = __bfloat16_as_ushort(hb);
    l = __bfloat16_as_ushort(lb);
}

// flags
#define FTA   1
#define FTB   2
#define FBN   4
#define FBM   8
#define FGELU 16
#define FADD  32
#define FOUT  64
#define FSPL  128

#define TC_SMEM (131072 + 1024)

// stage 16B segments via cp.async (non-trans): op[r][k] = G[off0 + r*ld + k]
__device__ __forceinline__ void stage_nt(const u16* __restrict__ Gh, const u16* __restrict__ Gl,
        long long off0, long long flim, int ld, int k0, int rows,
        uint32_t smh, uint32_t sml) {
    int nseg = rows * 8;
    for (int idx = threadIdx.x; idx < nseg; idx += 256) {
        int r = idx >> 3, s = idx & 7;
        long long f = off0 + (long long)r * ld + k0 + s * 8;
        uint32_t d = SWZ((uint32_t)(r * 128 + s * 16));
        if (f >= 0 && f + 8 <= flim) {
            CP16(smh + d, Gh + f);
            CP16(sml + d, Gl + f);
        } else {
            asm volatile("st.shared.v4.u32 [%0], {%1,%1,%1,%1};" :: "r"(smh + d), "r"(0));
            asm volatile("st.shared.v4.u32 [%0], {%1,%1,%1,%1};" :: "r"(sml + d), "r"(0));
        }
    }
}
// synchronous trans staging: op[r][k] = G[off0 + k*ld + r]
__device__ __forceinline__ void stage_t(const u16* __restrict__ Gh, const u16* __restrict__ Gl,
        long long off0, long long flim, int ld, int k0, int rows,
        uint32_t smh, uint32_t sml) {
    int items = 64 * (rows >> 3);
    for (int idx = threadIdx.x; idx < items; idx += 256) {
        int kk = idx & 63, r0 = (idx >> 6) << 3;
        long long f = off0 + (long long)(k0 + kk) * ld + r0;
        uint32_t hw[4] = {0,0,0,0}, lw[4] = {0,0,0,0};
        if (f >= 0 && f + 8 <= flim) {
            uint4 a = *(const uint4*)(Gh + f);
            uint4 b = *(const uint4*)(Gl + f);
            hw[0]=a.x; hw[1]=a.y; hw[2]=a.z; hw[3]=a.w;
            lw[0]=b.x; lw[1]=b.y; lw[2]=b.z; lw[3]=b.w;
        }
        const u16* hp = (const u16*)hw;
        const u16* lp = (const u16*)lw;
        #pragma unroll
        for (int j = 0; j < 8; ++j) {
            uint32_t d = SWZ((uint32_t)((r0 + j) * 128 + kk * 2));
            asm volatile("st.shared.u16 [%0], %1;" :: "r"(smh + d), "h"(hp[j]));
            asm volatile("st.shared.u16 [%0], %1;" :: "r"(sml + d), "h"(lp[j]));
        }
    }
}

// ======================= tensor-core GEMM (bf16 hi/lo, cp.async 2-stage) ===========
template<int NT>
__global__ void __launch_bounds__(256, 1)
tc_gemm(const u16* __restrict__ Ah, const u16* __restrict__ Al,
        const u16* __restrict__ Bh, const u16* __restrict__ Bl,
        const float* __restrict__ bias, float* __restrict__ out,
        u16* __restrict__ oh, u16* __restrict__ ol,
        int K, int lda, int ldb, long long ldo, int flags, float alpha,
        long long offA, long long flimA, int b2,
        long long sA1, long long sA2, long long sB1, long long sB2,
        long long sC1, long long sC2)
{
    extern __shared__ char dynsm[];
    long long z1 = blockIdx.z / b2, z2 = blockIdx.z % b2;
    Ah += z1 * sA1 + z2 * sA2;  Al += z1 * sA1 + z2 * sA2;
    Bh += z1 * sB1 + z2 * sB2;  Bl += z1 * sB1 + z2 * sB2;
    long long zc = z1 * sC1 + z2 * sC2;
    out += zc;
    if (flags & FSPL) { oh += zc; ol += zc; }

    const int tid = threadIdx.x;
    const int lane = tid & 31;
    const int wid = tid >> 5;
    const int wm = (wid & 3) * 32;
    const int wn = (wid >> 2) * (NT / 2);
    const int m0 = blockIdx.y * 128;
    const int n0 = blockIdx.x * NT;
    constexpr int NTW = NT / 16;

    uint32_t smBase = smem_u32(dynsm);
    smBase = (smBase + 1023) & ~1023u;

    const int tAf = flags & FTA, tBf = flags & FTB;
    const long long aoff = offA + (tAf ? (long long)m0 : (long long)m0 * lda);
    const long long boff = (tBf ? (long long)n0 : (long long)n0 * ldb);
    const long long BIGL = 1LL << 62;
    const int nc = K / 64;

    float acc[2][NTW][4];
    #pragma unroll
    for (int i = 0; i < 2; ++i)
        #pragma unroll
        for (int j = 0; j < NTW; ++j)
            #pragma unroll
            for (int l = 0; l < 4; ++l) acc[i][j][l] = 0.f;

    const uint32_t aRow = wm + (lane & 15);
    const uint32_t aKof = (lane >> 4) << 3;
    const int bi = lane >> 3;
    const uint32_t bRowBase = wn + ((bi >> 1) << 3) + (lane & 7);
    const uint32_t bKof = (bi & 1) << 3;

    // stage chunk c into buffer s
    auto stage = [&](int c, int s) {
        uint32_t base = smBase + s * 65536;
        if (tAf) stage_t (Ah, Al, aoff, flimA, lda, c * 64, 128, base, base + 16384);
        else     stage_nt(Ah, Al, aoff, flimA, lda, c * 64, 128, base, base + 16384);
        if (tBf) stage_t (Bh, Bl, boff, BIGL, ldb, c * 64, NT, base + 32768, base + 49152);
        else     stage_nt(Bh, Bl, boff, BIGL, ldb, c * 64, NT, base + 32768, base + 49152);
        CPCOMMIT();
    };

    stage(0, 0);
    for (int c = 0; c < nc; ++c) {
        if (c + 1 < nc) { stage(c + 1, (c + 1) & 1); CPWAIT1(); }
        else            { CPWAIT0(); }
        __syncthreads();
        uint32_t base = smBase + (c & 1) * 65536;
        const uint32_t aHi = base, aLo = base + 16384;
        const uint32_t bHi = base + 32768, bLo = base + 49152;
        #pragma unroll
        for (int ks = 0; ks < 4; ++ks) {
            const uint32_t kb = ks * 16;
            uint32_t ah[2][4], al[2][4];
            #pragma unroll
            for (int mt = 0; mt < 2; ++mt) {
                uint32_t off = SWZ((aRow + mt * 16) * 128 + (kb + aKof) * 2);
                ldsm4(ah[mt], aHi + off);
                ldsm4(al[mt], aLo + off);
            }
            #pragma unroll
            for (int bp = 0; bp < NTW / 2; ++bp) {
                uint32_t off = SWZ((bRowBase + bp * 16) * 128 + (kb + bKof) * 2);
                uint32_t bh[4], bl[4];
                ldsm4(bh, bHi + off);
                ldsm4(bl, bLo + off);
                #pragma unroll
                for (int mt = 0; mt < 2; ++mt) {
                    mma16816(acc[mt][2 * bp], ah[mt], bh);
                    mma16816(acc[mt][2 * bp], al[mt], bh);
                    mma16816(acc[mt][2 * bp], ah[mt], bl);
                    mma16816(acc[mt][2 * bp + 1], ah[mt], bh + 2);
                    mma16816(acc[mt][2 * bp + 1], al[mt], bh + 2);
                    mma16816(acc[mt][2 * bp + 1], ah[mt], bl + 2);
                }
            }
        }
        __syncthreads();
    }

    // epilogue
    const int g = lane >> 2, tg = lane & 3;
    #pragma unroll
    for (int mt = 0; mt < 2; ++mt) {
        #pragma unroll
        for (int hf = 0; hf < 2; ++hf) {
            int m = m0 + wm + mt * 16 + g + hf * 8;
            float bm = (flags & FBM) ? bias[m] : 0.f;
            long long rbase = (long long)m * ldo;
            #pragma unroll
            for (int nt = 0; nt < NTW; ++nt) {
                int n = n0 + wn + nt * 8 + tg * 2;
                float v0 = alpha * acc[mt][nt][hf * 2 + 0];
                float v1 = alpha * acc[mt][nt][hf * 2 + 1];
                if (flags & FBN) { v0 += bias[n]; v1 += bias[n + 1]; }
                else if (flags & FBM) { v0 += bm; v1 += bm; }
                if (flags & FGELU) {
                    v0 = 0.5f * v0 * (1.f + erff(v0 * 0.70710678118654752f));
                    v1 = 0.5f * v1 * (1.f + erff(v1 * 0.70710678118654752f));
                }
                if (flags & FADD) { v0 += out[rbase + n]; v1 += out[rbase + n + 1]; }
                if (flags & (FOUT | FADD)) { out[rbase + n] = v0; out[rbase + n + 1] = v1; }
                if (flags & FSPL) {
                    u16 h0, l0, h1, l1;
                    splitf(v0, h0, l0);
                    splitf(v1, h1, l1);
                    oh[rbase + n] = h0; ol[rbase + n] = l0;
                    oh[rbase + n + 1] = h1; ol[rbase + n + 1] = l1;
                }
            }
        }
    }
}

// ---------------- reductions ----------------
__device__ __forceinline__ float blockReduceSum(float v) {
    __shared__ float sm[32];
    int lane = threadIdx.x & 31, wid = threadIdx.x >> 5;
    #pragma unroll
    for (int o = 16; o; o >>= 1) v += __shfl_xor_sync(0xffffffffu, v, o);
    if (lane == 0) sm[wid] = v;
    __syncthreads();
    if (wid == 0) {
        int nw = (blockDim.x + 31) >> 5;
        v = (lane < nw) ? sm[lane] : 0.f;
        #pragma unroll
        for (int o = 16; o; o >>= 1) v += __shfl_xor_sync(0xffffffffu, v, o);
        if (lane == 0) sm[0] = v;
    }
    __syncthreads();
    float r = sm[0];
    __syncthreads();
    return r;
}
__device__ __forceinline__ float blockReduceMax(float v) {
    __shared__ float sm[32];
    int lane = threadIdx.x & 31, wid = threadIdx.x >> 5;
    #pragma unroll
    for (int o = 16; o; o >>= 1) v = fmaxf(v, __shfl_xor_sync(0xffffffffu, v, o));
    if (lane == 0) sm[wid] = v;
    __syncthreads();
    if (wid == 0) {
        int nw = (blockDim.x + 31) >> 5;
        v = (lane < nw) ? sm[lane] : -INFINITY;
        #pragma unroll
        for (int o = 16; o; o >>= 1) v = fmaxf(v, __shfl_xor_sync(0xffffffffu, v, o));
        if (lane == 0) sm[0] = v;
    }
    __syncthreads();
    float r = sm[0];
    __syncthreads();
    return r;
}

__global__ void groupnorm_kernel(const float* __restrict__ x, const float* __restrict__ sc,
                                 const float* __restrict__ bi,
                                 u16* __restrict__ oh, u16* __restrict__ ol) {
    const int CPG = Cc / 32;
    int b = blockIdx.x >> 5, g = blockIdx.x & 31;
    const long long base = ((long long)b * Cc + (long long)g * CPG) * Tt;
    const float* xp = x + base;
    const int n = CPG * Tt;
    float s = 0.f, ss = 0.f;
    for (int i = threadIdx.x; i < n; i += blockDim.x) {
        float v = xp[i]; s += v; ss = fmaf(v, v, ss);
    }
    s = blockReduceSum(s); ss = blockReduceSum(ss);
    float mean = s / n;
    float inv = rsqrtf(ss / n - mean * mean + 1e-6f);
    for (int i = threadIdx.x; i < n; i += blockDim.x) {
        int c = g * CPG + i / Tt;
        float v = (xp[i] - mean) * inv * sc[c] + bi[c];
        u16 hv, lv; splitf(v, hv, lv);
        oh[base + i] = hv; ol[base + i] = lv;
    }
}

__global__ void layernorm_kernel(const float* __restrict__ x, const float* __restrict__ sc,
                                 const float* __restrict__ bi,
                                 u16* __restrict__ oh, u16* __restrict__ ol) {
    const long long rb = (long long)blockIdx.x * Ii;
    const float* row = x + rb;
    float s = 0.f, ss = 0.f;
    for (int i = threadIdx.x; i < Ii; i += blockDim.x) {
        float v = row[i]; s += v; ss = fmaf(v, v, ss);
    }
    s = blockReduceSum(s); ss = blockReduceSum(ss);
    float mean = s / (float)Ii;
    float inv = rsqrtf(ss / (float)Ii - mean * mean + 1e-5f);
    for (int i = threadIdx.x; i < Ii; i += blockDim.x) {
        float v = (row[i] - mean) * inv * sc[i] + bi[i];
        u16 hv, lv; splitf(v, hv, lv);
        oh[rb + i] = hv; ol[rb + i] = lv;
    }
}

// small fp32 gemm for tiny cross-attn K/V projections (M=32)
__global__ void __launch_bounds__(256) gemm_kernel(
    const float* __restrict__ A, const float* __restrict__ B, float* __restrict__ Cp,
    int M, int N, int K, int lda, int ldb, int ldc)
{
    __shared__ float As[16][65];
    __shared__ float Bs[16][65];
    int n0 = blockIdx.x * 64, m0 = blockIdx.y * 64;
    int tid = threadIdx.x;
    int tx = tid & 15, ty = tid >> 4;
    float acc[4][4] = {};
    for (int k0 = 0; k0 < K; k0 += 16) {
        #pragma unroll
        for (int u = 0; u < 4; ++u) {
            int i = tid + u * 256;
            int mm = i >> 4, kk = i & 15;
            int m = m0 + mm, k = k0 + kk;
            As[kk][mm] = (m < M && k < K) ? A[(long long)m * lda + k] : 0.f;
        }
        #pragma unroll
        for (int u = 0; u < 4; ++u) {
            int i = tid + u * 256;
            int kk = i >> 6, nn = i & 63;
            int k = k0 + kk, n = n0 + nn;
            Bs[kk][nn] = (k < K && n < N) ? B[(long long)k * ldb + n] : 0.f;
        }
        __syncthreads();
        #pragma unroll
        for (int kk = 0; kk < 16; ++kk) {
            float a[4], bb[4];
            #pragma unroll
            for (int i = 0; i < 4; ++i) a[i] = As[kk][ty * 4 + i];
            #pragma unroll
            for (int j = 0; j < 4; ++j) bb[j] = Bs[kk][tx * 4 + j];
            #pragma unroll
            for (int i = 0; i < 4; ++i)
                #pragma unroll
                for (int j = 0; j < 4; ++j)
                    acc[i][j] = fmaf(a[i], bb[j], acc[i][j]);
        }
        __syncthreads();
    }
    #pragma unroll
    for (int i = 0; i < 4; ++i) {
        int m = m0 + ty * 4 + i;
        if (m >= M) continue;
        #pragma unroll
        for (int j = 0; j < 4; ++j) {
            int n = n0 + tx * 4 + j;
            if (n < N) Cp[(long long)m * ldc + n] = acc[i][j];
        }
    }
}

__global__ void softmax_kernel(const float* __restrict__ s,
                               u16* __restrict__ oh, u16* __restrict__ ol) {
    const long long rb = (long long)blockIdx.x * Tt;
    const float* row = s + rb;
    int tid = threadIdx.x;
    float v[8];
    float mx = -INFINITY;
    #pragma unroll
    for (int i = 0; i < 8; ++i) { v[i] = row[tid + (i << 8)]; mx = fmaxf(mx, v[i]); }
    mx = blockReduceMax(mx);
    float sum = 0.f;
    #pragma unroll
    for (int i = 0; i < 8; ++i) { v[i] = expf(v[i] - mx); sum += v[i]; }
    sum = blockReduceSum(sum);
    float inv = 1.f / sum;
    #pragma unroll
    for (int i = 0; i < 8; ++i) {
        u16 hv, lv; splitf(v[i] * inv, hv, lv);
        oh[rb + tid + (i << 8)] = hv;
        ol[rb + tid + (i << 8)] = lv;
    }
}

__global__ void crossattn_kernel(const float* __restrict__ q, const float* __restrict__ kc,
                                 const float* __restrict__ vc,
                                 u16* __restrict__ oh, u16* __restrict__ ol) {
    int gw = blockIdx.x * (blockDim.x >> 5) + (threadIdx.x >> 5);
    int lane = threadIdx.x & 31;
    int t = gw % Tt;
    int rem = gw / Tt;
    int h = rem % Hh;
    int b = rem / Hh;
    const float* qp = q + ((long long)(b * Tt + t)) * Ii + h * Dh;
    const float* kb = kc + (long long)b * Ss * Ii + h * Dh;
    const float* vb = vc + (long long)b * Ss * Ii + h * Dh;
    float sj = -INFINITY;
    if (lane < Ss) {
        const float* kp = kb + lane * Ii;
        float acc = 0.f;
        #pragma unroll
        for (int d2 = 0; d2 < Dh; ++d2) acc = fmaf(qp[d2], kp[d2], acc);
        sj = acc * 0.125f;
    }
    float mx = sj;
    #pragma unroll
    for (int o = 16; o; o >>= 1) mx = fmaxf(mx, __shfl_xor_sync(0xffffffffu, mx, o));
    float p = (lane < Ss) ? expf(sj - mx) : 0.f;
    float sum = p;
    #pragma unroll
    for (int o = 16; o; o >>= 1) sum += __shfl_xor_sync(0xffffffffu, sum, o);
    p /= sum;
    float o0 = 0.f, o1 = 0.f;
    #pragma unroll
    for (int j = 0; j < Ss; ++j) {
        float pj = __shfl_sync(0xffffffffu, p, j);
        const float* vp = vb + j * Ii;
        o0 = fmaf(pj, vp[lane], o0);
        o1 = fmaf(pj, vp[lane + 32], o1);
    }
    long long ob = ((long long)(b * Tt + t)) * Ii + h * Dh;
    u16 hv, lv;
    splitf(o0, hv, lv); oh[ob + lane] = hv; ol[ob + lane] = lv;
    splitf(o1, hv, lv); oh[ob + lane + 32] = hv; ol[ob + lane + 32] = lv;
}

// elementwise split fp32 -> bf16 hi/lo
__global__ void split_ew(const float* __restrict__ w, u16* __restrict__ oh,
                         u16* __restrict__ ol, long long n) {
    long long i = (long long)blockIdx.x * 256 + threadIdx.x;
    if (i >= n) return;
    u16 hv, lv; splitf(w[i], hv, lv);
    oh[i] = hv; ol[i] = lv;
}

// transpose 768x768 [K][N] -> [N][K] + split
__global__ void splitT768(const float* __restrict__ w, u16* __restrict__ oh,
                          u16* __restrict__ ol) {
    __shared__ float t[32][33];
    int k0 = blockIdx.y * 32, n0 = blockIdx.x * 32;
    #pragma unroll
    for (int i = 0; i < 32; i += 8)
        t[threadIdx.y + i][threadIdx.x] = w[(long long)(k0 + threadIdx.y + i) * Ii + n0 + threadIdx.x];
    __syncthreads();
    #pragma unroll
    for (int i = 0; i < 32; i += 8) {
        long long o = (long long)(n0 + threadIdx.y + i) * Ii + k0 + threadIdx.x;
        u16 hv, lv; splitf(t[threadIdx.x][threadIdx.y + i], hv, lv);
        oh[o] = hv; ol[o] = lv;
    }
}

// conv weight reorder+split: out[o][k*Cin+c] = in[o][c*Ksz+k]
__global__ void reorder_split(const float* __restrict__ w, u16* __restrict__ oh,
                              u16* __restrict__ ol, long long total, int Cin) {
    long long i = (long long)blockIdx.x * 256 + threadIdx.x;
    if (i >= total) return;
    int rk = Cin * Ksz;
    long long oc = i / rk;
    int r = (int)(i - oc * rk);
    int k = r / Cin, c = r - k * Cin;
    u16 hv, lv; splitf(w[oc * rk + (long long)c * Ksz + k], hv, lv);
    oh[i] = hv; ol[i] = lv;
}

// ---------------- host wrapper ----------------
static void tc(const u16* Ah, const u16* Al, const u16* Bh, const u16* Bl,
               const float* bias, float* out, u16* oh, u16* ol,
               int gx, int gy, int gz, int K, int lda, int ldb, long long ldo,
               int ntile, int flags, float alpha, long long offA, long long flimA,
               int b2, long long sA1, long long sA2, long long sB1, long long sB2,
               long long sC1, long long sC2)
{
    dim3 g(gx, gy, gz);
    if (ntile == 64)
        tc_gemm<64><<<g, 256, TC_SMEM>>>(Ah, Al, Bh, Bl, bias, out, oh, ol, K, lda, ldb,
            ldo, flags, alpha, offA, flimA, b2, sA1, sA2, sB1, sB2, sC1, sC2);
    else
        tc_gemm<128><<<g, 256, TC_SMEM>>>(Ah, Al, Bh, Bl, bias, out, oh, ol, K, lda, ldb,
            ldo, flags, alpha, offA, flimA, b2, sA1, sA2, sB1, sB2, sC1, sC2);
}

extern "C" void kernel_launch(void* const* d_in, const int* in_sizes, int n_in,
                              void* d_out, int out_size) {
    const float* x      = (const float*)d_in[0];
    const float* ctx    = (const float*)d_in[1];
    const float* gn_s   = (const float*)d_in[2];
    const float* gn_b   = (const float*)d_in[3];
    const float* pin_w  = (const float*)d_in[4];
    const float* pin_b  = (const float*)d_in[5];
    const float* n1_s   = (const float*)d_in[6];
    const float* n1_b   = (const float*)d_in[7];
    const float* a1_wq  = (const float*)d_in[8];
    const float* a1_wk  = (const float*)d_in[9];
    const float* a1_wv  = (const float*)d_in[10];
    const float* a1_wo  = (const float*)d_in[11];
    const float* a1_bo  = (const float*)d_in[12];
    const float* n2_s   = (const float*)d_in[13];
    const float* n2_b   = (const float*)d_in[14];
    const float* a2_wq  = (const float*)d_in[15];
    const float* a2_wk  = (const float*)d_in[16];
    const float* a2_wv  = (const float*)d_in[17];
    const float* a2_wo  = (const float*)d_in[18];
    const float* a2_bo  = (const float*)d_in[19];
    const float* n3_s   = (const float*)d_in[20];
    const float* n3_b   = (const float*)d_in[21];
    const float* ff1_w  = (const float*)d_in[22];
    const float* ff1_b  = (const float*)d_in[23];
    const float* ff2_w  = (const float*)d_in[24];
    const float* ff2_b  = (const float*)d_in[25];
    const float* pout_w = (const float*)d_in[26];
    const float* pout_b = (const float*)d_in[27];
    float* out = (float*)d_out;

    cudaFuncSetAttribute(tc_gemm<128>, cudaFuncAttributeMaxDynamicSharedMemorySize, TC_SMEM);
    cudaFuncSetAttribute(tc_gemm<64>,  cudaFuncAttributeMaxDynamicSharedMemorySize, TC_SMEM);

    float *h, *q, *sc, *kcb, *vcb;
    u16 *gnh, *gnl, *yh, *yl, *qh, *ql, *kh, *kl, *vh, *vl, *ath, *atl;
    u16 *hh, *hl, *ph, *pl, *ffh, *ffl, *w1h, *w1l, *w2h, *w2l, *wth, *wtl;
    cudaGetSymbolAddress((void**)&h,   g_h);
    cudaGetSymbolAddress((void**)&q,   g_q);
    cudaGetSymbolAddress((void**)&sc,  g_sc);
    cudaGetSymbolAddress((void**)&kcb, g_kc);
    cudaGetSymbolAddress((void**)&vcb, g_vc);
    cudaGetSymbolAddress((void**)&gnh, g_gnh); cudaGetSymbolAddress((void**)&gnl, g_gnl);
    cudaGetSymbolAddress((void**)&yh,  g_yh);  cudaGetSymbolAddress((void**)&yl,  g_yl);
    cudaGetSymbolAddress((void**)&qh,  g_qh);  cudaGetSymbolAddress((void**)&ql,  g_ql);
    cudaGetSymbolAddress((void**)&kh,  g_kh);  cudaGetSymbolAddress((void**)&kl,  g_kl);
    cudaGetSymbolAddress((void**)&vh,  g_vh);  cudaGetSymbolAddress((void**)&vl,  g_vl);
    cudaGetSymbolAddress((void**)&ath, g_ath); cudaGetSymbolAddress((void**)&atl, g_atl);
    cudaGetSymbolAddress((void**)&hh,  g_hh);  cudaGetSymbolAddress((void**)&hl,  g_hl);
    cudaGetSymbolAddress((void**)&ph,  g_ph);  cudaGetSymbolAddress((void**)&pl,  g_pl);
    cudaGetSymbolAddress((void**)&ffh, g_ffh); cudaGetSymbolAddress((void**)&ffl, g_ffl);
    cudaGetSymbolAddress((void**)&w1h, g_w1h); cudaGetSymbolAddress((void**)&w1l, g_w1l);
    cudaGetSymbolAddress((void**)&w2h, g_w2h); cudaGetSymbolAddress((void**)&w2l, g_w2l);
    cudaGetSymbolAddress((void**)&wth, g_wth); cudaGetSymbolAddress((void**)&wtl, g_wtl);

    const long long BIG = 1LL << 62;
    const long long TI = (long long)Tt * Ii;
    const long long WSZ = (long long)Ii * Ii;
    const unsigned WB = (unsigned)((WSZ + 255) / 256);

    // weight conversions done once: pin (slot6, already [N][K]), pout (slot7)
    split_ew<<<WB, 256>>>(pin_w,  wth + 6 * WSZ, wtl + 6 * WSZ, WSZ);
    split_ew<<<WB, 256>>>(pout_w, wth + 7 * WSZ, wtl + 7 * WSZ, WSZ);

    // GroupNorm -> split
    groupnorm_kernel<<<Bb * 32, 256>>>(x, gn_s, gn_b, gnh, gnl);

    // proj_in: h = pin_w . gn + pin_b (A trans-staged)
    tc(gnh, gnl, wth + 6 * WSZ, wtl + 6 * WSZ, pin_b, h, 0, 0,
       Ii / 128, Tt / 128, Bb, Cc, Tt, Cc, Ii, 128, FTA | FBN | FOUT, 1.f,
       0, (long long)Cc * Tt, 1, (long long)Cc * Tt, 0, 0, 0, TI, 0);

    for (int d = 0; d < Dd; ++d) {
        long long wofs = (long long)d * WSZ;
        dim3 tg(24, 24), tb(32, 8);
        splitT768<<<tg, tb>>>(a1_wq + wofs, wth + 0 * WSZ, wtl + 0 * WSZ);
        splitT768<<<tg, tb>>>(a1_wk + wofs, wth + 1 * WSZ, wtl + 1 * WSZ);
        splitT768<<<tg, tb>>>(a1_wv + wofs, wth + 2 * WSZ, wtl + 2 * WSZ);
        splitT768<<<tg, tb>>>(a1_wo + wofs, wth + 3 * WSZ, wtl + 3 * WSZ);
        splitT768<<<tg, tb>>>(a2_wq + wofs, wth + 4 * WSZ, wtl + 4 * WSZ);
        splitT768<<<tg, tb>>>(a2_wo + wofs, wth + 5 * WSZ, wtl + 5 * WSZ);
        {
            long long t1 = (long long)Fi * Ii * Ksz;
            reorder_split<<<(unsigned)((t1 + 255) / 256), 256>>>(ff1_w + d * t1, w1h, w1l, t1, Ii);
            long long t2 = (long long)Ii * Fi * Ksz;
            reorder_split<<<(unsigned)((t2 + 255) / 256), 256>>>(ff2_w + d * t2, w2h, w2l, t2, Fi);
        }

        // --- self attention ---
        layernorm_kernel<<<Bb * Tt, 256>>>(h, n1_s + d * Ii, n1_b + d * Ii, yh, yl);
        tc(yh, yl, wth + 0 * WSZ, wtl + 0 * WSZ, 0, sc, qh, ql, Ii / 128, (Bb * Tt) / 128, 1,
           Ii, Ii, Ii, Ii, 128, FSPL, 1.f, 0, BIG, 1, 0, 0, 0, 0, 0, 0);
        tc(yh, yl, wth + 1 * WSZ, wtl + 1 * WSZ, 0, sc, kh, kl, Ii / 128, (Bb * Tt) / 128, 1,
           Ii, Ii, Ii, Ii, 128, FSPL, 1.f, 0, BIG, 1, 0, 0, 0, 0, 0, 0);
        tc(yh, yl, wth + 2 * WSZ, wtl + 2 * WSZ, 0, sc, vh, vl, Ii / 128, (Bb * Tt) / 128, 1,
           Ii, Ii, Ii, Ii, 128, FSPL, 1.f, 0, BIG, 1, 0, 0, 0, 0, 0, 0);
        // scores = 0.125 q k^T per (b,h)
        tc(qh, ql, kh, kl, 0, sc, 0, 0, Tt / 128, Tt / 128, Bb * Hh, Dh, Ii, Ii, Tt, 128,
           FOUT, 0.125f, 0, BIG, Hh, TI, Dh, TI, Dh,
           (long long)Hh * Tt * Tt, (long long)Tt * Tt);
        softmax_kernel<<<Bb * Hh * Tt, 256>>>(sc, ph, pl);
        // att = P @ V per (b,h) (B trans-staged)
        tc(ph, pl, vh, vl, 0, sc, ath, atl, 1, Tt / 128, Bb * Hh, Tt, Tt, Ii, Ii, 64,
           FTB | FSPL, 1.f, 0, BIG, Hh,
           (long long)Hh * Tt * Tt, (long long)Tt * Tt, TI, Dh, TI, Dh);
        // h += att @ wo + bo
        tc(ath, atl, wth + 3 * WSZ, wtl + 3 * WSZ, a1_bo + d * Ii, h, 0, 0,
           Ii / 128, (Bb * Tt) / 128, 1, Ii, Ii, Ii, Ii, 128,
           FBN | FADD, 1.f, 0, BIG, 1, 0, 0, 0, 0, 0, 0);

        // --- cross attention ---
        layernorm_kernel<<<Bb * Tt, 256>>>(h, n2_s + d * Ii, n2_b + d * Ii, yh, yl);
        tc(yh, yl, wth + 4 * WSZ, wtl + 4 * WSZ, 0, q, 0, 0, Ii / 128, (Bb * Tt) / 128, 1,
           Ii, Ii, Ii, Ii, 128, FOUT, 1.f, 0, BIG, 1, 0, 0, 0, 0, 0, 0);
        {
            dim3 g((Ii + 63) / 64, (Bb * Ss + 63) / 64);
            gemm_kernel<<<g, 256>>>(ctx, a2_wk + (long long)d * Cx * Ii, kcb,
                                    Bb * Ss, Ii, Cx, Cx, Ii, Ii);
            gemm_kernel<<<g, 256>>>(ctx, a2_wv + (long long)d * Cx * Ii, vcb,
                                    Bb * Ss, Ii, Cx, Cx, Ii, Ii);
        }
        crossattn_kernel<<<Bb * Hh * Tt / 8, 256>>>(q, kcb, vcb, ath, atl);
        tc(ath, atl, wth + 5 * WSZ, wtl + 5 * WSZ, a2_bo + d * Ii, h, 0, 0,
           Ii / 128, (Bb * Tt) / 128, 1, Ii, Ii, Ii, Ii, 128,
           FBN | FADD, 1.f, 0, BIG, 1, 0, 0, 0, 0, 0, 0);

        // --- feed-forward ---
        layernorm_kernel<<<Bb * Tt, 256>>>(h, n3_s + d * Ii, n3_b + d * Ii, yh, yl);
        // conv1: A = y windows (contiguous im2col), out gelu-split
        tc(yh, yl, w1h, w1l, ff1_b + d * Fi, sc, ffh, ffl, Fi / 128, Tt / 128, Bb,
           Ii * Ksz, Ii, Ii * Ksz, Fi, 128, FBN | FGELU | FSPL, 1.f,
           -(long long)4 * Ii, TI, 1, TI, 0, 0, 0, (long long)Tt * Fi, 0);
        // conv2: h += conv(ff) (+ split h at final depth for proj_out)
        tc(ffh, ffl, w2h, w2l, ff2_b + d * Ii, h, hh, hl, Ii / 128, Tt / 128, Bb,
           Fi * Ksz, Fi, Fi * Ksz, Ii, 128,
           FBN | FADD | (d == Dd - 1 ? FSPL : 0), 1.f,
           -(long long)4 * Fi, (long long)Tt * Fi, 1,
           (long long)Tt * Fi, 0, 0, 0, TI, 0);
    }

    // out = x + pout_w @ h^T + pout_b
    cudaMemcpyAsync(out, x, (size_t)Bb * Cc * Tt * sizeof(float),
                    cudaMemcpyDeviceToDevice);
    tc(wth + 7 * WSZ, wtl + 7 * WSZ, hh, hl, pout_b, out, 0, 0,
       Tt / 128, Cc / 128, Bb, Ii, Ii, Ii, Tt, 128, FBM | FADD, 1.f,
       0, BIG, 1, 0, 0, TI, 0, (long long)Cc * Tt, 0);
}

// round 7
// speedup vs baseline: 2.6949x; 1.0164x over previous
#include <cuda_runtime.h>
#include <cuda_bf16.h>
#include <math.h>
#include <stdint.h>

#define Bb 2
#define Cc 768
#define Tt 2048
#define Ii 768
#define Hh 12
#define Dh 64
#define Ss 16
#define Cx 512
#define Fi 3072
#define Dd 2
#define Ksz 9

typedef __nv_bfloat16 bf16;
typedef unsigned short u16;

// ---------------- scratch ----------------
__device__ float g_h  [(long long)Bb*Tt*Ii];
__device__ float g_q  [(long long)Bb*Tt*Ii];
__device__ float g_sc [(long long)Bb*Hh*Tt*Tt];
__device__ float g_kc [(long long)Bb*Ss*Ii];
__device__ float g_vc [(long long)Bb*Ss*Ii];

__device__ u16 g_gnh[(long long)Bb*Cc*Tt], g_gnl[(long long)Bb*Cc*Tt];
__device__ u16 g_yh [(long long)Bb*Tt*Ii], g_yl [(long long)Bb*Tt*Ii];
__device__ u16 g_qh [(long long)Bb*Tt*Ii], g_ql [(long long)Bb*Tt*Ii];
__device__ u16 g_kh [(long long)Bb*Tt*Ii], g_kl [(long long)Bb*Tt*Ii];
__device__ u16 g_vh [(long long)Bb*Tt*Ii], g_vl [(long long)Bb*Tt*Ii];
__device__ u16 g_vth[(long long)Bb*Ii*Tt], g_vtl[(long long)Bb*Ii*Tt];
__device__ u16 g_ath[(long long)Bb*Tt*Ii], g_atl[(long long)Bb*Tt*Ii];
__device__ u16 g_hh [(long long)Bb*Tt*Ii], g_hl [(long long)Bb*Tt*Ii];
__device__ u16 g_ph [(long long)Bb*Hh*Tt*Tt], g_pl [(long long)Bb*Hh*Tt*Tt];
__device__ u16 g_ffh[(long long)Bb*Tt*Fi], g_ffl[(long long)Bb*Tt*Fi];
__device__ u16 g_w1h[(long long)Fi*Ii*Ksz], g_w1l[(long long)Fi*Ii*Ksz];
__device__ u16 g_w2h[(long long)Ii*Fi*Ksz], g_w2l[(long long)Ii*Fi*Ksz];
__device__ u16 g_wth[8ll*Ii*Ii], g_wtl[8ll*Ii*Ii];

// ---------------- helpers ----------------
__device__ __forceinline__ uint32_t smem_u32(const void* p) {
    uint32_t a;
    asm("{ .reg .u64 t; cvta.to.shared.u64 t, %1; cvt.u32.u64 %0, t; }" : "=r"(a) : "l"(p));
    return a;
}
#define SWZ(x) ((x) ^ ((((uint32_t)(x)) >> 3) & 0x70))
#define CP16(dst, src) asm volatile("cp.async.cg.shared.global [%0], [%1], 16;" :: "r"(dst), "l"(src))
#define CPCOMMIT() asm volatile("cp.async.commit_group;" ::: "memory")
#define CPWAIT1() asm volatile("cp.async.wait_group 1;" ::: "memory")
#define CPWAIT0() asm volatile("cp.async.wait_group 0;" ::: "memory")

__device__ __forceinline__ void ldsm4(uint32_t* r, uint32_t addr) {
    asm volatile("ldmatrix.sync.aligned.m8n8.x4.shared.b16 {%0,%1,%2,%3}, [%4];"
        : "=r"(r[0]), "=r"(r[1]), "=r"(r[2]), "=r"(r[3]) : "r"(addr));
}
__device__ __forceinline__ void mma16816(float* c, const uint32_t* a, const uint32_t* b) {
    asm volatile("mma.sync.aligned.m16n8k16.row.col.f32.bf16.bf16.f32 "
        "{%0,%1,%2,%3}, {%4,%5,%6,%7}, {%8,%9}, {%0,%1,%2,%3};"
        : "+f"(c[0]), "+f"(c[1]), "+f"(c[2]), "+f"(c[3])
        : "r"(a[0]), "r"(a[1]), "r"(a[2]), "r"(a[3]), "r"(b[0]), "r"(b[1]));
}
__device__ __forceinline__ void splitf(float x, u16& h, u16& l) {
    bf16 hb = __float2bfloat16(x);
    bf16 lb = __float2bfloat16(x - __bfloat162float(hb));
    h = __bfloat16_as_ushort(hb);
    l = __bfloat16_as_ushort(lb);
}

// flags
#define FTA   1
#define FTB   2
#define FBN   4
#define FBM   8
#define FGELU 16
#define FADD  32
#define FOUT  64
#define FSPL  128

#define TC_SMEM (131072 + 1024)

// stage 16B segments via cp.async (non-trans): op[r][k] = G[off0 + r*ld + k]
__device__ __forceinline__ void stage_nt(const u16* __restrict__ Gh, const u16* __restrict__ Gl,
        long long off0, long long flim, int ld, int k0, int rows,
        uint32_t smh, uint32_t sml) {
    int nseg = rows * 8;
    for (int idx = threadIdx.x; idx < nseg; idx += 256) {
        int r = idx >> 3, s = idx & 7;
        long long f = off0 + (long long)r * ld + k0 + s * 8;
        uint32_t d = SWZ((uint32_t)(r * 128 + s * 16));
        if (f >= 0 && f + 8 <= flim) {
            CP16(smh + d, Gh + f);
            CP16(sml + d, Gl + f);
        } else {
            asm volatile("st.shared.v4.u32 [%0], {%1,%1,%1,%1};" :: "r"(smh + d), "r"(0));
            asm volatile("st.shared.v4.u32 [%0], {%1,%1,%1,%1};" :: "r"(sml + d), "r"(0));
        }
    }
}
// synchronous trans staging: op[r][k] = G[off0 + k*ld + r]
__device__ __forceinline__ void stage_t(const u16* __restrict__ Gh, const u16* __restrict__ Gl,
        long long off0, long long flim, int ld, int k0, int rows,
        uint32_t smh, uint32_t sml) {
    int items = 64 * (rows >> 3);
    for (int idx = threadIdx.x; idx < items; idx += 256) {
        int kk = idx & 63, r0 = (idx >> 6) << 3;
        long long f = off0 + (long long)(k0 + kk) * ld + r0;
        uint32_t hw[4] = {0,0,0,0}, lw[4] = {0,0,0,0};
        if (f >= 0 && f + 8 <= flim) {
            uint4 a = *(const uint4*)(Gh + f);
            uint4 b = *(const uint4*)(Gl + f);
            hw[0]=a.x; hw[1]=a.y; hw[2]=a.z; hw[3]=a.w;
            lw[0]=b.x; lw[1]=b.y; lw[2]=b.z; lw[3]=b.w;
        }
        const u16* hp = (const u16*)hw;
        const u16* lp = (const u16*)lw;
        #pragma unroll
        for (int j = 0; j < 8; ++j) {
            uint32_t d = SWZ((uint32_t)((r0 + j) * 128 + kk * 2));
            asm volatile("st.shared.u16 [%0], %1;" :: "r"(smh + d), "h"(hp[j]));
            asm volatile("st.shared.u16 [%0], %1;" :: "r"(sml + d), "h"(lp[j]));
        }
    }
}

// ======================= tensor-core GEMM (bf16 hi/lo, cp.async 2-stage) ===========
template<int NT>
__global__ void __launch_bounds__(256, 1)
tc_gemm(const u16* __restrict__ Ah, const u16* __restrict__ Al,
        const u16* __restrict__ Bh, const u16* __restrict__ Bl,
        const float* __restrict__ bias, float* __restrict__ out,
        u16* __restrict__ oh, u16* __restrict__ ol,
        int K, int lda, int ldb, long long ldo, int flags, float alpha,
        long long offA, long long flimA, int b2,
        long long sA1, long long sA2, long long sB1, long long sB2,
        long long sC1, long long sC2)
{
    extern __shared__ char dynsm[];
    long long z1 = blockIdx.z / b2, z2 = blockIdx.z % b2;
    Ah += z1 * sA1 + z2 * sA2;  Al += z1 * sA1 + z2 * sA2;
    Bh += z1 * sB1 + z2 * sB2;  Bl += z1 * sB1 + z2 * sB2;
    long long zc = z1 * sC1 + z2 * sC2;
    out += zc;
    if (flags & FSPL) { oh += zc; ol += zc; }

    const int tid = threadIdx.x;
    const int lane = tid & 31;
    const int wid = tid >> 5;
    const int wm = (wid & 3) * 32;
    const int wn = (wid >> 2) * (NT / 2);
    const int m0 = blockIdx.y * 128;
    const int n0 = blockIdx.x * NT;
    constexpr int NTW = NT / 16;
    constexpr int NB = NTW / 2;

    uint32_t smBase = smem_u32(dynsm);
    smBase = (smBase + 1023) & ~1023u;

    const int tAf = flags & FTA, tBf = flags & FTB;
    const long long aoff = offA + (tAf ? (long long)m0 : (long long)m0 * lda);
    const long long boff = (tBf ? (long long)n0 : (long long)n0 * ldb);
    const long long BIGL = 1LL << 62;
    const int nc = K / 64;

    float acc[2][NTW][4];
    #pragma unroll
    for (int i = 0; i < 2; ++i)
        #pragma unroll
        for (int j = 0; j < NTW; ++j)
            #pragma unroll
            for (int l = 0; l < 4; ++l) acc[i][j][l] = 0.f;

    const uint32_t aRow = wm + (lane & 15);
    const uint32_t aKof = (lane >> 4) << 3;
    const int bi = lane >> 3;
    const uint32_t bRowBase = wn + ((bi >> 1) << 3) + (lane & 7);
    const uint32_t bKof = (bi & 1) << 3;

    auto stage = [&](int c, int s) {
        uint32_t base = smBase + s * 65536;
        if (tAf) stage_t (Ah, Al, aoff, flimA, lda, c * 64, 128, base, base + 16384);
        else     stage_nt(Ah, Al, aoff, flimA, lda, c * 64, 128, base, base + 16384);
        if (tBf) stage_t (Bh, Bl, boff, BIGL, ldb, c * 64, NT, base + 32768, base + 49152);
        else     stage_nt(Bh, Bl, boff, BIGL, ldb, c * 64, NT, base + 32768, base + 49152);
        CPCOMMIT();
    };

    stage(0, 0);
    for (int c = 0; c < nc; ++c) {
        if (c + 1 < nc) { stage(c + 1, (c + 1) & 1); CPWAIT1(); }
        else            { CPWAIT0(); }
        __syncthreads();
        uint32_t base = smBase + (c & 1) * 65536;
        const uint32_t aHi = base, aLo = base + 16384;
        const uint32_t bHi = base + 32768, bLo = base + 49152;
        #pragma unroll
        for (int ks = 0; ks < 4; ++ks) {
            const uint32_t kb = ks * 16;
            uint32_t ah[2][4], al[2][4], bh[NB][4], bl[NB][4];
            #pragma unroll
            for (int mt = 0; mt < 2; ++mt) {
                uint32_t off = SWZ((aRow + mt * 16) * 128 + (kb + aKof) * 2);
                ldsm4(ah[mt], aHi + off);
                ldsm4(al[mt], aLo + off);
            }
            #pragma unroll
            for (int bp = 0; bp < NB; ++bp) {
                uint32_t off = SWZ((bRowBase + bp * 16) * 128 + (kb + bKof) * 2);
                ldsm4(bh[bp], bHi + off);
                ldsm4(bl[bp], bLo + off);
            }
            // term 1: hi*hi — all independent accumulators
            #pragma unroll
            for (int bp = 0; bp < NB; ++bp)
                #pragma unroll
                for (int mt = 0; mt < 2; ++mt) {
                    mma16816(acc[mt][2 * bp],     ah[mt], bh[bp]);
                    mma16816(acc[mt][2 * bp + 1], ah[mt], bh[bp] + 2);
                }
            // term 2: lo*hi — spaced 2*NTW issues from matching term-1 mma
            #pragma unroll
            for (int bp = 0; bp < NB; ++bp)
                #pragma unroll
                for (int mt = 0; mt < 2; ++mt) {
                    mma16816(acc[mt][2 * bp],     al[mt], bh[bp]);
                    mma16816(acc[mt][2 * bp + 1], al[mt], bh[bp] + 2);
                }
            // term 3: hi*lo
            #pragma unroll
            for (int bp = 0; bp < NB; ++bp)
                #pragma unroll
                for (int mt = 0; mt < 2; ++mt) {
                    mma16816(acc[mt][2 * bp],     ah[mt], bl[bp]);
                    mma16816(acc[mt][2 * bp + 1], ah[mt], bl[bp] + 2);
                }
        }
        __syncthreads();
    }

    // epilogue
    const int g = lane >> 2, tg = lane & 3;
    #pragma unroll
    for (int mt = 0; mt < 2; ++mt) {
        #pragma unroll
        for (int hf = 0; hf < 2; ++hf) {
            int m = m0 + wm + mt * 16 + g + hf * 8;
            float bm = (flags & FBM) ? bias[m] : 0.f;
            long long rbase = (long long)m * ldo;
            #pragma unroll
            for (int nt = 0; nt < NTW; ++nt) {
                int n = n0 + wn + nt * 8 + tg * 2;
                float v0 = alpha * acc[mt][nt][hf * 2 + 0];
                float v1 = alpha * acc[mt][nt][hf * 2 + 1];
                if (flags & FBN) { v0 += bias[n]; v1 += bias[n + 1]; }
                else if (flags & FBM) { v0 += bm; v1 += bm; }
                if (flags & FGELU) {
                    v0 = 0.5f * v0 * (1.f + erff(v0 * 0.70710678118654752f));
                    v1 = 0.5f * v1 * (1.f + erff(v1 * 0.70710678118654752f));
                }
                if (flags & FADD) { v0 += out[rbase + n]; v1 += out[rbase + n + 1]; }
                if (flags & (FOUT | FADD)) { out[rbase + n] = v0; out[rbase + n + 1] = v1; }
                if (flags & FSPL) {
                    u16 h0, l0, h1, l1;
                    splitf(v0, h0, l0);
                    splitf(v1, h1, l1);
                    oh[rbase + n] = h0; ol[rbase + n] = l0;
                    oh[rbase + n + 1] = h1; ol[rbase + n + 1] = l1;
                }
            }
        }
    }
}

// ---------------- reductions ----------------
__device__ __forceinline__ float blockReduceSum(float v) {
    __shared__ float sm[32];
    int lane = threadIdx.x & 31, wid = threadIdx.x >> 5;
    #pragma unroll
    for (int o = 16; o; o >>= 1) v += __shfl_xor_sync(0xffffffffu, v, o);
    if (lane == 0) sm[wid] = v;
    __syncthreads();
    if (wid == 0) {
        int nw = (blockDim.x + 31) >> 5;
        v = (lane < nw) ? sm[lane] : 0.f;
        #pragma unroll
        for (int o = 16; o; o >>= 1) v += __shfl_xor_sync(0xffffffffu, v, o);
        if (lane == 0) sm[0] = v;
    }
    __syncthreads();
    float r = sm[0];
    __syncthreads();
    return r;
}
__device__ __forceinline__ float blockReduceMax(float v) {
    __shared__ float sm[32];
    int lane = threadIdx.x & 31, wid = threadIdx.x >> 5;
    #pragma unroll
    for (int o = 16; o; o >>= 1) v = fmaxf(v, __shfl_xor_sync(0xffffffffu, v, o));
    if (lane == 0) sm[wid] = v;
    __syncthreads();
    if (wid == 0) {
        int nw = (blockDim.x + 31) >> 5;
        v = (lane < nw) ? sm[lane] : -INFINITY;
        #pragma unroll
        for (int o = 16; o; o >>= 1) v = fmaxf(v, __shfl_xor_sync(0xffffffffu, v, o));
        if (lane == 0) sm[0] = v;
    }
    __syncthreads();
    float r = sm[0];
    __syncthreads();
    return r;
}

__global__ void groupnorm_kernel(const float* __restrict__ x, const float* __restrict__ sc,
                                 const float* __restrict__ bi,
                                 u16* __restrict__ oh, u16* __restrict__ ol) {
    const int CPG = Cc / 32;
    int b = blockIdx.x >> 5, g = blockIdx.x & 31;
    const long long base = ((long long)b * Cc + (long long)g * CPG) * Tt;
    const float* xp = x + base;
    const int n = CPG * Tt;
    float s = 0.f, ss = 0.f;
    for (int i = threadIdx.x; i < n; i += blockDim.x) {
        float v = xp[i]; s += v; ss = fmaf(v, v, ss);
    }
    s = blockReduceSum(s); ss = blockReduceSum(ss);
    float mean = s / n;
    float inv = rsqrtf(ss / n - mean * mean + 1e-6f);
    for (int i = threadIdx.x; i < n; i += blockDim.x) {
        int c = g * CPG + i / Tt;
        float v = (xp[i] - mean) * inv * sc[c] + bi[c];
        u16 hv, lv; splitf(v, hv, lv);
        oh[base + i] = hv; ol[base + i] = lv;
    }
}

__global__ void layernorm_kernel(const float* __restrict__ x, const float* __restrict__ sc,
                                 const float* __restrict__ bi,
                                 u16* __restrict__ oh, u16* __restrict__ ol) {
    const long long rb = (long long)blockIdx.x * Ii;
    const float* row = x + rb;
    float s = 0.f, ss = 0.f;
    for (int i = threadIdx.x; i < Ii; i += blockDim.x) {
        float v = row[i]; s += v; ss = fmaf(v, v, ss);
    }
    s = blockReduceSum(s); ss = blockReduceSum(ss);
    float mean = s / (float)Ii;
    float inv = rsqrtf(ss / (float)Ii - mean * mean + 1e-5f);
    for (int i = threadIdx.x; i < Ii; i += blockDim.x) {
        float v = (row[i] - mean) * inv * sc[i] + bi[i];
        u16 hv, lv; splitf(v, hv, lv);
        oh[rb + i] = hv; ol[rb + i] = lv;
    }
}

// small fp32 gemm for tiny cross-attn K/V projections (M=32)
__global__ void __launch_bounds__(256) gemm_kernel(
    const float* __restrict__ A, const float* __restrict__ B, float* __restrict__ Cp,
    int M, int N, int K, int lda, int ldb, int ldc)
{
    __shared__ float As[16][65];
    __shared__ float Bs[16][65];
    int n0 = blockIdx.x * 64, m0 = blockIdx.y * 64;
    int tid = threadIdx.x;
    int tx = tid & 15, ty = tid >> 4;
    float acc[4][4] = {};
    for (int k0 = 0; k0 < K; k0 += 16) {
        #pragma unroll
        for (int u = 0; u < 4; ++u) {
            int i = tid + u * 256;
            int mm = i >> 4, kk = i & 15;
            int m = m0 + mm, k = k0 + kk;
            As[kk][mm] = (m < M && k < K) ? A[(long long)m * lda + k] : 0.f;
        }
        #pragma unroll
        for (int u = 0; u < 4; ++u) {
            int i = tid + u * 256;
            int kk = i >> 6, nn = i & 63;
            int k = k0 + kk, n = n0 + nn;
            Bs[kk][nn] = (k < K && n < N) ? B[(long long)k * ldb + n] : 0.f;
        }
        __syncthreads();
        #pragma unroll
        for (int kk = 0; kk < 16; ++kk) {
            float a[4], bb[4];
            #pragma unroll
            for (int i = 0; i < 4; ++i) a[i] = As[kk][ty * 4 + i];
            #pragma unroll
            for (int j = 0; j < 4; ++j) bb[j] = Bs[kk][tx * 4 + j];
            #pragma unroll
            for (int i = 0; i < 4; ++i)
                #pragma unroll
                for (int j = 0; j < 4; ++j)
                    acc[i][j] = fmaf(a[i], bb[j], acc[i][j]);
        }
        __syncthreads();
    }
    #pragma unroll
    for (int i = 0; i < 4; ++i) {
        int m = m0 + ty * 4 + i;
        if (m >= M) continue;
        #pragma unroll
        for (int j = 0; j < 4; ++j) {
            int n = n0 + tx * 4 + j;
            if (n < N) Cp[(long long)m * ldc + n] = acc[i][j];
        }
    }
}

__global__ void softmax_kernel(const float* __restrict__ s,
                               u16* __restrict__ oh, u16* __restrict__ ol) {
    const long long rb = (long long)blockIdx.x * Tt;
    const float* row = s + rb;
    int tid = threadIdx.x;
    float v[8];
    float mx = -INFINITY;
    #pragma unroll
    for (int i = 0; i < 8; ++i) { v[i] = row[tid + (i << 8)]; mx = fmaxf(mx, v[i]); }
    mx = blockReduceMax(mx);
    float sum = 0.f;
    #pragma unroll
    for (int i = 0; i < 8; ++i) { v[i] = expf(v[i] - mx); sum += v[i]; }
    sum = blockReduceSum(sum);
    float inv = 1.f / sum;
    #pragma unroll
    for (int i = 0; i < 8; ++i) {
        u16 hv, lv; splitf(v[i] * inv, hv, lv);
        oh[rb + tid + (i << 8)] = hv;
        ol[rb + tid + (i << 8)] = lv;
    }
}

__global__ void crossattn_kernel(const float* __restrict__ q, const float* __restrict__ kc,
                                 const float* __restrict__ vc,
                                 u16* __restrict__ oh, u16* __restrict__ ol) {
    int gw = blockIdx.x * (blockDim.x >> 5) + (threadIdx.x >> 5);
    int lane = threadIdx.x & 31;
    int t = gw % Tt;
    int rem = gw / Tt;
    int h = rem % Hh;
    int b = rem / Hh;
    const float* qp = q + ((long long)(b * Tt + t)) * Ii + h * Dh;
    const float* kb = kc + (long long)b * Ss * Ii + h * Dh;
    const float* vb = vc + (long long)b * Ss * Ii + h * Dh;
    float sj = -INFINITY;
    if (lane < Ss) {
        const float* kp = kb + lane * Ii;
        float acc = 0.f;
        #pragma unroll
        for (int d2 = 0; d2 < Dh; ++d2) acc = fmaf(qp[d2], kp[d2], acc);
        sj = acc * 0.125f;
    }
    float mx = sj;
    #pragma unroll
    for (int o = 16; o; o >>= 1) mx = fmaxf(mx, __shfl_xor_sync(0xffffffffu, mx, o));
    float p = (lane < Ss) ? expf(sj - mx) : 0.f;
    float sum = p;
    #pragma unroll
    for (int o = 16; o; o >>= 1) sum += __shfl_xor_sync(0xffffffffu, sum, o);
    p /= sum;
    float o0 = 0.f, o1 = 0.f;
    #pragma unroll
    for (int j = 0; j < Ss; ++j) {
        float pj = __shfl_sync(0xffffffffu, p, j);
        const float* vp = vb + j * Ii;
        o0 = fmaf(pj, vp[lane], o0);
        o1 = fmaf(pj, vp[lane + 32], o1);
    }
    long long ob = ((long long)(b * Tt + t)) * Ii + h * Dh;
    u16 hv, lv;
    splitf(o0, hv, lv); oh[ob + lane] = hv; ol[ob + lane] = lv;
    splitf(o1, hv, lv); oh[ob + lane + 32] = hv; ol[ob + lane + 32] = lv;
}

// per-head transpose of split V: vT[(b*Hh+h)*Dh+d][t] = v[(b*Tt+t)*Ii + h*Dh + d]
__global__ void transposeV_kernel(const u16* __restrict__ vh, const u16* __restrict__ vl,
                                  u16* __restrict__ oth, u16* __restrict__ otl) {
    __shared__ u16 th[32][33], tl[32][33];
    int bh = blockIdx.z;
    int b = bh / Hh, h = bh % Hh;
    int t0 = blockIdx.x * 32, d0 = blockIdx.y * 32;
    #pragma unroll
    for (int i = 0; i < 32; i += 8) {
        long long src = ((long long)(b * Tt + t0 + threadIdx.y + i)) * Ii + h * Dh + d0 + threadIdx.x;
        th[threadIdx.y + i][threadIdx.x] = vh[src];
        tl[threadIdx.y + i][threadIdx.x] = vl[src];
    }
    __syncthreads();
    #pragma unroll
    for (int i = 0; i < 32; i += 8) {
        long long dst = ((long long)((b * Hh + h) * Dh + d0 + threadIdx.y + i)) * Tt + t0 + threadIdx.x;
        oth[dst] = th[threadIdx.x][threadIdx.y + i];
        otl[dst] = tl[threadIdx.x][threadIdx.y + i];
    }
}

// elementwise split fp32 -> bf16 hi/lo
__global__ void split_ew(const float* __restrict__ w, u16* __restrict__ oh,
                         u16* __restrict__ ol, long long n) {
    long long i = (long long)blockIdx.x * 256 + threadIdx.x;
    if (i >= n) return;
    u16 hv, lv; splitf(w[i], hv, lv);
    oh[i] = hv; ol[i] = lv;
}

// transpose 768x768 [K][N] -> [N][K] + split
__global__ void splitT768(const float* __restrict__ w, u16* __restrict__ oh,
                          u16* __restrict__ ol) {
    __shared__ float t[32][33];
    int k0 = blockIdx.y * 32, n0 = blockIdx.x * 32;
    #pragma unroll
    for (int i = 0; i < 32; i += 8)
        t[threadIdx.y + i][threadIdx.x] = w[(long long)(k0 + threadIdx.y + i) * Ii + n0 + threadIdx.x];
    __syncthreads();
    #pragma unroll
    for (int i = 0; i < 32; i += 8) {
        long long o = (long long)(n0 + threadIdx.y + i) * Ii + k0 + threadIdx.x;
        u16 hv, lv; splitf(t[threadIdx.x][threadIdx.y + i], hv, lv);
        oh[o] = hv; ol[o] = lv;
    }
}

// conv weight reorder+split: out[o][k*Cin+c] = in[o][c*Ksz+k]
__global__ void reorder_split(const float* __restrict__ w, u16* __restrict__ oh,
                              u16* __restrict__ ol, long long total, int Cin) {
    long long i = (long long)blockIdx.x * 256 + threadIdx.x;
    if (i >= total) return;
    int rk = Cin * Ksz;
    long long oc = i / rk;
    int r = (int)(i - oc * rk);
    int k = r / Cin, c = r - k * Cin;
    u16 hv, lv; splitf(w[oc * rk + (long long)c * Ksz + k], hv, lv);
    oh[i] = hv; ol[i] = lv;
}

// ---------------- host wrapper ----------------
static void tc(const u16* Ah, const u16* Al, const u16* Bh, const u16* Bl,
               const float* bias, float* out, u16* oh, u16* ol,
               int gx, int gy, int gz, int K, int lda, int ldb, long long ldo,
               int ntile, int flags, float alpha, long long offA, long long flimA,
               int b2, long long sA1, long long sA2, long long sB1, long long sB2,
               long long sC1, long long sC2)
{
    dim3 g(gx, gy, gz);
    if (ntile == 64)
        tc_gemm<64><<<g, 256, TC_SMEM>>>(Ah, Al, Bh, Bl, bias, out, oh, ol, K, lda, ldb,
            ldo, flags, alpha, offA, flimA, b2, sA1, sA2, sB1, sB2, sC1, sC2);
    else
        tc_gemm<128><<<g, 256, TC_SMEM>>>(Ah, Al, Bh, Bl, bias, out, oh, ol, K, lda, ldb,
            ldo, flags, alpha, offA, flimA, b2, sA1, sA2, sB1, sB2, sC1, sC2);
}

extern "C" void kernel_launch(void* const* d_in, const int* in_sizes, int n_in,
                              void* d_out, int out_size) {
    const float* x      = (const float*)d_in[0];
    const float* ctx    = (const float*)d_in[1];
    const float* gn_s   = (const float*)d_in[2];
    const float* gn_b   = (const float*)d_in[3];
    const float* pin_w  = (const float*)d_in[4];
    const float* pin_b  = (const float*)d_in[5];
    const float* n1_s   = (const float*)d_in[6];
    const float* n1_b   = (const float*)d_in[7];
    const float* a1_wq  = (const float*)d_in[8];
    const float* a1_wk  = (const float*)d_in[9];
    const float* a1_wv  = (const float*)d_in[10];
    const float* a1_wo  = (const float*)d_in[11];
    const float* a1_bo  = (const float*)d_in[12];
    const float* n2_s   = (const float*)d_in[13];
    const float* n2_b   = (const float*)d_in[14];
    const float* a2_wq  = (const float*)d_in[15];
    const float* a2_wk  = (const float*)d_in[16];
    const float* a2_wv  = (const float*)d_in[17];
    const float* a2_wo  = (const float*)d_in[18];
    const float* a2_bo  = (const float*)d_in[19];
    const float* n3_s   = (const float*)d_in[20];
    const float* n3_b   = (const float*)d_in[21];
    const float* ff1_w  = (const float*)d_in[22];
    const float* ff1_b  = (const float*)d_in[23];
    const float* ff2_w  = (const float*)d_in[24];
    const float* ff2_b  = (const float*)d_in[25];
    const float* pout_w = (const float*)d_in[26];
    const float* pout_b = (const float*)d_in[27];
    float* out = (float*)d_out;

    cudaFuncSetAttribute(tc_gemm<128>, cudaFuncAttributeMaxDynamicSharedMemorySize, TC_SMEM);
    cudaFuncSetAttribute(tc_gemm<64>,  cudaFuncAttributeMaxDynamicSharedMemorySize, TC_SMEM);

    float *h, *q, *sc, *kcb, *vcb;
    u16 *gnh, *gnl, *yh, *yl, *qh, *ql, *kh, *kl, *vh, *vl, *vth_, *vtl_, *ath, *atl;
    u16 *hh, *hl, *ph, *pl, *ffh, *ffl, *w1h, *w1l, *w2h, *w2l, *wth, *wtl;
    cudaGetSymbolAddress((void**)&h,   g_h);
    cudaGetSymbolAddress((void**)&q,   g_q);
    cudaGetSymbolAddress((void**)&sc,  g_sc);
    cudaGetSymbolAddress((void**)&kcb, g_kc);
    cudaGetSymbolAddress((void**)&vcb, g_vc);
    cudaGetSymbolAddress((void**)&gnh, g_gnh); cudaGetSymbolAddress((void**)&gnl, g_gnl);
    cudaGetSymbolAddress((void**)&yh,  g_yh);  cudaGetSymbolAddress((void**)&yl,  g_yl);
    cudaGetSymbolAddress((void**)&qh,  g_qh);  cudaGetSymbolAddress((void**)&ql,  g_ql);
    cudaGetSymbolAddress((void**)&kh,  g_kh);  cudaGetSymbolAddress((void**)&kl,  g_kl);
    cudaGetSymbolAddress((void**)&vh,  g_vh);  cudaGetSymbolAddress((void**)&vl,  g_vl);
    cudaGetSymbolAddress((void**)&vth_, g_vth); cudaGetSymbolAddress((void**)&vtl_, g_vtl);
    cudaGetSymbolAddress((void**)&ath, g_ath); cudaGetSymbolAddress((void**)&atl, g_atl);
    cudaGetSymbolAddress((void**)&hh,  g_hh);  cudaGetSymbolAddress((void**)&hl,  g_hl);
    cudaGetSymbolAddress((void**)&ph,  g_ph);  cudaGetSymbolAddress((void**)&pl,  g_pl);
    cudaGetSymbolAddress((void**)&ffh, g_ffh); cudaGetSymbolAddress((void**)&ffl, g_ffl);
    cudaGetSymbolAddress((void**)&w1h, g_w1h); cudaGetSymbolAddress((void**)&w1l, g_w1l);
    cudaGetSymbolAddress((void**)&w2h, g_w2h); cudaGetSymbolAddress((void**)&w2l, g_w2l);
    cudaGetSymbolAddress((void**)&wth, g_wth); cudaGetSymbolAddress((void**)&wtl, g_wtl);

    const long long BIG = 1LL << 62;
    const long long TI = (long long)Tt * Ii;
    const long long WSZ = (long long)Ii * Ii;
    const unsigned WB = (unsigned)((WSZ + 255) / 256);

    split_ew<<<WB, 256>>>(pin_w,  wth + 6 * WSZ, wtl + 6 * WSZ, WSZ);
    split_ew<<<WB, 256>>>(pout_w, wth + 7 * WSZ, wtl + 7 * WSZ, WSZ);

    groupnorm_kernel<<<Bb * 32, 256>>>(x, gn_s, gn_b, gnh, gnl);

    // proj_in: h = pin_w . gn + pin_b (A trans-staged)
    tc(gnh, gnl, wth + 6 * WSZ, wtl + 6 * WSZ, pin_b, h, 0, 0,
       Ii / 128, Tt / 128, Bb, Cc, Tt, Cc, Ii, 128, FTA | FBN | FOUT, 1.f,
       0, (long long)Cc * Tt, 1, (long long)Cc * Tt, 0, 0, 0, TI, 0);

    for (int d = 0; d < Dd; ++d) {
        long long wofs = (long long)d * WSZ;
        dim3 tg(24, 24), tb(32, 8);
        splitT768<<<tg, tb>>>(a1_wq + wofs, wth + 0 * WSZ, wtl + 0 * WSZ);
        splitT768<<<tg, tb>>>(a1_wk + wofs, wth + 1 * WSZ, wtl + 1 * WSZ);
        splitT768<<<tg, tb>>>(a1_wv + wofs, wth + 2 * WSZ, wtl + 2 * WSZ);
        splitT768<<<tg, tb>>>(a1_wo + wofs, wth + 3 * WSZ, wtl + 3 * WSZ);
        splitT768<<<tg, tb>>>(a2_wq + wofs, wth + 4 * WSZ, wtl + 4 * WSZ);
        splitT768<<<tg, tb>>>(a2_wo + wofs, wth + 5 * WSZ, wtl + 5 * WSZ);
        {
            long long t1 = (long long)Fi * Ii * Ksz;
            reorder_split<<<(unsigned)((t1 + 255) / 256), 256>>>(ff1_w + d * t1, w1h, w1l, t1, Ii);
            long long t2 = (long long)Ii * Fi * Ksz;
            reorder_split<<<(unsigned)((t2 + 255) / 256), 256>>>(ff2_w + d * t2, w2h, w2l, t2, Fi);
        }

        // --- self attention ---
        layernorm_kernel<<<Bb * Tt, 256>>>(h, n1_s + d * Ii, n1_b + d * Ii, yh, yl);
        tc(yh, yl, wth + 0 * WSZ, wtl + 0 * WSZ, 0, sc, qh, ql, Ii / 128, (Bb * Tt) / 128, 1,
           Ii, Ii, Ii, Ii, 128, FSPL, 1.f, 0, BIG, 1, 0, 0, 0, 0, 0, 0);
        tc(yh, yl, wth + 1 * WSZ, wtl + 1 * WSZ, 0, sc, kh, kl, Ii / 128, (Bb * Tt) / 128, 1,
           Ii, Ii, Ii, Ii, 128, FSPL, 1.f, 0, BIG, 1, 0, 0, 0, 0, 0, 0);
        tc(yh, yl, wth + 2 * WSZ, wtl + 2 * WSZ, 0, sc, vh, vl, Ii / 128, (Bb * Tt) / 128, 1,
           Ii, Ii, Ii, Ii, 128, FSPL, 1.f, 0, BIG, 1, 0, 0, 0, 0, 0, 0);
        {
            dim3 g(Tt / 32, Dh / 32, Bb * Hh);
            transposeV_kernel<<<g, dim3(32, 8)>>>(vh, vl, vth_, vtl_);
        }
        // scores = 0.125 q k^T per (b,h)
        tc(qh, ql, kh, kl, 0, sc, 0, 0, Tt / 128, Tt / 128, Bb * Hh, Dh, Ii, Ii, Tt, 128,
           FOUT, 0.125f, 0, BIG, Hh, TI, Dh, TI, Dh,
           (long long)Hh * Tt * Tt, (long long)Tt * Tt);
        softmax_kernel<<<Bb * Hh * Tt, 256>>>(sc, ph, pl);
        // att = P @ V per (b,h)  (B = pre-transposed V, non-trans cp.async)
        tc(ph, pl, vth_, vtl_, 0, sc, ath, atl, 1, Tt / 128, Bb * Hh, Tt, Tt, Tt, Ii, 64,
           FSPL, 1.f, 0, BIG, Hh,
           (long long)Hh * Tt * Tt, (long long)Tt * Tt,
           (long long)Hh * Dh * Tt, (long long)Dh * Tt, TI, Dh);
        // h += att @ wo + bo
        tc(ath, atl, wth + 3 * WSZ, wtl + 3 * WSZ, a1_bo + d * Ii, h, 0, 0,
           Ii / 128, (Bb * Tt) / 128, 1, Ii, Ii, Ii, Ii, 128,
           FBN | FADD, 1.f, 0, BIG, 1, 0, 0, 0, 0, 0, 0);

        // --- cross attention ---
        layernorm_kernel<<<Bb * Tt, 256>>>(h, n2_s + d * Ii, n2_b + d * Ii, yh, yl);
        tc(yh, yl, wth + 4 * WSZ, wtl + 4 * WSZ, 0, q, 0, 0, Ii / 128, (Bb * Tt) / 128, 1,
           Ii, Ii, Ii, Ii, 128, FOUT, 1.f, 0, BIG, 1, 0, 0, 0, 0, 0, 0);
        {
            dim3 g((Ii + 63) / 64, (Bb * Ss + 63) / 64);
            gemm_kernel<<<g, 256>>>(ctx, a2_wk + (long long)d * Cx * Ii, kcb,
                                    Bb * Ss, Ii, Cx, Cx, Ii, Ii);
            gemm_kernel<<<g, 256>>>(ctx, a2_wv + (long long)d * Cx * Ii, vcb,
                                    Bb * Ss, Ii, Cx, Cx, Ii, Ii);
        }
        crossattn_kernel<<<Bb * Hh * Tt / 8, 256>>>(q, kcb, vcb, ath, atl);
        tc(ath, atl, wth + 5 * WSZ, wtl + 5 * WSZ, a2_bo + d * Ii, h, 0, 0,
           Ii / 128, (Bb * Tt) / 128, 1, Ii, Ii, Ii, Ii, 128,
           FBN | FADD, 1.f, 0, BIG, 1, 0, 0, 0, 0, 0, 0);

        // --- feed-forward ---
        layernorm_kernel<<<Bb * Tt, 256>>>(h, n3_s + d * Ii, n3_b + d * Ii, yh, yl);
        tc(yh, yl, w1h, w1l, ff1_b + d * Fi, sc, ffh, ffl, Fi / 128, Tt / 128, Bb,
           Ii * Ksz, Ii, Ii * Ksz, Fi, 128, FBN | FGELU | FSPL, 1.f,
           -(long long)4 * Ii, TI, 1, TI, 0, 0, 0, (long long)Tt * Fi, 0);
        tc(ffh, ffl, w2h, w2l, ff2_b + d * Ii, h, hh, hl, Ii / 128, Tt / 128, Bb,
           Fi * Ksz, Fi, Fi * Ksz, Ii, 128,
           FBN | FADD | (d == Dd - 1 ? FSPL : 0), 1.f,
           -(long long)4 * Fi, (long long)Tt * Fi, 1,
           (long long)Tt * Fi, 0, 0, 0, TI, 0);
    }

    // out = x + pout_w @ h^T + pout_b
    cudaMemcpyAsync(out, x, (size_t)Bb * Cc * Tt * sizeof(float),
                    cudaMemcpyDeviceToDevice);
    tc(wth + 7 * WSZ, wtl + 7 * WSZ, hh, hl, pout_b, out, 0, 0,
       Tt / 128, Cc / 128, Bb, Ii, Ii, Ii, Tt, 128, FBM | FADD, 1.f,
       0, BIG, 1, 0, 0, TI, 0, (long long)Cc * Tt, 0);
}

// round 8
// speedup vs baseline: 2.8272x; 1.0491x over previous
#include <cuda_runtime.h>
#include <cuda_bf16.h>
#include <math.h>
#include <stdint.h>

#define Bb 2
#define Cc 768
#define Tt 2048
#define Ii 768
#define Hh 12
#define Dh 64
#define Ss 16
#define Cx 512
#define Fi 3072
#define Dd 2
#define Ksz 9

typedef __nv_bfloat16 bf16;
typedef unsigned short u16;

// ---------------- scratch ----------------
__device__ float g_h  [(long long)Bb*Tt*Ii];
__device__ float g_q  [(long long)Bb*Tt*Ii];
__device__ float g_sc [(long long)Bb*Hh*Tt*Tt];
__device__ float g_kc [(long long)Bb*Ss*Ii];
__device__ float g_vc [(long long)Bb*Ss*Ii];

__device__ u16 g_gnh[(long long)Bb*Cc*Tt], g_gnl[(long long)Bb*Cc*Tt];
__device__ u16 g_yh [(long long)Bb*Tt*Ii], g_yl [(long long)Bb*Tt*Ii];
__device__ u16 g_qh [(long long)Bb*Tt*Ii], g_ql [(long long)Bb*Tt*Ii];
__device__ u16 g_kh [(long long)Bb*Tt*Ii], g_kl [(long long)Bb*Tt*Ii];
__device__ u16 g_vh [(long long)Bb*Tt*Ii], g_vl [(long long)Bb*Tt*Ii];
__device__ u16 g_vth[(long long)Bb*Ii*Tt], g_vtl[(long long)Bb*Ii*Tt];
__device__ u16 g_ath[(long long)Bb*Tt*Ii], g_atl[(long long)Bb*Tt*Ii];
__device__ u16 g_hh [(long long)Bb*Tt*Ii], g_hl [(long long)Bb*Tt*Ii];
__device__ u16 g_ph [(long long)Bb*Hh*Tt*Tt], g_pl [(long long)Bb*Hh*Tt*Tt];
__device__ u16 g_ffh[(long long)Bb*Tt*Fi], g_ffl[(long long)Bb*Tt*Fi];
__device__ u16 g_w1h[(long long)Fi*Ii*Ksz], g_w1l[(long long)Fi*Ii*Ksz];
__device__ u16 g_w2h[(long long)Ii*Fi*Ksz], g_w2l[(long long)Ii*Fi*Ksz];
__device__ u16 g_wth[8ll*Ii*Ii], g_wtl[8ll*Ii*Ii];

// ---------------- helpers ----------------
__device__ __forceinline__ uint32_t smem_u32(const void* p) {
    uint32_t a;
    asm("{ .reg .u64 t; cvta.to.shared.u64 t, %1; cvt.u32.u64 %0, t; }" : "=r"(a) : "l"(p));
    return a;
}
#define SWZ(x) ((x) ^ ((((uint32_t)(x)) >> 3) & 0x70))
#define CP16(dst, src) asm volatile("cp.async.cg.shared.global [%0], [%1], 16;" :: "r"(dst), "l"(src))
#define CPCOMMIT() asm volatile("cp.async.commit_group;" ::: "memory")
#define CPWAIT1() asm volatile("cp.async.wait_group 1;" ::: "memory")
#define CPWAIT0() asm volatile("cp.async.wait_group 0;" ::: "memory")

__device__ __forceinline__ void ldsm4(uint32_t* r, uint32_t addr) {
    asm volatile("ldmatrix.sync.aligned.m8n8.x4.shared.b16 {%0,%1,%2,%3}, [%4];"
        : "=r"(r[0]), "=r"(r[1]), "=r"(r[2]), "=r"(r[3]) : "r"(addr));
}
__device__ __forceinline__ void mma16816(float* c, const uint32_t* a, const uint32_t* b) {
    asm volatile("mma.sync.aligned.m16n8k16.row.col.f32.bf16.bf16.f32 "
        "{%0,%1,%2,%3}, {%4,%5,%6,%7}, {%8,%9}, {%0,%1,%2,%3};"
        : "+f"(c[0]), "+f"(c[1]), "+f"(c[2]), "+f"(c[3])
        : "r"(a[0]), "r"(a[1]), "r"(a[2]), "r"(a[3]), "r"(b[0]), "r"(b[1]));
}
__device__ __forceinline__ void splitf(float x, u16& h, u16& l) {
    bf16 hb = __float2bfloat16(x);
    bf16 lb = __float2bfloat16(x - __bfloat162float(hb));
    h = __bfloat16_as_ushort(hb);
    l = __bfloat16_as_ushort(lb);
}

// flags
#define FTA   1
#define FTB   2
#define FBN   4
#define FBM   8
#define FGELU 16
#define FADD  32
#define FOUT  64
#define FSPL  128

#define TC_SMEM (131072 + 1024)
#define NTHREADS 512

// stage 16B segments via cp.async (non-trans): op[r][k] = G[off0 + r*ld + k]
__device__ __forceinline__ void stage_nt(const u16* __restrict__ Gh, const u16* __restrict__ Gl,
        long long off0, long long flim, int ld, int k0, int rows,
        uint32_t smh, uint32_t sml) {
    int nseg = rows * 8;
    for (int idx = threadIdx.x; idx < nseg; idx += NTHREADS) {
        int r = idx >> 3, s = idx & 7;
        long long f = off0 + (long long)r * ld + k0 + s * 8;
        uint32_t d = SWZ((uint32_t)(r * 128 + s * 16));
        if (f >= 0 && f + 8 <= flim) {
            CP16(smh + d, Gh + f);
            CP16(sml + d, Gl + f);
        } else {
            asm volatile("st.shared.v4.u32 [%0], {%1,%1,%1,%1};" :: "r"(smh + d), "r"(0));
            asm volatile("st.shared.v4.u32 [%0], {%1,%1,%1,%1};" :: "r"(sml + d), "r"(0));
        }
    }
}
// synchronous trans staging: op[r][k] = G[off0 + k*ld + r]
__device__ __forceinline__ void stage_t(const u16* __restrict__ Gh, const u16* __restrict__ Gl,
        long long off0, long long flim, int ld, int k0, int rows,
        uint32_t smh, uint32_t sml) {
    int items = 64 * (rows >> 3);
    for (int idx = threadIdx.x; idx < items; idx += NTHREADS) {
        int kk = idx & 63, r0 = (idx >> 6) << 3;
        long long f = off0 + (long long)(k0 + kk) * ld + r0;
        uint32_t hw[4] = {0,0,0,0}, lw[4] = {0,0,0,0};
        if (f >= 0 && f + 8 <= flim) {
            uint4 a = *(const uint4*)(Gh + f);
            uint4 b = *(const uint4*)(Gl + f);
            hw[0]=a.x; hw[1]=a.y; hw[2]=a.z; hw[3]=a.w;
            lw[0]=b.x; lw[1]=b.y; lw[2]=b.z; lw[3]=b.w;
        }
        const u16* hp = (const u16*)hw;
        const u16* lp = (const u16*)lw;
        #pragma unroll
        for (int j = 0; j < 8; ++j) {
            uint32_t d = SWZ((uint32_t)((r0 + j) * 128 + kk * 2));
            asm volatile("st.shared.u16 [%0], %1;" :: "r"(smh + d), "h"(hp[j]));
            asm volatile("st.shared.u16 [%0], %1;" :: "r"(sml + d), "h"(lp[j]));
        }
    }
}

// ===== tensor-core GEMM: 512 threads, 4x4 warp grid, warp tile 32 x (NT/4) =====
template<int NT>
__global__ void __launch_bounds__(NTHREADS, 1)
tc_gemm(const u16* __restrict__ Ah, const u16* __restrict__ Al,
        const u16* __restrict__ Bh, const u16* __restrict__ Bl,
        const float* __restrict__ bias, float* __restrict__ out,
        u16* __restrict__ oh, u16* __restrict__ ol,
        int K, int lda, int ldb, long long ldo, int flags, float alpha,
        long long offA, long long flimA, int b2,
        long long sA1, long long sA2, long long sB1, long long sB2,
        long long sC1, long long sC2)
{
    extern __shared__ char dynsm[];
    long long z1 = blockIdx.z / b2, z2 = blockIdx.z % b2;
    Ah += z1 * sA1 + z2 * sA2;  Al += z1 * sA1 + z2 * sA2;
    Bh += z1 * sB1 + z2 * sB2;  Bl += z1 * sB1 + z2 * sB2;
    long long zc = z1 * sC1 + z2 * sC2;
    out += zc;
    if (flags & FSPL) { oh += zc; ol += zc; }

    const int tid = threadIdx.x;
    const int lane = tid & 31;
    const int wid = tid >> 5;                 // 0..15
    const int wm = (wid & 3) * 32;            // 4 M-warps * 32 rows
    constexpr int WN = NT / 4;                // warp N extent (32 or 16)
    const int wn = (wid >> 2) * WN;           // 4 N-warps
    const int m0 = blockIdx.y * 128;
    const int n0 = blockIdx.x * NT;
    constexpr int NTW = WN / 8;               // n8 tiles per warp (4 or 2)
    constexpr int NB = NTW / 2;               // 16-col pairs (2 or 1)

    uint32_t smBase = smem_u32(dynsm);
    smBase = (smBase + 1023) & ~1023u;

    const int tAf = flags & FTA, tBf = flags & FTB;
    const long long aoff = offA + (tAf ? (long long)m0 : (long long)m0 * lda);
    const long long boff = (tBf ? (long long)n0 : (long long)n0 * ldb);
    const long long BIGL = 1LL << 62;
    const int nc = K / 64;

    float acc[2][NTW][4];
    #pragma unroll
    for (int i = 0; i < 2; ++i)
        #pragma unroll
        for (int j = 0; j < NTW; ++j)
            #pragma unroll
            for (int l = 0; l < 4; ++l) acc[i][j][l] = 0.f;

    const uint32_t aRow = wm + (lane & 15);
    const uint32_t aKof = (lane >> 4) << 3;
    const int bi = lane >> 3;
    const uint32_t bRowBase = wn + ((bi >> 1) << 3) + (lane & 7);
    const uint32_t bKof = (bi & 1) << 3;

    auto stage = [&](int c, int s) {
        uint32_t base = smBase + s * 65536;
        if (tAf) stage_t (Ah, Al, aoff, flimA, lda, c * 64, 128, base, base + 16384);
        else     stage_nt(Ah, Al, aoff, flimA, lda, c * 64, 128, base, base + 16384);
        if (tBf) stage_t (Bh, Bl, boff, BIGL, ldb, c * 64, NT, base + 32768, base + 49152);
        else     stage_nt(Bh, Bl, boff, BIGL, ldb, c * 64, NT, base + 32768, base + 49152);
        CPCOMMIT();
    };

    stage(0, 0);
    for (int c = 0; c < nc; ++c) {
        if (c + 1 < nc) { stage(c + 1, (c + 1) & 1); CPWAIT1(); }
        else            { CPWAIT0(); }
        __syncthreads();
        uint32_t base = smBase + (c & 1) * 65536;
        const uint32_t aHi = base, aLo = base + 16384;
        const uint32_t bHi = base + 32768, bLo = base + 49152;
        #pragma unroll
        for (int ks = 0; ks < 4; ++ks) {
            const uint32_t kb = ks * 16;
            uint32_t ah[2][4], al[2][4], bh[NB][4], bl[NB][4];
            #pragma unroll
            for (int mt = 0; mt < 2; ++mt) {
                uint32_t off = SWZ((aRow + mt * 16) * 128 + (kb + aKof) * 2);
                ldsm4(ah[mt], aHi + off);
                ldsm4(al[mt], aLo + off);
            }
            #pragma unroll
            for (int bp = 0; bp < NB; ++bp) {
                uint32_t off = SWZ((bRowBase + bp * 16) * 128 + (kb + bKof) * 2);
                ldsm4(bh[bp], bHi + off);
                ldsm4(bl[bp], bLo + off);
            }
            #pragma unroll
            for (int bp = 0; bp < NB; ++bp)
                #pragma unroll
                for (int mt = 0; mt < 2; ++mt) {
                    mma16816(acc[mt][2 * bp],     ah[mt], bh[bp]);
                    mma16816(acc[mt][2 * bp + 1], ah[mt], bh[bp] + 2);
                }
            #pragma unroll
            for (int bp = 0; bp < NB; ++bp)
                #pragma unroll
                for (int mt = 0; mt < 2; ++mt) {
                    mma16816(acc[mt][2 * bp],     al[mt], bh[bp]);
                    mma16816(acc[mt][2 * bp + 1], al[mt], bh[bp] + 2);
                }
            #pragma unroll
            for (int bp = 0; bp < NB; ++bp)
                #pragma unroll
                for (int mt = 0; mt < 2; ++mt) {
                    mma16816(acc[mt][2 * bp],     ah[mt], bl[bp]);
                    mma16816(acc[mt][2 * bp + 1], ah[mt], bl[bp] + 2);
                }
        }
        __syncthreads();
    }

    // epilogue
    const int g = lane >> 2, tg = lane & 3;
    #pragma unroll
    for (int mt = 0; mt < 2; ++mt) {
        #pragma unroll
        for (int hf = 0; hf < 2; ++hf) {
            int m = m0 + wm + mt * 16 + g + hf * 8;
            float bm = (flags & FBM) ? bias[m] : 0.f;
            long long rbase = (long long)m * ldo;
            #pragma unroll
            for (int nt = 0; nt < NTW; ++nt) {
                int n = n0 + wn + nt * 8 + tg * 2;
                float v0 = alpha * acc[mt][nt][hf * 2 + 0];
                float v1 = alpha * acc[mt][nt][hf * 2 + 1];
                if (flags & FBN) { v0 += bias[n]; v1 += bias[n + 1]; }
                else if (flags & FBM) { v0 += bm; v1 += bm; }
                if (flags & FGELU) {
                    v0 = 0.5f * v0 * (1.f + erff(v0 * 0.70710678118654752f));
                    v1 = 0.5f * v1 * (1.f + erff(v1 * 0.70710678118654752f));
                }
                if (flags & FADD) { v0 += out[rbase + n]; v1 += out[rbase + n + 1]; }
                if (flags & (FOUT | FADD)) { out[rbase + n] = v0; out[rbase + n + 1] = v1; }
                if (flags & FSPL) {
                    u16 h0, l0, h1, l1;
                    splitf(v0, h0, l0);
                    splitf(v1, h1, l1);
                    oh[rbase + n] = h0; ol[rbase + n] = l0;
                    oh[rbase + n + 1] = h1; ol[rbase + n + 1] = l1;
                }
            }
        }
    }
}

// ---------------- reductions ----------------
__device__ __forceinline__ float blockReduceSum(float v) {
    __shared__ float sm[32];
    int lane = threadIdx.x & 31, wid = threadIdx.x >> 5;
    #pragma unroll
    for (int o = 16; o; o >>= 1) v += __shfl_xor_sync(0xffffffffu, v, o);
    if (lane == 0) sm[wid] = v;
    __syncthreads();
    if (wid == 0) {
        int nw = (blockDim.x + 31) >> 5;
        v = (lane < nw) ? sm[lane] : 0.f;
        #pragma unroll
        for (int o = 16; o; o >>= 1) v += __shfl_xor_sync(0xffffffffu, v, o);
        if (lane == 0) sm[0] = v;
    }
    __syncthreads();
    float r = sm[0];
    __syncthreads();
    return r;
}
__device__ __forceinline__ float blockReduceMax(float v) {
    __shared__ float sm[32];
    int lane = threadIdx.x & 31, wid = threadIdx.x >> 5;
    #pragma unroll
    for (int o = 16; o; o >>= 1) v = fmaxf(v, __shfl_xor_sync(0xffffffffu, v, o));
    if (lane == 0) sm[wid] = v;
    __syncthreads();
    if (wid == 0) {
        int nw = (blockDim.x + 31) >> 5;
        v = (lane < nw) ? sm[lane] : -INFINITY;
        #pragma unroll
        for (int o = 16; o; o >>= 1) v = fmaxf(v, __shfl_xor_sync(0xffffffffu, v, o));
        if (lane == 0) sm[0] = v;
    }
    __syncthreads();
    float r = sm[0];
    __syncthreads();
    return r;
}

__global__ void groupnorm_kernel(const float* __restrict__ x, const float* __restrict__ sc,
                                 const float* __restrict__ bi,
                                 u16* __restrict__ oh, u16* __restrict__ ol) {
    const int CPG = Cc / 32;
    int b = blockIdx.x >> 5, g = blockIdx.x & 31;
    const long long base = ((long long)b * Cc + (long long)g * CPG) * Tt;
    const float* xp = x + base;
    const int n = CPG * Tt;
    float s = 0.f, ss = 0.f;
    for (int i = threadIdx.x; i < n; i += blockDim.x) {
        float v = xp[i]; s += v; ss = fmaf(v, v, ss);
    }
    s = blockReduceSum(s); ss = blockReduceSum(ss);
    float mean = s / n;
    float inv = rsqrtf(ss / n - mean * mean + 1e-6f);
    for (int i = threadIdx.x; i < n; i += blockDim.x) {
        int c = g * CPG + i / Tt;
        float v = (xp[i] - mean) * inv * sc[c] + bi[c];
        u16 hv, lv; splitf(v, hv, lv);
        oh[base + i] = hv; ol[base + i] = lv;
    }
}

__global__ void layernorm_kernel(const float* __restrict__ x, const float* __restrict__ sc,
                                 const float* __restrict__ bi,
                                 u16* __restrict__ oh, u16* __restrict__ ol) {
    const long long rb = (long long)blockIdx.x * Ii;
    const float* row = x + rb;
    float s = 0.f, ss = 0.f;
    for (int i = threadIdx.x; i < Ii; i += blockDim.x) {
        float v = row[i]; s += v; ss = fmaf(v, v, ss);
    }
    s = blockReduceSum(s); ss = blockReduceSum(ss);
    float mean = s / (float)Ii;
    float inv = rsqrtf(ss / (float)Ii - mean * mean + 1e-5f);
    for (int i = threadIdx.x; i < Ii; i += blockDim.x) {
        float v = (row[i] - mean) * inv * sc[i] + bi[i];
        u16 hv, lv; splitf(v, hv, lv);
        oh[rb + i] = hv; ol[rb + i] = lv;
    }
}

// small fp32 gemm for tiny cross-attn K/V projections (M=32)
__global__ void __launch_bounds__(256) gemm_kernel(
    const float* __restrict__ A, const float* __restrict__ B, float* __restrict__ Cp,
    int M, int N, int K, int lda, int ldb, int ldc)
{
    __shared__ float As[16][65];
    __shared__ float Bs[16][65];
    int n0 = blockIdx.x * 64, m0 = blockIdx.y * 64;
    int tid = threadIdx.x;
    int tx = tid & 15, ty = tid >> 4;
    float acc[4][4] = {};
    for (int k0 = 0; k0 < K; k0 += 16) {
        #pragma unroll
        for (int u = 0; u < 4; ++u) {
            int i = tid + u * 256;
            int mm = i >> 4, kk = i & 15;
            int m = m0 + mm, k = k0 + kk;
            As[kk][mm] = (m < M && k < K) ? A[(long long)m * lda + k] : 0.f;
        }
        #pragma unroll
        for (int u = 0; u < 4; ++u) {
            int i = tid + u * 256;
            int kk = i >> 6, nn = i & 63;
            int k = k0 + kk, n = n0 + nn;
            Bs[kk][nn] = (k < K && n < N) ? B[(long long)k * ldb + n] : 0.f;
        }
        __syncthreads();
        #pragma unroll
        for (int kk = 0; kk < 16; ++kk) {
            float a[4], bb[4];
            #pragma unroll
            for (int i = 0; i < 4; ++i) a[i] = As[kk][ty * 4 + i];
            #pragma unroll
            for (int j = 0; j < 4; ++j) bb[j] = Bs[kk][tx * 4 + j];
            #pragma unroll
            for (int i = 0; i < 4; ++i)
                #pragma unroll
                for (int j = 0; j < 4; ++j)
                    acc[i][j] = fmaf(a[i], bb[j], acc[i][j]);
        }
        __syncthreads();
    }
    #pragma unroll
    for (int i = 0; i < 4; ++i) {
        int m = m0 + ty * 4 + i;
        if (m >= M) continue;
        #pragma unroll
        for (int j = 0; j < 4; ++j) {
            int n = n0 + tx * 4 + j;
            if (n < N) Cp[(long long)m * ldc + n] = acc[i][j];
        }
    }
}

__global__ void softmax_kernel(const float* __restrict__ s,
                               u16* __restrict__ oh, u16* __restrict__ ol) {
    const long long rb = (long long)blockIdx.x * Tt;
    const float* row = s + rb;
    int tid = threadIdx.x;
    float v[8];
    float mx = -INFINITY;
    #pragma unroll
    for (int i = 0; i < 8; ++i) { v[i] = row[tid + (i << 8)]; mx = fmaxf(mx, v[i]); }
    mx = blockReduceMax(mx);
    float sum = 0.f;
    #pragma unroll
    for (int i = 0; i < 8; ++i) { v[i] = expf(v[i] - mx); sum += v[i]; }
    sum = blockReduceSum(sum);
    float inv = 1.f / sum;
    #pragma unroll
    for (int i = 0; i < 8; ++i) {
        u16 hv, lv; splitf(v[i] * inv, hv, lv);
        oh[rb + tid + (i << 8)] = hv;
        ol[rb + tid + (i << 8)] = lv;
    }
}

__global__ void crossattn_kernel(const float* __restrict__ q, const float* __restrict__ kc,
                                 const float* __restrict__ vc,
                                 u16* __restrict__ oh, u16* __restrict__ ol) {
    int gw = blockIdx.x * (blockDim.x >> 5) + (threadIdx.x >> 5);
    int lane = threadIdx.x & 31;
    int t = gw % Tt;
    int rem = gw / Tt;
    int h = rem % Hh;
    int b = rem / Hh;
    const float* qp = q + ((long long)(b * Tt + t)) * Ii + h * Dh;
    const float* kb = kc + (long long)b * Ss * Ii + h * Dh;
    const float* vb = vc + (long long)b * Ss * Ii + h * Dh;
    float sj = -INFINITY;
    if (lane < Ss) {
        const float* kp = kb + lane * Ii;
        float acc = 0.f;
        #pragma unroll
        for (int d2 = 0; d2 < Dh; ++d2) acc = fmaf(qp[d2], kp[d2], acc);
        sj = acc * 0.125f;
    }
    float mx = sj;
    #pragma unroll
    for (int o = 16; o; o >>= 1) mx = fmaxf(mx, __shfl_xor_sync(0xffffffffu, mx, o));
    float p = (lane < Ss) ? expf(sj - mx) : 0.f;
    float sum = p;
    #pragma unroll
    for (int o = 16; o; o >>= 1) sum += __shfl_xor_sync(0xffffffffu, sum, o);
    p /= sum;
    float o0 = 0.f, o1 = 0.f;
    #pragma unroll
    for (int j = 0; j < Ss; ++j) {
        float pj = __shfl_sync(0xffffffffu, p, j);
        const float* vp = vb + j * Ii;
        o0 = fmaf(pj, vp[lane], o0);
        o1 = fmaf(pj, vp[lane + 32], o1);
    }
    long long ob = ((long long)(b * Tt + t)) * Ii + h * Dh;
    u16 hv, lv;
    splitf(o0, hv, lv); oh[ob + lane] = hv; ol[ob + lane] = lv;
    splitf(o1, hv, lv); oh[ob + lane + 32] = hv; ol[ob + lane + 32] = lv;
}

// per-head transpose of split V
__global__ void transposeV_kernel(const u16* __restrict__ vh, const u16* __restrict__ vl,
                                  u16* __restrict__ oth, u16* __restrict__ otl) {
    __shared__ u16 th[32][33], tl[32][33];
    int bh = blockIdx.z;
    int b = bh / Hh, h = bh % Hh;
    int t0 = blockIdx.x * 32, d0 = blockIdx.y * 32;
    #pragma unroll
    for (int i = 0; i < 32; i += 8) {
        long long src = ((long long)(b * Tt + t0 + threadIdx.y + i)) * Ii + h * Dh + d0 + threadIdx.x;
        th[threadIdx.y + i][threadIdx.x] = vh[src];
        tl[threadIdx.y + i][threadIdx.x] = vl[src];
    }
    __syncthreads();
    #pragma unroll
    for (int i = 0; i < 32; i += 8) {
        long long dst = ((long long)((b * Hh + h) * Dh + d0 + threadIdx.y + i)) * Tt + t0 + threadIdx.x;
        oth[dst] = th[threadIdx.x][threadIdx.y + i];
        otl[dst] = tl[threadIdx.x][threadIdx.y + i];
    }
}

// elementwise split fp32 -> bf16 hi/lo
__global__ void split_ew(const float* __restrict__ w, u16* __restrict__ oh,
                         u16* __restrict__ ol, long long n) {
    long long i = (long long)blockIdx.x * 256 + threadIdx.x;
    if (i >= n) return;
    u16 hv, lv; splitf(w[i], hv, lv);
    oh[i] = hv; ol[i] = lv;
}

// transpose 768x768 [K][N] -> [N][K] + split
__global__ void splitT768(const float* __restrict__ w, u16* __restrict__ oh,
                          u16* __restrict__ ol) {
    __shared__ float t[32][33];
    int k0 = blockIdx.y * 32, n0 = blockIdx.x * 32;
    #pragma unroll
    for (int i = 0; i < 32; i += 8)
        t[threadIdx.y + i][threadIdx.x] = w[(long long)(k0 + threadIdx.y + i) * Ii + n0 + threadIdx.x];
    __syncthreads();
    #pragma unroll
    for (int i = 0; i < 32; i += 8) {
        long long o = (long long)(n0 + threadIdx.y + i) * Ii + k0 + threadIdx.x;
        u16 hv, lv; splitf(t[threadIdx.x][threadIdx.y + i], hv, lv);
        oh[o] = hv; ol[o] = lv;
    }
}

// conv weight reorder+split: out[o][k*Cin+c] = in[o][c*Ksz+k]
__global__ void reorder_split(const float* __restrict__ w, u16* __restrict__ oh,
                              u16* __restrict__ ol, long long total, int Cin) {
    long long i = (long long)blockIdx.x * 256 + threadIdx.x;
    if (i >= total) return;
    int rk = Cin * Ksz;
    long long oc = i / rk;
    int r = (int)(i - oc * rk);
    int k = r / Cin, c = r - k * Cin;
    u16 hv, lv; splitf(w[oc * rk + (long long)c * Ksz + k], hv, lv);
    oh[i] = hv; ol[i] = lv;
}

// ---------------- host wrapper ----------------
static void tc(const u16* Ah, const u16* Al, const u16* Bh, const u16* Bl,
               const float* bias, float* out, u16* oh, u16* ol,
               int gx, int gy, int gz, int K, int lda, int ldb, long long ldo,
               int ntile, int flags, float alpha, long long offA, long long flimA,
               int b2, long long sA1, long long sA2, long long sB1, long long sB2,
               long long sC1, long long sC2)
{
    dim3 g(gx, gy, gz);
    if (ntile == 64)
        tc_gemm<64><<<g, NTHREADS, TC_SMEM>>>(Ah, Al, Bh, Bl, bias, out, oh, ol, K, lda, ldb,
            ldo, flags, alpha, offA, flimA, b2, sA1, sA2, sB1, sB2, sC1, sC2);
    else
        tc_gemm<128><<<g, NTHREADS, TC_SMEM>>>(Ah, Al, Bh, Bl, bias, out, oh, ol, K, lda, ldb,
            ldo, flags, alpha, offA, flimA, b2, sA1, sA2, sB1, sB2, sC1, sC2);
}

extern "C" void kernel_launch(void* const* d_in, const int* in_sizes, int n_in,
                              void* d_out, int out_size) {
    const float* x      = (const float*)d_in[0];
    const float* ctx    = (const float*)d_in[1];
    const float* gn_s   = (const float*)d_in[2];
    const float* gn_b   = (const float*)d_in[3];
    const float* pin_w  = (const float*)d_in[4];
    const float* pin_b  = (const float*)d_in[5];
    const float* n1_s   = (const float*)d_in[6];
    const float* n1_b   = (const float*)d_in[7];
    const float* a1_wq  = (const float*)d_in[8];
    const float* a1_wk  = (const float*)d_in[9];
    const float* a1_wv  = (const float*)d_in[10];
    const float* a1_wo  = (const float*)d_in[11];
    const float* a1_bo  = (const float*)d_in[12];
    const float* n2_s   = (const float*)d_in[13];
    const float* n2_b   = (const float*)d_in[14];
    const float* a2_wq  = (const float*)d_in[15];
    const float* a2_wk  = (const float*)d_in[16];
    const float* a2_wv  = (const float*)d_in[17];
    const float* a2_wo  = (const float*)d_in[18];
    const float* a2_bo  = (const float*)d_in[19];
    const float* n3_s   = (const float*)d_in[20];
    const float* n3_b   = (const float*)d_in[21];
    const float* ff1_w  = (const float*)d_in[22];
    const float* ff1_b  = (const float*)d_in[23];
    const float* ff2_w  = (const float*)d_in[24];
    const float* ff2_b  = (const float*)d_in[25];
    const float* pout_w = (const float*)d_in[26];
    const float* pout_b = (const float*)d_in[27];
    float* out = (float*)d_out;

    cudaFuncSetAttribute(tc_gemm<128>, cudaFuncAttributeMaxDynamicSharedMemorySize, TC_SMEM);
    cudaFuncSetAttribute(tc_gemm<64>,  cudaFuncAttributeMaxDynamicSharedMemorySize, TC_SMEM);

    float *h, *q, *sc, *kcb, *vcb;
    u16 *gnh, *gnl, *yh, *yl, *qh, *ql, *kh, *kl, *vh, *vl, *vth_, *vtl_, *ath, *atl;
    u16 *hh, *hl, *ph, *pl, *ffh, *ffl, *w1h, *w1l, *w2h, *w2l, *wth, *wtl;
    cudaGetSymbolAddress((void**)&h,   g_h);
    cudaGetSymbolAddress((void**)&q,   g_q);
    cudaGetSymbolAddress((void**)&sc,  g_sc);
    cudaGetSymbolAddress((void**)&kcb, g_kc);
    cudaGetSymbolAddress((void**)&vcb, g_vc);
    cudaGetSymbolAddress((void**)&gnh, g_gnh); cudaGetSymbolAddress((void**)&gnl, g_gnl);
    cudaGetSymbolAddress((void**)&yh,  g_yh);  cudaGetSymbolAddress((void**)&yl,  g_yl);
    cudaGetSymbolAddress((void**)&qh,  g_qh);  cudaGetSymbolAddress((void**)&ql,  g_ql);
    cudaGetSymbolAddress((void**)&kh,  g_kh);  cudaGetSymbolAddress((void**)&kl,  g_kl);
    cudaGetSymbolAddress((void**)&vh,  g_vh);  cudaGetSymbolAddress((void**)&vl,  g_vl);
    cudaGetSymbolAddress((void**)&vth_, g_vth); cudaGetSymbolAddress((void**)&vtl_, g_vtl);
    cudaGetSymbolAddress((void**)&ath, g_ath); cudaGetSymbolAddress((void**)&atl, g_atl);
    cudaGetSymbolAddress((void**)&hh,  g_hh);  cudaGetSymbolAddress((void**)&hl,  g_hl);
    cudaGetSymbolAddress((void**)&ph,  g_ph);  cudaGetSymbolAddress((void**)&pl,  g_pl);
    cudaGetSymbolAddress((void**)&ffh, g_ffh); cudaGetSymbolAddress((void**)&ffl, g_ffl);
    cudaGetSymbolAddress((void**)&w1h, g_w1h); cudaGetSymbolAddress((void**)&w1l, g_w1l);
    cudaGetSymbolAddress((void**)&w2h, g_w2h); cudaGetSymbolAddress((void**)&w2l, g_w2l);
    cudaGetSymbolAddress((void**)&wth, g_wth); cudaGetSymbolAddress((void**)&wtl, g_wtl);

    const long long BIG = 1LL << 62;
    const long long TI = (long long)Tt * Ii;
    const long long WSZ = (long long)Ii * Ii;
    const unsigned WB = (unsigned)((WSZ + 255) / 256);

    split_ew<<<WB, 256>>>(pin_w,  wth + 6 * WSZ, wtl + 6 * WSZ, WSZ);
    split_ew<<<WB, 256>>>(pout_w, wth + 7 * WSZ, wtl + 7 * WSZ, WSZ);

    groupnorm_kernel<<<Bb * 32, 256>>>(x, gn_s, gn_b, gnh, gnl);

    // proj_in: h = pin_w . gn + pin_b (A trans-staged)
    tc(gnh, gnl, wth + 6 * WSZ, wtl + 6 * WSZ, pin_b, h, 0, 0,
       Ii / 128, Tt / 128, Bb, Cc, Tt, Cc, Ii, 128, FTA | FBN | FOUT, 1.f,
       0, (long long)Cc * Tt, 1, (long long)Cc * Tt, 0, 0, 0, TI, 0);

    for (int d = 0; d < Dd; ++d) {
        long long wofs = (long long)d * WSZ;
        dim3 tg(24, 24), tb(32, 8);
        splitT768<<<tg, tb>>>(a1_wq + wofs, wth + 0 * WSZ, wtl + 0 * WSZ);
        splitT768<<<tg, tb>>>(a1_wk + wofs, wth + 1 * WSZ, wtl + 1 * WSZ);
        splitT768<<<tg, tb>>>(a1_wv + wofs, wth + 2 * WSZ, wtl + 2 * WSZ);
        splitT768<<<tg, tb>>>(a1_wo + wofs, wth + 3 * WSZ, wtl + 3 * WSZ);
        splitT768<<<tg, tb>>>(a2_wq + wofs, wth + 4 * WSZ, wtl + 4 * WSZ);
        splitT768<<<tg, tb>>>(a2_wo + wofs, wth + 5 * WSZ, wtl + 5 * WSZ);
        {
            long long t1 = (long long)Fi * Ii * Ksz;
            reorder_split<<<(unsigned)((t1 + 255) / 256), 256>>>(ff1_w + d * t1, w1h, w1l, t1, Ii);
            long long t2 = (long long)Ii * Fi * Ksz;
            reorder_split<<<(unsigned)((t2 + 255) / 256), 256>>>(ff2_w + d * t2, w2h, w2l, t2, Fi);
        }

        // --- self attention ---
        layernorm_kernel<<<Bb * Tt, 256>>>(h, n1_s + d * Ii, n1_b + d * Ii, yh, yl);
        tc(yh, yl, wth + 0 * WSZ, wtl + 0 * WSZ, 0, sc, qh, ql, Ii / 128, (Bb * Tt) / 128, 1,
           Ii, Ii, Ii, Ii, 128, FSPL, 1.f, 0, BIG, 1, 0, 0, 0, 0, 0, 0);
        tc(yh, yl, wth + 1 * WSZ, wtl + 1 * WSZ, 0, sc, kh, kl, Ii / 128, (Bb * Tt) / 128, 1,
           Ii, Ii, Ii, Ii, 128, FSPL, 1.f, 0, BIG, 1, 0, 0, 0, 0, 0, 0);
        tc(yh, yl, wth + 2 * WSZ, wtl + 2 * WSZ, 0, sc, vh, vl, Ii / 128, (Bb * Tt) / 128, 1,
           Ii, Ii, Ii, Ii, 128, FSPL, 1.f, 0, BIG, 1, 0, 0, 0, 0, 0, 0);
        {
            dim3 g(Tt / 32, Dh / 32, Bb * Hh);
            transposeV_kernel<<<g, dim3(32, 8)>>>(vh, vl, vth_, vtl_);
        }
        // scores = 0.125 q k^T per (b,h)
        tc(qh, ql, kh, kl, 0, sc, 0, 0, Tt / 128, Tt / 128, Bb * Hh, Dh, Ii, Ii, Tt, 128,
           FOUT, 0.125f, 0, BIG, Hh, TI, Dh, TI, Dh,
           (long long)Hh * Tt * Tt, (long long)Tt * Tt);
        softmax_kernel<<<Bb * Hh * Tt, 256>>>(sc, ph, pl);
        // att = P @ V per (b,h)  (B = pre-transposed V, non-trans cp.async)
        tc(ph, pl, vth_, vtl_, 0, sc, ath, atl, 1, Tt / 128, Bb * Hh, Tt, Tt, Tt, Ii, 64,
           FSPL, 1.f, 0, BIG, Hh,
           (long long)Hh * Tt * Tt, (long long)Tt * Tt,
           (long long)Hh * Dh * Tt, (long long)Dh * Tt, TI, Dh);
        // h += att @ wo + bo
        tc(ath, atl, wth + 3 * WSZ, wtl + 3 * WSZ, a1_bo + d * Ii, h, 0, 0,
           Ii / 128, (Bb * Tt) / 128, 1, Ii, Ii, Ii, Ii, 128,
           FBN | FADD, 1.f, 0, BIG, 1, 0, 0, 0, 0, 0, 0);

        // --- cross attention ---
        layernorm_kernel<<<Bb * Tt, 256>>>(h, n2_s + d * Ii, n2_b + d * Ii, yh, yl);
        tc(yh, yl, wth + 4 * WSZ, wtl + 4 * WSZ, 0, q, 0, 0, Ii / 128, (Bb * Tt) / 128, 1,
           Ii, Ii, Ii, Ii, 128, FOUT, 1.f, 0, BIG, 1, 0, 0, 0, 0, 0, 0);
        {
            dim3 g((Ii + 63) / 64, (Bb * Ss + 63) / 64);
            gemm_kernel<<<g, 256>>>(ctx, a2_wk + (long long)d * Cx * Ii, kcb,
                                    Bb * Ss, Ii, Cx, Cx, Ii, Ii);
            gemm_kernel<<<g, 256>>>(ctx, a2_wv + (long long)d * Cx * Ii, vcb,
                                    Bb * Ss, Ii, Cx, Cx, Ii, Ii);
        }
        crossattn_kernel<<<Bb * Hh * Tt / 8, 256>>>(q, kcb, vcb, ath, atl);
        tc(ath, atl, wth + 5 * WSZ, wtl + 5 * WSZ, a2_bo + d * Ii, h, 0, 0,
           Ii / 128, (Bb * Tt) / 128, 1, Ii, Ii, Ii, Ii, 128,
           FBN | FADD, 1.f, 0, BIG, 1, 0, 0, 0, 0, 0, 0);

        // --- feed-forward ---
        layernorm_kernel<<<Bb * Tt, 256>>>(h, n3_s + d * Ii, n3_b + d * Ii, yh, yl);
        tc(yh, yl, w1h, w1l, ff1_b + d * Fi, sc, ffh, ffl, Fi / 128, Tt / 128, Bb,
           Ii * Ksz, Ii, Ii * Ksz, Fi, 128, FBN | FGELU | FSPL, 1.f,
           -(long long)4 * Ii, TI, 1, TI, 0, 0, 0, (long long)Tt * Fi, 0);
        tc(ffh, ffl, w2h, w2l, ff2_b + d * Ii, h, hh, hl, Ii / 128, Tt / 128, Bb,
           Fi * Ksz, Fi, Fi * Ksz, Ii, 128,
           FBN | FADD | (d == Dd - 1 ? FSPL : 0), 1.f,
           -(long long)4 * Fi, (long long)Tt * Fi, 1,
           (long long)Tt * Fi, 0, 0, 0, TI, 0);
    }

    // out = x + pout_w @ h^T + pout_b
    cudaMemcpyAsync(out, x, (size_t)Bb * Cc * Tt * sizeof(float),
                    cudaMemcpyDeviceToDevice);
    tc(wth + 7 * WSZ, wtl + 7 * WSZ, hh, hl, pout_b, out, 0, 0,
       Tt / 128, Cc / 128, Bb, Ii, Ii, Ii, Tt, 128, FBM | FADD, 1.f,
       0, BIG, 1, 0, 0, TI, 0, (long long)Cc * Tt, 0);
}

// round 10
// speedup vs baseline: 2.8495x; 1.0079x over previous
#include <cuda_runtime.h>
#include <cuda_bf16.h>
#include <math.h>
#include <stdint.h>

#define Bb 2
#define Cc 768
#define Tt 2048
#define Ii 768
#define Hh 12
#define Dh 64
#define Ss 16
#define Cx 512
#define Fi 3072
#define Dd 2
#define Ksz 9

typedef __nv_bfloat16 bf16;
typedef unsigned short u16;

// ---------------- scratch ----------------
__device__ float g_h  [(long long)Bb*Tt*Ii];
__device__ float g_q  [(long long)Bb*Tt*Ii];
__device__ float g_sc [(long long)Bb*Hh*Tt*Tt];
__device__ float g_kc [(long long)Bb*Ss*Ii];
__device__ float g_vc [(long long)Bb*Ss*Ii];

__device__ u16 g_gnh[(long long)Bb*Cc*Tt], g_gnl[(long long)Bb*Cc*Tt];
__device__ u16 g_yh [(long long)Bb*Tt*Ii], g_yl [(long long)Bb*Tt*Ii];
__device__ u16 g_qkvh[(long long)Bb*Tt*3*Ii], g_qkvl[(long long)Bb*Tt*3*Ii];
__device__ u16 g_vth[(long long)Bb*Ii*Tt], g_vtl[(long long)Bb*Ii*Tt];
__device__ u16 g_ath[(long long)Bb*Tt*Ii], g_atl[(long long)Bb*Tt*Ii];
__device__ u16 g_hh [(long long)Bb*Tt*Ii], g_hl [(long long)Bb*Tt*Ii];
__device__ u16 g_ph [(long long)Bb*Hh*Tt*Tt], g_pl [(long long)Bb*Hh*Tt*Tt];
__device__ u16 g_ffh[(long long)Bb*Tt*Fi], g_ffl[(long long)Bb*Tt*Fi];
__device__ u16 g_w1h[(long long)Fi*Ii*Ksz], g_w1l[(long long)Fi*Ii*Ksz];
__device__ u16 g_w2h[(long long)Ii*Fi*Ksz], g_w2l[(long long)Ii*Fi*Ksz];
__device__ u16 g_wth[8ll*Ii*Ii], g_wtl[8ll*Ii*Ii];

// ---------------- helpers ----------------
__device__ __forceinline__ uint32_t smem_u32(const void* p) {
    uint32_t a;
    asm("{ .reg .u64 t; cvta.to.shared.u64 t, %1; cvt.u32.u64 %0, t; }" : "=r"(a) : "l"(p));
    return a;
}
#define SWZ(x) ((x) ^ ((((uint32_t)(x)) >> 3) & 0x70))
#define CP16(dst, src) asm volatile("cp.async.cg.shared.global [%0], [%1], 16;" :: "r"(dst), "l"(src))
#define CPCOMMIT() asm volatile("cp.async.commit_group;" ::: "memory")
#define CPWAIT1() asm volatile("cp.async.wait_group 1;" ::: "memory")
#define CPWAIT0() asm volatile("cp.async.wait_group 0;" ::: "memory")

__device__ __forceinline__ void ldsm4(uint32_t* r, uint32_t addr) {
    asm volatile("ldmatrix.sync.aligned.m8n8.x4.shared.b16 {%0,%1,%2,%3}, [%4];"
        : "=r"(r[0]), "=r"(r[1]), "=r"(r[2]), "=r"(r[3]) : "r"(addr));
}
__device__ __forceinline__ void mma16816(float* c, const uint32_t* a, const uint32_t* b) {
    asm volatile("mma.sync.aligned.m16n8k16.row.col.f32.bf16.bf16.f32 "
        "{%0,%1,%2,%3}, {%4,%5,%6,%7}, {%8,%9}, {%0,%1,%2,%3};"
        : "+f"(c[0]), "+f"(c[1]), "+f"(c[2]), "+f"(c[3])
        : "r"(a[0]), "r"(a[1]), "r"(a[2]), "r"(a[3]), "r"(b[0]), "r"(b[1]));
}
__device__ __forceinline__ void splitf(float x, u16& h, u16& l) {
    bf16 hb = __float2bfloat16(x);
    bf16 lb = __float2bfloat16(x - __bfloat162float(hb));
    h = __bfloat16_as_ushort(hb);
    l = __bfloat16_as_ushort(lb);
}

// flags
#define FTA   1
#define FTB   2
#define FBN   4
#define FBM   8
#define FGELU 16
#define FADD  32
#define FOUT  64
#define FSPL  128

#define TC_SMEM (131072 + 1024)
#define NTHREADS 512

// stage 16B segments via cp.async (non-trans): op[r][k] = G[off0 + r*ld + k]
__device__ __forceinline__ void stage_nt(const u16* __restrict__ Gh, const u16* __restrict__ Gl,
        long long off0, long long flim, int ld, int k0, int rows,
        uint32_t smh, uint32_t sml) {
    int nseg = rows * 8;
    for (int idx = threadIdx.x; idx < nseg; idx += NTHREADS) {
        int r = idx >> 3, s = idx & 7;
        long long f = off0 + (long long)r * ld + k0 + s * 8;
        uint32_t d = SWZ((uint32_t)(r * 128 + s * 16));
        if (f >= 0 && f + 8 <= flim) {
            CP16(smh + d, Gh + f);
            CP16(sml + d, Gl + f);
        } else {
            asm volatile("st.shared.v4.u32 [%0], {%1,%1,%1,%1};" :: "r"(smh + d), "r"(0));
            asm volatile("st.shared.v4.u32 [%0], {%1,%1,%1,%1};" :: "r"(sml + d), "r"(0));
        }
    }
}
// synchronous trans staging: op[r][k] = G[off0 + k*ld + r]
__device__ __forceinline__ void stage_t(const u16* __restrict__ Gh, const u16* __restrict__ Gl,
        long long off0, long long flim, int ld, int k0, int rows,
        uint32_t smh, uint32_t sml) {
    int items = 64 * (rows >> 3);
    for (int idx = threadIdx.x; idx < items; idx += NTHREADS) {
        int kk = idx & 63, r0 = (idx >> 6) << 3;
        long long f = off0 + (long long)(k0 + kk) * ld + r0;
        uint32_t hw[4] = {0,0,0,0}, lw[4] = {0,0,0,0};
        if (f >= 0 && f + 8 <= flim) {
            uint4 a = *(const uint4*)(Gh + f);
            uint4 b = *(const uint4*)(Gl + f);
            hw[0]=a.x; hw[1]=a.y; hw[2]=a.z; hw[3]=a.w;
            lw[0]=b.x; lw[1]=b.y; lw[2]=b.z; lw[3]=b.w;
        }
        const u16* hp = (const u16*)hw;
        const u16* lp = (const u16*)lw;
        #pragma unroll
        for (int j = 0; j < 8; ++j) {
            uint32_t d = SWZ((uint32_t)((r0 + j) * 128 + kk * 2));
            asm volatile("st.shared.u16 [%0], %1;" :: "r"(smh + d), "h"(hp[j]));
            asm volatile("st.shared.u16 [%0], %1;" :: "r"(sml + d), "h"(lp[j]));
        }
    }
}

// ===== tensor-core GEMM: 512 threads, 4x4 warp grid, warp tile 32 x (NT/4) =====
template<int NT>
__global__ void __launch_bounds__(NTHREADS, 1)
tc_gemm(const u16* __restrict__ Ah, const u16* __restrict__ Al,
        const u16* __restrict__ Bh, const u16* __restrict__ Bl,
        const float* __restrict__ bias, float* __restrict__ out,
        u16* __restrict__ oh, u16* __restrict__ ol,
        int K, int lda, int ldb, long long ldo, int flags, float alpha,
        long long offA, long long flimA, int b2,
        long long sA1, long long sA2, long long sB1, long long sB2,
        long long sC1, long long sC2)
{
    extern __shared__ char dynsm[];
    long long z1 = blockIdx.z / b2, z2 = blockIdx.z % b2;
    Ah += z1 * sA1 + z2 * sA2;  Al += z1 * sA1 + z2 * sA2;
    Bh += z1 * sB1 + z2 * sB2;  Bl += z1 * sB1 + z2 * sB2;
    long long zc = z1 * sC1 + z2 * sC2;
    out += zc;
    if (flags & FSPL) { oh += zc; ol += zc; }

    const int tid = threadIdx.x;
    const int lane = tid & 31;
    const int wid = tid >> 5;                 // 0..15
    const int wm = (wid & 3) * 32;            // 4 M-warps * 32 rows
    constexpr int WN = NT / 4;                // warp N extent (32 or 16)
    const int wn = (wid >> 2) * WN;           // 4 N-warps
    const int ksrot = (wid >> 2) & 3;         // phase stagger per SMSP
    const int m0 = blockIdx.y * 128;
    const int n0 = blockIdx.x * NT;
    constexpr int NTW = WN / 8;               // n8 tiles per warp (4 or 2)
    constexpr int NB = NTW / 2;               // 16-col pairs (2 or 1)

    uint32_t smBase = smem_u32(dynsm);
    smBase = (smBase + 1023) & ~1023u;

    const int tAf = flags & FTA, tBf = flags & FTB;
    const long long aoff = offA + (tAf ? (long long)m0 : (long long)m0 * lda);
    const long long boff = (tBf ? (long long)n0 : (long long)n0 * ldb);
    const long long BIGL = 1LL << 62;
    const int nc = K / 64;

    float acc[2][NTW][4];
    #pragma unroll
    for (int i = 0; i < 2; ++i)
        #pragma unroll
        for (int j = 0; j < NTW; ++j)
            #pragma unroll
            for (int l = 0; l < 4; ++l) acc[i][j][l] = 0.f;

    const uint32_t aRow = wm + (lane & 15);
    const uint32_t aKof = (lane >> 4) << 3;
    const int bi = lane >> 3;
    const uint32_t bRowBase = wn + ((bi >> 1) << 3) + (lane & 7);
    const uint32_t bKof = (bi & 1) << 3;

    auto stage = [&](int c, int s) {
        uint32_t base = smBase + s * 65536;
        if (tAf) stage_t (Ah, Al, aoff, flimA, lda, c * 64, 128, base, base + 16384);
        else     stage_nt(Ah, Al, aoff, flimA, lda, c * 64, 128, base, base + 16384);
        if (tBf) stage_t (Bh, Bl, boff, BIGL, ldb, c * 64, NT, base + 32768, base + 49152);
        else     stage_nt(Bh, Bl, boff, BIGL, ldb, c * 64, NT, base + 32768, base + 49152);
        CPCOMMIT();
    };

    stage(0, 0);
    for (int c = 0; c < nc; ++c) {
        if (c + 1 < nc) { stage(c + 1, (c + 1) & 1); CPWAIT1(); }
        else            { CPWAIT0(); }
        __syncthreads();
        uint32_t base = smBase + (c & 1) * 65536;
        const uint32_t aHi = base, aLo = base + 16384;
        const uint32_t bHi = base + 32768, bLo = base + 49152;
        #pragma unroll
        for (int ki = 0; ki < 4; ++ki) {
            const int ks = (ki + ksrot) & 3;      // stagger phases across SMSP warps
            const uint32_t kb = ks * 16;
            uint32_t ah[2][4], al[2][4], bh[NB][4], bl[NB][4];
            #pragma unroll
            for (int mt = 0; mt < 2; ++mt) {
                uint32_t off = SWZ((aRow + mt * 16) * 128 + (kb + aKof) * 2);
                ldsm4(ah[mt], aHi + off);
                ldsm4(al[mt], aLo + off);
            }
            #pragma unroll
            for (int bp = 0; bp < NB; ++bp) {
                uint32_t off = SWZ((bRowBase + bp * 16) * 128 + (kb + bKof) * 2);
                ldsm4(bh[bp], bHi + off);
                ldsm4(bl[bp], bLo + off);
            }
            #pragma unroll
            for (int bp = 0; bp < NB; ++bp)
                #pragma unroll
                for (int mt = 0; mt < 2; ++mt) {
                    mma16816(acc[mt][2 * bp],     ah[mt], bh[bp]);
                    mma16816(acc[mt][2 * bp + 1], ah[mt], bh[bp] + 2);
                }
            #pragma unroll
            for (int bp = 0; bp < NB; ++bp)
                #pragma unroll
                for (int mt = 0; mt < 2; ++mt) {
                    mma16816(acc[mt][2 * bp],     al[mt], bh[bp]);
                    mma16816(acc[mt][2 * bp + 1], al[mt], bh[bp] + 2);
                }
            #pragma unroll
            for (int bp = 0; bp < NB; ++bp)
                #pragma unroll
                for (int mt = 0; mt < 2; ++mt) {
                    mma16816(acc[mt][2 * bp],     ah[mt], bl[bp]);
                    mma16816(acc[mt][2 * bp + 1], ah[mt], bl[bp] + 2);
                }
        }
        __syncthreads();
    }

    // epilogue
    const int g = lane >> 2, tg = lane & 3;
    #pragma unroll
    for (int mt = 0; mt < 2; ++mt) {
        #pragma unroll
        for (int hf = 0; hf < 2; ++hf) {
            int m = m0 + wm + mt * 16 + g + hf * 8;
            float bm = (flags & FBM) ? bias[m] : 0.f;
            long long rbase = (long long)m * ldo;
            #pragma unroll
            for (int nt = 0; nt < NTW; ++nt) {
                int n = n0 + wn + nt * 8 + tg * 2;
                float v0 = alpha * acc[mt][nt][hf * 2 + 0];
                float v1 = alpha * acc[mt][nt][hf * 2 + 1];
                if (flags & FBN) { v0 += bias[n]; v1 += bias[n + 1]; }
                else if (flags & FBM) { v0 += bm; v1 += bm; }
                if (flags & FGELU) {
                    v0 = 0.5f * v0 * (1.f + erff(v0 * 0.70710678118654752f));
                    v1 = 0.5f * v1 * (1.f + erff(v1 * 0.70710678118654752f));
                }
                if (flags & FADD) { v0 += out[rbase + n]; v1 += out[rbase + n + 1]; }
                if (flags & (FOUT | FADD)) { out[rbase + n] = v0; out[rbase + n + 1] = v1; }
                if (flags & FSPL) {
                    u16 h0, l0, h1, l1;
                    splitf(v0, h0, l0);
                    splitf(v1, h1, l1);
                    oh[rbase + n] = h0; ol[rbase + n] = l0;
                    oh[rbase + n + 1] = h1; ol[rbase + n + 1] = l1;
                }
            }
        }
    }
}

// ---------------- reductions ----------------
__device__ __forceinline__ float blockReduceSum(float v) {
    __shared__ float sm[32];
    int lane = threadIdx.x & 31, wid = threadIdx.x >> 5;
    #pragma unroll
    for (int o = 16; o; o >>= 1) v += __shfl_xor_sync(0xffffffffu, v, o);
    if (lane == 0) sm[wid] = v;
    __syncthreads();
    if (wid == 0) {
        int nw = (blockDim.x + 31) >> 5;
        v = (lane < nw) ? sm[lane] : 0.f;
        #pragma unroll
        for (int o = 16; o; o >>= 1) v += __shfl_xor_sync(0xffffffffu, v, o);
        if (lane == 0) sm[0] = v;
    }
    __syncthreads();
    float r = sm[0];
    __syncthreads();
    return r;
}
__device__ __forceinline__ float blockReduceMax(float v) {
    __shared__ float sm[32];
    int lane = threadIdx.x & 31, wid = threadIdx.x >> 5;
    #pragma unroll
    for (int o = 16; o; o >>= 1) v = fmaxf(v, __shfl_xor_sync(0xffffffffu, v, o));
    if (lane == 0) sm[wid] = v;
    __syncthreads();
    if (wid == 0) {
        int nw = (blockDim.x + 31) >> 5;
        v = (lane < nw) ? sm[lane] : -INFINITY;
        #pragma unroll
        for (int o = 16; o; o >>= 1) v = fmaxf(v, __shfl_xor_sync(0xffffffffu, v, o));
        if (lane == 0) sm[0] = v;
    }
    __syncthreads();
    float r = sm[0];
    __syncthreads();
    return r;
}

__global__ void groupnorm_kernel(const float* __restrict__ x, const float* __restrict__ sc,
                                 const float* __restrict__ bi,
                                 u16* __restrict__ oh, u16* __restrict__ ol) {
    const int CPG = Cc / 32;
    int b = blockIdx.x >> 5, g = blockIdx.x & 31;
    const long long base = ((long long)b * Cc + (long long)g * CPG) * Tt;
    const float* xp = x + base;
    const int n = CPG * Tt;
    float s = 0.f, ss = 0.f;
    for (int i = threadIdx.x; i < n; i += blockDim.x) {
        float v = xp[i]; s += v; ss = fmaf(v, v, ss);
    }
    s = blockReduceSum(s); ss = blockReduceSum(ss);
    float mean = s / n;
    float inv = rsqrtf(ss / n - mean * mean + 1e-6f);
    for (int i = threadIdx.x; i < n; i += blockDim.x) {
        int c = g * CPG + i / Tt;
        float v = (xp[i] - mean) * inv * sc[c] + bi[c];
        u16 hv, lv; splitf(v, hv, lv);
        oh[base + i] = hv; ol[base + i] = lv;
    }
}

__global__ void layernorm_kernel(const float* __restrict__ x, const float* __restrict__ sc,
                                 const float* __restrict__ bi,
                                 u16* __restrict__ oh, u16* __restrict__ ol) {
    const long long rb = (long long)blockIdx.x * Ii;
    const float* row = x + rb;
    float s = 0.f, ss = 0.f;
    for (int i = threadIdx.x; i < Ii; i += blockDim.x) {
        float v = row[i]; s += v; ss = fmaf(v, v, ss);
    }
    s = blockReduceSum(s); ss = blockReduceSum(ss);
    float mean = s / (float)Ii;
    float inv = rsqrtf(ss / (float)Ii - mean * mean + 1e-5f);
    for (int i = threadIdx.x; i < Ii; i += blockDim.x) {
        float v = (row[i] - mean) * inv * sc[i] + bi[i];
        u16 hv, lv; splitf(v, hv, lv);
        oh[rb + i] = hv; ol[rb + i] = lv;
    }
}

// small fp32 gemm for tiny cross-attn K/V projections (M=32)
__global__ void __launch_bounds__(256) gemm_kernel(
    const float* __restrict__ A, const float* __restrict__ B, float* __restrict__ Cp,
    int M, int N, int K, int lda, int ldb, int ldc)
{
    __shared__ float As[16][65];
    __shared__ float Bs[16][65];
    int n0 = blockIdx.x * 64, m0 = blockIdx.y * 64;
    int tid = threadIdx.x;
    int tx = tid & 15, ty = tid >> 4;
    float acc[4][4] = {};
    for (int k0 = 0; k0 < K; k0 += 16) {
        #pragma unroll
        for (int u = 0; u < 4; ++u) {
            int i = tid + u * 256;
            int mm = i >> 4, kk = i & 15;
            int m = m0 + mm, k = k0 + kk;
            As[kk][mm] = (m < M && k < K) ? A[(long long)m * lda + k] : 0.f;
        }
        #pragma unroll
        for (int u = 0; u < 4; ++u) {
            int i = tid + u * 256;
            int kk = i >> 6, nn = i & 63;
            int k = k0 + kk, n = n0 + nn;
            Bs[kk][nn] = (k < K && n < N) ? B[(long long)k * ldb + n] : 0.f;
        }
        __syncthreads();
        #pragma unroll
        for (int kk = 0; kk < 16; ++kk) {
            float a[4], bb[4];
            #pragma unroll
            for (int i = 0; i < 4; ++i) a[i] = As[kk][ty * 4 + i];
            #pragma unroll
            for (int j = 0; j < 4; ++j) bb[j] = Bs[kk][tx * 4 + j];
            #pragma unroll
            for (int i = 0; i < 4; ++i)
                #pragma unroll
                for (int j = 0; j < 4; ++j)
                    acc[i][j] = fmaf(a[i], bb[j], acc[i][j]);
        }
        __syncthreads();
    }
    #pragma unroll
    for (int i = 0; i < 4; ++i) {
        int m = m0 + ty * 4 + i;
        if (m >= M) continue;
        #pragma unroll
        for (int j = 0; j < 4; ++j) {
            int n = n0 + tx * 4 + j;
            if (n < N) Cp[(long long)m * ldc + n] = acc[i][j];
        }
    }
}

__global__ void softmax_kernel(const float* __restrict__ s,
                               u16* __restrict__ oh, u16* __restrict__ ol) {
    const long long rb = (long long)blockIdx.x * Tt;
    const float* row = s + rb;
    int tid = threadIdx.x;
    float v[8];
    float mx = -INFINITY;
    #pragma unroll
    for (int i = 0; i < 8; ++i) { v[i] = row[tid + (i << 8)]; mx = fmaxf(mx, v[i]); }
    mx = blockReduceMax(mx);
    float sum = 0.f;
    #pragma unroll
    for (int i = 0; i < 8; ++i) { v[i] = expf(v[i] - mx); sum += v[i]; }
    sum = blockReduceSum(sum);
    float inv = 1.f / sum;
    #pragma unroll
    for (int i = 0; i < 8; ++i) {
        u16 hv, lv; splitf(v[i] * inv, hv, lv);
        oh[rb + tid + (i << 8)] = hv;
        ol[rb + tid + (i << 8)] = lv;
    }
}

__global__ void crossattn_kernel(const float* __restrict__ q, const float* __restrict__ kc,
                                 const float* __restrict__ vc,
                                 u16* __restrict__ oh, u16* __restrict__ ol) {
    int gw = blockIdx.x * (blockDim.x >> 5) + (threadIdx.x >> 5);
    int lane = threadIdx.x & 31;
    int t = gw % Tt;
    int rem = gw / Tt;
    int h = rem % Hh;
    int b = rem / Hh;
    const float* qp = q + ((long long)(b * Tt + t)) * Ii + h * Dh;
    const float* kb = kc + (long long)b * Ss * Ii + h * Dh;
    const float* vb = vc + (long long)b * Ss * Ii + h * Dh;
    float sj = -INFINITY;
    if (lane < Ss) {
        const float* kp = kb + lane * Ii;
        float acc = 0.f;
        #pragma unroll
        for (int d2 = 0; d2 < Dh; ++d2) acc = fmaf(qp[d2], kp[d2], acc);
        sj = acc * 0.125f;
    }
    float mx = sj;
    #pragma unroll
    for (int o = 16; o; o >>= 1) mx = fmaxf(mx, __shfl_xor_sync(0xffffffffu, mx, o));
    float p = (lane < Ss) ? expf(sj - mx) : 0.f;
    float sum = p;
    #pragma unroll
    for (int o = 16; o; o >>= 1) sum += __shfl_xor_sync(0xffffffffu, sum, o);
    p /= sum;
    float o0 = 0.f, o1 = 0.f;
    #pragma unroll
    for (int j = 0; j < Ss; ++j) {
        float pj = __shfl_sync(0xffffffffu, p, j);
        const float* vp = vb + j * Ii;
        o0 = fmaf(pj, vp[lane], o0);
        o1 = fmaf(pj, vp[lane + 32], o1);
    }
    long long ob = ((long long)(b * Tt + t)) * Ii + h * Dh;
    u16 hv, lv;
    splitf(o0, hv, lv); oh[ob + lane] = hv; ol[ob + lane] = lv;
    splitf(o1, hv, lv); oh[ob + lane + 32] = hv; ol[ob + lane + 32] = lv;
}

// per-head transpose of split V (src row stride ld, col offset off)
__global__ void transposeV_kernel(const u16* __restrict__ vh, const u16* __restrict__ vl,
                                  u16* __restrict__ oth, u16* __restrict__ otl,
                                  int ld, int off) {
    __shared__ u16 th[32][33], tl[32][33];
    int bh = blockIdx.z;
    int b = bh / Hh, h = bh % Hh;
    int t0 = blockIdx.x * 32, d0 = blockIdx.y * 32;
    #pragma unroll
    for (int i = 0; i < 32; i += 8) {
        long long src = ((long long)(b * Tt + t0 + threadIdx.y + i)) * ld + off + h * Dh + d0 + threadIdx.x;
        th[threadIdx.y + i][threadIdx.x] = vh[src];
        tl[threadIdx.y + i][threadIdx.x] = vl[src];
    }
    __syncthreads();
    #pragma unroll
    for (int i = 0; i < 32; i += 8) {
        long long dst = ((long long)((b * Hh + h) * Dh + d0 + threadIdx.y + i)) * Tt + t0 + threadIdx.x;
        oth[dst] = th[threadIdx.x][threadIdx.y + i];
        otl[dst] = tl[threadIdx.x][threadIdx.y + i];
    }
}

// elementwise split fp32 -> bf16 hi/lo
__global__ void split_ew(const float* __restrict__ w, u16* __restrict__ oh,
                         u16* __restrict__ ol, long long n) {
    long long i = (long long)blockIdx.x * 256 + threadIdx.x;
    if (i >= n) return;
    u16 hv, lv; splitf(w[i], hv, lv);
    oh[i] = hv; ol[i] = lv;
}

// transpose 768x768 [K][N] -> [N][K] + split
__global__ void splitT768(const float* __restrict__ w, u16* __restrict__ oh,
                          u16* __restrict__ ol) {
    __shared__ float t[32][33];
    int k0 = blockIdx.y * 32, n0 = blockIdx.x * 32;
    #pragma unroll
    for (int i = 0; i < 32; i += 8)
        t[threadIdx.y + i][threadIdx.x] = w[(long long)(k0 + threadIdx.y + i) * Ii + n0 + threadIdx.x];
    __syncthreads();
    #pragma unroll
    for (int i = 0; i < 32; i += 8) {
        long long o = (long long)(n0 + threadIdx.y + i) * Ii + k0 + threadIdx.x;
        u16 hv, lv; splitf(t[threadIdx.x][threadIdx.y + i], hv, lv);
        oh[o] = hv; ol[o] = lv;
    }
}

// conv weight reorder+split: out[o][k*Cin+c] = in[o][c*Ksz+k]
__global__ void reorder_split(const float* __restrict__ w, u16* __restrict__ oh,
                              u16* __restrict__ ol, long long total, int Cin) {
    long long i = (long long)blockIdx.x * 256 + threadIdx.x;
    if (i >= total) return;
    int rk = Cin * Ksz;
    long long oc = i / rk;
    int r = (int)(i - oc * rk);
    int k = r / Cin, c = r - k * Cin;
    u16 hv, lv; splitf(w[oc * rk + (long long)c * Ksz + k], hv, lv);
    oh[i] = hv; ol[i] = lv;
}

// ---------------- host wrapper ----------------
static void tc(const u16* Ah, const u16* Al, const u16* Bh, const u16* Bl,
               const float* bias, float* out, u16* oh, u16* ol,
               int gx, int gy, int gz, int K, int lda, int ldb, long long ldo,
               int ntile, int flags, float alpha, long long offA, long long flimA,
               int b2, long long sA1, long long sA2, long long sB1, long long sB2,
               long long sC1, long long sC2)
{
    dim3 g(gx, gy, gz);
    if (ntile == 64)
        tc_gemm<64><<<g, NTHREADS, TC_SMEM>>>(Ah, Al, Bh, Bl, bias, out, oh, ol, K, lda, ldb,
            ldo, flags, alpha, offA, flimA, b2, sA1, sA2, sB1, sB2, sC1, sC2);
    else
        tc_gemm<128><<<g, NTHREADS, TC_SMEM>>>(Ah, Al, Bh, Bl, bias, out, oh, ol, K, lda, ldb,
            ldo, flags, alpha, offA, flimA, b2, sA1, sA2, sB1, sB2, sC1, sC2);
}

extern "C" void kernel_launch(void* const* d_in, const int* in_sizes, int n_in,
                              void* d_out, int out_size) {
    const float* x      = (const float*)d_in[0];
    const float* ctx    = (const float*)d_in[1];
    const float* gn_s   = (const float*)d_in[2];
    const float* gn_b   = (const float*)d_in[3];
    const float* pin_w  = (const float*)d_in[4];
    const float* pin_b  = (const float*)d_in[5];
    const float* n1_s   = (const float*)d_in[6];
    const float* n1_b   = (const float*)d_in[7];
    const float* a1_wq  = (const float*)d_in[8];
    const float* a1_wk  = (const float*)d_in[9];
    const float* a1_wv  = (const float*)d_in[10];
    const float* a1_wo  = (const float*)d_in[11];
    const float* a1_bo  = (const float*)d_in[12];
    const float* n2_s   = (const float*)d_in[13];
    const float* n2_b   = (const float*)d_in[14];
    const float* a2_wq  = (const float*)d_in[15];
    const float* a2_wk  = (const float*)d_in[16];
    const float* a2_wv  = (const float*)d_in[17];
    const float* a2_wo  = (const float*)d_in[18];
    const float* a2_bo  = (const float*)d_in[19];
    const float* n3_s   = (const float*)d_in[20];
    const float* n3_b   = (const float*)d_in[21];
    const float* ff1_w  = (const float*)d_in[22];
    const float* ff1_b  = (const float*)d_in[23];
    const float* ff2_w  = (const float*)d_in[24];
    const float* ff2_b  = (const float*)d_in[25];
    const float* pout_w = (const float*)d_in[26];
    const float* pout_b = (const float*)d_in[27];
    float* out = (float*)d_out;

    cudaFuncSetAttribute(tc_gemm<128>, cudaFuncAttributeMaxDynamicSharedMemorySize, TC_SMEM);
    cudaFuncSetAttribute(tc_gemm<64>,  cudaFuncAttributeMaxDynamicSharedMemorySize, TC_SMEM);

    float *h, *q, *sc, *kcb, *vcb;
    u16 *gnh, *gnl, *yh, *yl, *qkvh, *qkvl, *vth_, *vtl_, *ath, *atl;
    u16 *hh, *hl, *ph, *pl, *ffh, *ffl, *w1h, *w1l, *w2h, *w2l, *wth, *wtl;
    cudaGetSymbolAddress((void**)&h,   g_h);
    cudaGetSymbolAddress((void**)&q,   g_q);
    cudaGetSymbolAddress((void**)&sc,  g_sc);
    cudaGetSymbolAddress((void**)&kcb, g_kc);
    cudaGetSymbolAddress((void**)&vcb, g_vc);
    cudaGetSymbolAddress((void**)&gnh, g_gnh); cudaGetSymbolAddress((void**)&gnl, g_gnl);
    cudaGetSymbolAddress((void**)&yh,  g_yh);  cudaGetSymbolAddress((void**)&yl,  g_yl);
    cudaGetSymbolAddress((void**)&qkvh, g_qkvh); cudaGetSymbolAddress((void**)&qkvl, g_qkvl);
    cudaGetSymbolAddress((void**)&vth_, g_vth); cudaGetSymbolAddress((void**)&vtl_, g_vtl);
    cudaGetSymbolAddress((void**)&ath, g_ath); cudaGetSymbolAddress((void**)&atl, g_atl);
    cudaGetSymbolAddress((void**)&hh,  g_hh);  cudaGetSymbolAddress((void**)&hl,  g_hl);
    cudaGetSymbolAddress((void**)&ph,  g_ph);  cudaGetSymbolAddress((void**)&pl,  g_pl);
    cudaGetSymbolAddress((void**)&ffh, g_ffh); cudaGetSymbolAddress((void**)&ffl, g_ffl);
    cudaGetSymbolAddress((void**)&w1h, g_w1h); cudaGetSymbolAddress((void**)&w1l, g_w1l);
    cudaGetSymbolAddress((void**)&w2h, g_w2h); cudaGetSymbolAddress((void**)&w2l, g_w2l);
    cudaGetSymbolAddress((void**)&wth, g_wth); cudaGetSymbolAddress((void**)&wtl, g_wtl);

    const long long BIG = 1LL << 62;
    const long long TI = (long long)Tt * Ii;
    const long long T3I = (long long)Tt * 3 * Ii;
    const long long WSZ = (long long)Ii * Ii;
    const unsigned WB = (unsigned)((WSZ + 255) / 256);

    split_ew<<<WB, 256>>>(pin_w,  wth + 6 * WSZ, wtl + 6 * WSZ, WSZ);
    split_ew<<<WB, 256>>>(pout_w, wth + 7 * WSZ, wtl + 7 * WSZ, WSZ);

    groupnorm_kernel<<<Bb * 32, 256>>>(x, gn_s, gn_b, gnh, gnl);

    // proj_in: h = pin_w . gn + pin_b (A trans-staged)
    tc(gnh, gnl, wth + 6 * WSZ, wtl + 6 * WSZ, pin_b, h, 0, 0,
       Ii / 128, Tt / 128, Bb, Cc, Tt, Cc, Ii, 128, FTA | FBN | FOUT, 1.f,
       0, (long long)Cc * Tt, 1, (long long)Cc * Tt, 0, 0, 0, TI, 0);

    for (int d = 0; d < Dd; ++d) {
        long long wofs = (long long)d * WSZ;
        dim3 tg(24, 24), tb(32, 8);
        splitT768<<<tg, tb>>>(a1_wq + wofs, wth + 0 * WSZ, wtl + 0 * WSZ);
        splitT768<<<tg, tb>>>(a1_wk + wofs, wth + 1 * WSZ, wtl + 1 * WSZ);
        splitT768<<<tg, tb>>>(a1_wv + wofs, wth + 2 * WSZ, wtl + 2 * WSZ);
        splitT768<<<tg, tb>>>(a1_wo + wofs, wth + 3 * WSZ, wtl + 3 * WSZ);
        splitT768<<<tg, tb>>>(a2_wq + wofs, wth + 4 * WSZ, wtl + 4 * WSZ);
        splitT768<<<tg, tb>>>(a2_wo + wofs, wth + 5 * WSZ, wtl + 5 * WSZ);
        {
            long long t1 = (long long)Fi * Ii * Ksz;
            reorder_split<<<(unsigned)((t1 + 255) / 256), 256>>>(ff1_w + d * t1, w1h, w1l, t1, Ii);
            long long t2 = (long long)Ii * Fi * Ksz;
            reorder_split<<<(unsigned)((t2 + 255) / 256), 256>>>(ff2_w + d * t2, w2h, w2l, t2, Fi);
        }

        // --- self attention ---
        layernorm_kernel<<<Bb * Tt, 256>>>(h, n1_s + d * Ii, n1_b + d * Ii, yh, yl);
        // fused QKV: C[4096][2304] = y @ [wq|wk|wv]^T
        tc(yh, yl, wth, wtl, 0, sc, qkvh, qkvl, (3 * Ii) / 128, (Bb * Tt) / 128, 1,
           Ii, Ii, Ii, 3 * Ii, 128, FSPL, 1.f, 0, BIG, 1, 0, 0, 0, 0, 0, 0);
        {
            dim3 g(Tt / 32, Dh / 32, Bb * Hh);
            transposeV_kernel<<<g, dim3(32, 8)>>>(qkvh, qkvl, vth_, vtl_, 3 * Ii, 2 * Ii);
        }
        // scores = 0.125 q k^T per (b,h):  A = qkv[.., 0:768], B = qkv[.., 768:1536]
        tc(qkvh, qkvl, qkvh + Ii, qkvl + Ii, 0, sc, 0, 0,
           Tt / 128, Tt / 128, Bb * Hh, Dh, 3 * Ii, 3 * Ii, Tt, 128,
           FOUT, 0.125f, 0, BIG, Hh, T3I, Dh, T3I, Dh,
           (long long)Hh * Tt * Tt, (long long)Tt * Tt);
        softmax_kernel<<<Bb * Hh * Tt, 256>>>(sc, ph, pl);
        // att = P @ V per (b,h)  (B = pre-transposed V, non-trans cp.async)
        tc(ph, pl, vth_, vtl_, 0, sc, ath, atl, 1, Tt / 128, Bb * Hh, Tt, Tt, Tt, Ii, 64,
           FSPL, 1.f, 0, BIG, Hh,
           (long long)Hh * Tt * Tt, (long long)Tt * Tt,
           (long long)Hh * Dh * Tt, (long long)Dh * Tt, TI, Dh);
        // h += att @ wo + bo
        tc(ath, atl, wth + 3 * WSZ, wtl + 3 * WSZ, a1_bo + d * Ii, h, 0, 0,
           Ii / 128, (Bb * Tt) / 128, 1, Ii, Ii, Ii, Ii, 128,
           FBN | FADD, 1.f, 0, BIG, 1, 0, 0, 0, 0, 0, 0);

        // --- cross attention ---
        layernorm_kernel<<<Bb * Tt, 256>>>(h, n2_s + d * Ii, n2_b + d * Ii, yh, yl);
        tc(yh, yl, wth + 4 * WSZ, wtl + 4 * WSZ, 0, q, 0, 0, Ii / 128, (Bb * Tt) / 128, 1,
           Ii, Ii, Ii, Ii, 128, FOUT, 1.f, 0, BIG, 1, 0, 0, 0, 0, 0, 0);
        {
            dim3 g((Ii + 63) / 64, (Bb * Ss + 63) / 64);
            gemm_kernel<<<g, 256>>>(ctx, a2_wk + (long long)d * Cx * Ii, kcb,
                                    Bb * Ss, Ii, Cx, Cx, Ii, Ii);
            gemm_kernel<<<g, 256>>>(ctx, a2_wv + (long long)d * Cx * Ii, vcb,
                                    Bb * Ss, Ii, Cx, Cx, Ii, Ii);
        }
        crossattn_kernel<<<Bb * Hh * Tt / 8, 256>>>(q, kcb, vcb, ath, atl);
        tc(ath, atl, wth + 5 * WSZ, wtl + 5 * WSZ, a2_bo + d * Ii, h, 0, 0,
           Ii / 128, (Bb * Tt) / 128, 1, Ii, Ii, Ii, Ii, 128,
           FBN | FADD, 1.f, 0, BIG, 1, 0, 0, 0, 0, 0, 0);

        // --- feed-forward ---
        layernorm_kernel<<<Bb * Tt, 256>>>(h, n3_s + d * Ii, n3_b + d * Ii, yh, yl);
        tc(yh, yl, w1h, w1l, ff1_b + d * Fi, sc, ffh, ffl, Fi / 128, Tt / 128, Bb,
           Ii * Ksz, Ii, Ii * Ksz, Fi, 128, FBN | FGELU | FSPL, 1.f,
           -(long long)4 * Ii, TI, 1, TI, 0, 0, 0, (long long)Tt * Fi, 0);
        tc(ffh, ffl, w2h, w2l, ff2_b + d * Ii, h, hh, hl, Ii / 128, Tt / 128, Bb,
           Fi * Ksz, Fi, Fi * Ksz, Ii, 128,
           FBN | FADD | (d == Dd - 1 ? FSPL : 0), 1.f,
           -(long long)4 * Fi, (long long)Tt * Fi, 1,
           (long long)Tt * Fi, 0, 0, 0, TI, 0);
    }

    // out = x + pout_w @ h^T + pout_b
    cudaMemcpyAsync(out, x, (size_t)Bb * Cc * Tt * sizeof(float),
                    cudaMemcpyDeviceToDevice);
    tc(wth + 7 * WSZ, wtl + 7 * WSZ, hh, hl, pout_b, out, 0, 0,
       Tt / 128, Cc / 128, Bb, Ii, Ii, Ii, Tt, 128, FBM | FADD, 1.f,
       0, BIG, 1, 0, 0, TI, 0, (long long)Cc * Tt, 0);
}

// round 11
// speedup vs baseline: 2.9909x; 1.0496x over previous
#include <cuda_runtime.h>
#include <cuda_bf16.h>
#include <math.h>
#include <stdint.h>

#define Bb 2
#define Cc 768
#define Tt 2048
#define Ii 768
#define Hh 12
#define Dh 64
#define Ss 16
#define Cx 512
#define Fi 3072
#define Dd 2
#define Ksz 9

typedef __nv_bfloat16 bf16;
typedef unsigned short u16;

// ---------------- scratch ----------------
__device__ float g_h  [(long long)Bb*Tt*Ii];
__device__ float g_q  [(long long)Bb*Tt*Ii];
__device__ float g_sc [(long long)Bb*Hh*Tt*Tt];
__device__ float g_kc [(long long)Bb*Ss*Ii];
__device__ float g_vc [(long long)Bb*Ss*Ii];

__device__ u16 g_gnh[(long long)Bb*Cc*Tt], g_gnl[(long long)Bb*Cc*Tt];  // TRANSPOSED [b][t][c]
__device__ u16 g_yh [(long long)Bb*Tt*Ii], g_yl [(long long)Bb*Tt*Ii];
__device__ u16 g_qkvh[(long long)Bb*Tt*3*Ii], g_qkvl[(long long)Bb*Tt*3*Ii];
__device__ u16 g_vth[(long long)Bb*Ii*Tt], g_vtl[(long long)Bb*Ii*Tt];
__device__ u16 g_ath[(long long)Bb*Tt*Ii], g_atl[(long long)Bb*Tt*Ii];
__device__ u16 g_hh [(long long)Bb*Tt*Ii], g_hl [(long long)Bb*Tt*Ii];
__device__ u16 g_ph [(long long)Bb*Hh*Tt*Tt], g_pl [(long long)Bb*Hh*Tt*Tt];
__device__ u16 g_ffh[(long long)Bb*Tt*Fi], g_ffl[(long long)Bb*Tt*Fi];
__device__ u16 g_w1h[(long long)Fi*Ii*Ksz], g_w1l[(long long)Fi*Ii*Ksz];
__device__ u16 g_w2h[(long long)Ii*Fi*Ksz], g_w2l[(long long)Ii*Fi*Ksz];
__device__ u16 g_wth[8ll*Ii*Ii], g_wtl[8ll*Ii*Ii];

// ---------------- helpers ----------------
__device__ __forceinline__ uint32_t smem_u32(const void* p) {
    uint32_t a;
    asm("{ .reg .u64 t; cvta.to.shared.u64 t, %1; cvt.u32.u64 %0, t; }" : "=r"(a) : "l"(p));
    return a;
}
#define SWZ(x) ((x) ^ ((((uint32_t)(x)) >> 3) & 0x70))
#define CP16(dst, src) asm volatile("cp.async.cg.shared.global [%0], [%1], 16;" :: "r"(dst), "l"(src))
#define CPCOMMIT() asm volatile("cp.async.commit_group;" ::: "memory")
#define CPWAIT1() asm volatile("cp.async.wait_group 1;" ::: "memory")
#define CPWAIT0() asm volatile("cp.async.wait_group 0;" ::: "memory")

__device__ __forceinline__ void ldsm4(uint32_t* r, uint32_t addr) {
    asm volatile("ldmatrix.sync.aligned.m8n8.x4.shared.b16 {%0,%1,%2,%3}, [%4];"
        : "=r"(r[0]), "=r"(r[1]), "=r"(r[2]), "=r"(r[3]) : "r"(addr));
}
__device__ __forceinline__ void mma16816(float* c, const uint32_t* a, const uint32_t* b) {
    asm volatile("mma.sync.aligned.m16n8k16.row.col.f32.bf16.bf16.f32 "
        "{%0,%1,%2,%3}, {%4,%5,%6,%7}, {%8,%9}, {%0,%1,%2,%3};"
        : "+f"(c[0]), "+f"(c[1]), "+f"(c[2]), "+f"(c[3])
        : "r"(a[0]), "r"(a[1]), "r"(a[2]), "r"(a[3]), "r"(b[0]), "r"(b[1]));
}
__device__ __forceinline__ void splitf(float x, u16& h, u16& l) {
    bf16 hb = __float2bfloat16(x);
    bf16 lb = __float2bfloat16(x - __bfloat162float(hb));
    h = __bfloat16_as_ushort(hb);
    l = __bfloat16_as_ushort(lb);
}

// flags
#define FTA   1
#define FTB   2
#define FBN   4
#define FBM   8
#define FGELU 16
#define FADD  32
#define FOUT  64
#define FSPL  128

#define TC_SMEM (3*65536 + 1024)
#define NTHREADS 512

// stage 16B segments via cp.async (non-trans): op[r][k] = G[off0 + r*ld + k]
__device__ __forceinline__ void stage_nt(const u16* __restrict__ Gh, const u16* __restrict__ Gl,
        long long off0, long long flim, int ld, int k0, int rows,
        uint32_t smh, uint32_t sml) {
    int nseg = rows * 8;
    for (int idx = threadIdx.x; idx < nseg; idx += NTHREADS) {
        int r = idx >> 3, s = idx & 7;
        long long f = off0 + (long long)r * ld + k0 + s * 8;
        uint32_t d = SWZ((uint32_t)(r * 128 + s * 16));
        if (f >= 0 && f + 8 <= flim) {
            CP16(smh + d, Gh + f);
            CP16(sml + d, Gl + f);
        } else {
            asm volatile("st.shared.v4.u32 [%0], {%1,%1,%1,%1};" :: "r"(smh + d), "r"(0));
            asm volatile("st.shared.v4.u32 [%0], {%1,%1,%1,%1};" :: "r"(sml + d), "r"(0));
        }
    }
}
// synchronous trans staging: op[r][k] = G[off0 + k*ld + r]  (kept for generality)
__device__ __forceinline__ void stage_t(const u16* __restrict__ Gh, const u16* __restrict__ Gl,
        long long off0, long long flim, int ld, int k0, int rows,
        uint32_t smh, uint32_t sml) {
    int items = 64 * (rows >> 3);
    for (int idx = threadIdx.x; idx < items; idx += NTHREADS) {
        int kk = idx & 63, r0 = (idx >> 6) << 3;
        long long f = off0 + (long long)(k0 + kk) * ld + r0;
        uint32_t hw[4] = {0,0,0,0}, lw[4] = {0,0,0,0};
        if (f >= 0 && f + 8 <= flim) {
            uint4 a = *(const uint4*)(Gh + f);
            uint4 b = *(const uint4*)(Gl + f);
            hw[0]=a.x; hw[1]=a.y; hw[2]=a.z; hw[3]=a.w;
            lw[0]=b.x; lw[1]=b.y; lw[2]=b.z; lw[3]=b.w;
        }
        const u16* hp = (const u16*)hw;
        const u16* lp = (const u16*)lw;
        #pragma unroll
        for (int j = 0; j < 8; ++j) {
            uint32_t d = SWZ((uint32_t)((r0 + j) * 128 + kk * 2));
            asm volatile("st.shared.u16 [%0], %1;" :: "r"(smh + d), "h"(hp[j]));
            asm volatile("st.shared.u16 [%0], %1;" :: "r"(sml + d), "h"(lp[j]));
        }
    }
}

// ===== tensor-core GEMM: 512 threads, 4x4 warp grid, 3-stage pipeline =====
template<int NT>
__global__ void __launch_bounds__(NTHREADS, 1)
tc_gemm(const u16* __restrict__ Ah, const u16* __restrict__ Al,
        const u16* __restrict__ Bh, const u16* __restrict__ Bl,
        const float* __restrict__ bias, float* __restrict__ out,
        u16* __restrict__ oh, u16* __restrict__ ol,
        int K, int lda, int ldb, long long ldo, int flags, float alpha,
        long long offA, long long flimA, int b2,
        long long sA1, long long sA2, long long sB1, long long sB2,
        long long sC1, long long sC2)
{
    extern __shared__ char dynsm[];
    long long z1 = blockIdx.z / b2, z2 = blockIdx.z % b2;
    Ah += z1 * sA1 + z2 * sA2;  Al += z1 * sA1 + z2 * sA2;
    Bh += z1 * sB1 + z2 * sB2;  Bl += z1 * sB1 + z2 * sB2;
    long long zc = z1 * sC1 + z2 * sC2;
    out += zc;
    if (flags & FSPL) { oh += zc; ol += zc; }

    const int tid = threadIdx.x;
    const int lane = tid & 31;
    const int wid = tid >> 5;                 // 0..15
    const int wm = (wid & 3) * 32;            // 4 M-warps * 32 rows
    constexpr int WN = NT / 4;                // warp N extent (32 or 16)
    const int wn = (wid >> 2) * WN;           // 4 N-warps
    const int ksrot = (wid >> 2) & 3;         // phase stagger per SMSP
    const int m0 = blockIdx.y * 128;
    const int n0 = blockIdx.x * NT;
    constexpr int NTW = WN / 8;               // n8 tiles per warp (4 or 2)
    constexpr int NB = NTW / 2;               // 16-col pairs (2 or 1)

    uint32_t smBase = smem_u32(dynsm);
    smBase = (smBase + 1023) & ~1023u;

    const int tAf = flags & FTA, tBf = flags & FTB;
    const long long aoff = offA + (tAf ? (long long)m0 : (long long)m0 * lda);
    const long long boff = (tBf ? (long long)n0 : (long long)n0 * ldb);
    const long long BIGL = 1LL << 62;
    const int nc = K / 64;

    float acc[2][NTW][4];
    #pragma unroll
    for (int i = 0; i < 2; ++i)
        #pragma unroll
        for (int j = 0; j < NTW; ++j)
            #pragma unroll
            for (int l = 0; l < 4; ++l) acc[i][j][l] = 0.f;

    const uint32_t aRow = wm + (lane & 15);
    const uint32_t aKof = (lane >> 4) << 3;
    const int bi = lane >> 3;
    const uint32_t bRowBase = wn + ((bi >> 1) << 3) + (lane & 7);
    const uint32_t bKof = (bi & 1) << 3;

    auto stage = [&](int c, int s) {
        uint32_t base = smBase + s * 65536;
        if (tAf) stage_t (Ah, Al, aoff, flimA, lda, c * 64, 128, base, base + 16384);
        else     stage_nt(Ah, Al, aoff, flimA, lda, c * 64, 128, base, base + 16384);
        if (tBf) stage_t (Bh, Bl, boff, BIGL, ldb, c * 64, NT, base + 32768, base + 49152);
        else     stage_nt(Bh, Bl, boff, BIGL, ldb, c * 64, NT, base + 32768, base + 49152);
        CPCOMMIT();
    };

    // prologue: fill 2 stages, wait chunk 0, publish
    stage(0, 0);
    if (nc > 1) { stage(1, 1); CPWAIT1(); }
    else        { CPWAIT0(); }
    __syncthreads();

    for (int c = 0; c < nc; ++c) {
        int sb3 = c % 3;
        uint32_t base = smBase + sb3 * 65536;
        const uint32_t aHi = base, aLo = base + 16384;
        const uint32_t bHi = base + 32768, bLo = base + 49152;
        #pragma unroll
        for (int ki = 0; ki < 4; ++ki) {
            const int ks = (ki + ksrot) & 3;
            const uint32_t kb = ks * 16;
            uint32_t ah[2][4], al[2][4], bh[NB][4], bl[NB][4];
            #pragma unroll
            for (int mt = 0; mt < 2; ++mt) {
                uint32_t off = SWZ((aRow + mt * 16) * 128 + (kb + aKof) * 2);
                ldsm4(ah[mt], aHi + off);
                ldsm4(al[mt], aLo + off);
            }
            #pragma unroll
            for (int bp = 0; bp < NB; ++bp) {
                uint32_t off = SWZ((bRowBase + bp * 16) * 128 + (kb + bKof) * 2);
                ldsm4(bh[bp], bHi + off);
                ldsm4(bl[bp], bLo + off);
            }
            #pragma unroll
            for (int bp = 0; bp < NB; ++bp)
                #pragma unroll
                for (int mt = 0; mt < 2; ++mt) {
                    mma16816(acc[mt][2 * bp],     ah[mt], bh[bp]);
                    mma16816(acc[mt][2 * bp + 1], ah[mt], bh[bp] + 2);
                }
            #pragma unroll
            for (int bp = 0; bp < NB; ++bp)
                #pragma unroll
                for (int mt = 0; mt < 2; ++mt) {
                    mma16816(acc[mt][2 * bp],     al[mt], bh[bp]);
                    mma16816(acc[mt][2 * bp + 1], al[mt], bh[bp] + 2);
                }
            #pragma unroll
            for (int bp = 0; bp < NB; ++bp)
                #pragma unroll
                for (int mt = 0; mt < 2; ++mt) {
                    mma16816(acc[mt][2 * bp],     ah[mt], bl[bp]);
                    mma16816(acc[mt][2 * bp + 1], ah[mt], bl[bp] + 2);
                }
            if (ki == 0 && c + 2 < nc) stage(c + 2, (c + 2) % 3);
        }
        // single barrier per chunk: publish chunk c+1, protect buffer (c+2)%3
        if (c + 2 < nc)      { CPWAIT1(); __syncthreads(); }
        else if (c + 1 < nc) { CPWAIT0(); __syncthreads(); }
    }

    // epilogue
    const int g = lane >> 2, tg = lane & 3;
    #pragma unroll
    for (int mt = 0; mt < 2; ++mt) {
        #pragma unroll
        for (int hf = 0; hf < 2; ++hf) {
            int m = m0 + wm + mt * 16 + g + hf * 8;
            float bm = (flags & FBM) ? bias[m] : 0.f;
            long long rbase = (long long)m * ldo;
            #pragma unroll
            for (int nt = 0; nt < NTW; ++nt) {
                int n = n0 + wn + nt * 8 + tg * 2;
                float v0 = alpha * acc[mt][nt][hf * 2 + 0];
                float v1 = alpha * acc[mt][nt][hf * 2 + 1];
                if (flags & FBN) { v0 += bias[n]; v1 += bias[n + 1]; }
                else if (flags & FBM) { v0 += bm; v1 += bm; }
                if (flags & FGELU) {
                    v0 = 0.5f * v0 * (1.f + erff(v0 * 0.70710678118654752f));
                    v1 = 0.5f * v1 * (1.f + erff(v1 * 0.70710678118654752f));
                }
                if (flags & FADD) { v0 += out[rbase + n]; v1 += out[rbase + n + 1]; }
                if (flags & (FOUT | FADD)) { out[rbase + n] = v0; out[rbase + n + 1] = v1; }
                if (flags & FSPL) {
                    u16 h0, l0, h1, l1;
                    splitf(v0, h0, l0);
                    splitf(v1, h1, l1);
                    oh[rbase + n] = h0; ol[rbase + n] = l0;
                    oh[rbase + n + 1] = h1; ol[rbase + n + 1] = l1;
                }
            }
        }
    }
}

// ---------------- reductions ----------------
__device__ __forceinline__ float blockReduceSum(float v) {
    __shared__ float sm[32];
    int lane = threadIdx.x & 31, wid = threadIdx.x >> 5;
    #pragma unroll
    for (int o = 16; o; o >>= 1) v += __shfl_xor_sync(0xffffffffu, v, o);
    if (lane == 0) sm[wid] = v;
    __syncthreads();
    if (wid == 0) {
        int nw = (blockDim.x + 31) >> 5;
        v = (lane < nw) ? sm[lane] : 0.f;
        #pragma unroll
        for (int o = 16; o; o >>= 1) v += __shfl_xor_sync(0xffffffffu, v, o);
        if (lane == 0) sm[0] = v;
    }
    __syncthreads();
    float r = sm[0];
    __syncthreads();
    return r;
}
__device__ __forceinline__ float blockReduceMax(float v) {
    __shared__ float sm[32];
    int lane = threadIdx.x & 31, wid = threadIdx.x >> 5;
    #pragma unroll
    for (int o = 16; o; o >>= 1) v = fmaxf(v, __shfl_xor_sync(0xffffffffu, v, o));
    if (lane == 0) sm[wid] = v;
    __syncthreads();
    if (wid == 0) {
        int nw = (blockDim.x + 31) >> 5;
        v = (lane < nw) ? sm[lane] : -INFINITY;
        #pragma unroll
        for (int o = 16; o; o >>= 1) v = fmaxf(v, __shfl_xor_sync(0xffffffffu, v, o));
        if (lane == 0) sm[0] = v;
    }
    __syncthreads();
    float r = sm[0];
    __syncthreads();
    return r;
}

// groupnorm: writes split output TRANSPOSED: gnT[b][t][c]
__global__ void groupnorm_kernel(const float* __restrict__ x, const float* __restrict__ sc,
                                 const float* __restrict__ bi,
                                 u16* __restrict__ oh, u16* __restrict__ ol) {
    const int CPG = Cc / 32;
    int b = blockIdx.x >> 5, g = blockIdx.x & 31;
    const long long base = ((long long)b * Cc + (long long)g * CPG) * Tt;
    const float* xp = x + base;
    const int n = CPG * Tt;
    float s = 0.f, ss = 0.f;
    for (int i = threadIdx.x; i < n; i += blockDim.x) {
        float v = xp[i]; s += v; ss = fmaf(v, v, ss);
    }
    s = blockReduceSum(s); ss = blockReduceSum(ss);
    float mean = s / n;
    float inv = rsqrtf(ss / n - mean * mean + 1e-6f);
    const long long obase = (long long)b * Tt * Cc + g * CPG;
    for (int j = threadIdx.x; j < n; j += blockDim.x) {
        int t = j / CPG, cc2 = j - t * CPG;
        float v = (xp[(long long)cc2 * Tt + t] - mean) * inv * sc[g * CPG + cc2] + bi[g * CPG + cc2];
        u16 hv, lv; splitf(v, hv, lv);
        long long o = obase + (long long)t * Cc + cc2;
        oh[o] = hv; ol[o] = lv;
    }
}

__global__ void layernorm_kernel(const float* __restrict__ x, const float* __restrict__ sc,
                                 const float* __restrict__ bi,
                                 u16* __restrict__ oh, u16* __restrict__ ol) {
    const long long rb = (long long)blockIdx.x * Ii;
    const float* row = x + rb;
    float s = 0.f, ss = 0.f;
    for (int i = threadIdx.x; i < Ii; i += blockDim.x) {
        float v = row[i]; s += v; ss = fmaf(v, v, ss);
    }
    s = blockReduceSum(s); ss = blockReduceSum(ss);
    float mean = s / (float)Ii;
    float inv = rsqrtf(ss / (float)Ii - mean * mean + 1e-5f);
    for (int i = threadIdx.x; i < Ii; i += blockDim.x) {
        float v = (row[i] - mean) * inv * sc[i] + bi[i];
        u16 hv, lv; splitf(v, hv, lv);
        oh[rb + i] = hv; ol[rb + i] = lv;
    }
}

// small fp32 gemm for tiny cross-attn K/V projections (M=32)
__global__ void __launch_bounds__(256) gemm_kernel(
    const float* __restrict__ A, const float* __restrict__ B, float* __restrict__ Cp,
    int M, int N, int K, int lda, int ldb, int ldc)
{
    __shared__ float As[16][65];
    __shared__ float Bs[16][65];
    int n0 = blockIdx.x * 64, m0 = blockIdx.y * 64;
    int tid = threadIdx.x;
    int tx = tid & 15, ty = tid >> 4;
    float acc[4][4] = {};
    for (int k0 = 0; k0 < K; k0 += 16) {
        #pragma unroll
        for (int u = 0; u < 4; ++u) {
            int i = tid + u * 256;
            int mm = i >> 4, kk = i & 15;
            int m = m0 + mm, k = k0 + kk;
            As[kk][mm] = (m < M && k < K) ? A[(long long)m * lda + k] : 0.f;
        }
        #pragma unroll
        for (int u = 0; u < 4; ++u) {
            int i = tid + u * 256;
            int kk = i >> 6, nn = i & 63;
            int k = k0 + kk, n = n0 + nn;
            Bs[kk][nn] = (k < K && n < N) ? B[(long long)k * ldb + n] : 0.f;
        }
        __syncthreads();
        #pragma unroll
        for (int kk = 0; kk < 16; ++kk) {
            float a[4], bb[4];
            #pragma unroll
            for (int i = 0; i < 4; ++i) a[i] = As[kk][ty * 4 + i];
            #pragma unroll
            for (int j = 0; j < 4; ++j) bb[j] = Bs[kk][tx * 4 + j];
            #pragma unroll
            for (int i = 0; i < 4; ++i)
                #pragma unroll
                for (int j = 0; j < 4; ++j)
                    acc[i][j] = fmaf(a[i], bb[j], acc[i][j]);
        }
        __syncthreads();
    }
    #pragma unroll
    for (int i = 0; i < 4; ++i) {
        int m = m0 + ty * 4 + i;
        if (m >= M) continue;
        #pragma unroll
        for (int j = 0; j < 4; ++j) {
            int n = n0 + tx * 4 + j;
            if (n < N) Cp[(long long)m * ldc + n] = acc[i][j];
        }
    }
}

__global__ void softmax_kernel(const float* __restrict__ s,
                               u16* __restrict__ oh, u16* __restrict__ ol) {
    const long long rb = (long long)blockIdx.x * Tt;
    const float* row = s + rb;
    int tid = threadIdx.x;
    float v[8];
    float mx = -INFINITY;
    #pragma unroll
    for (int i = 0; i < 8; ++i) { v[i] = row[tid + (i << 8)]; mx = fmaxf(mx, v[i]); }
    mx = blockReduceMax(mx);
    float sum = 0.f;
    #pragma unroll
    for (int i = 0; i < 8; ++i) { v[i] = expf(v[i] - mx); sum += v[i]; }
    sum = blockReduceSum(sum);
    float inv = 1.f / sum;
    #pragma unroll
    for (int i = 0; i < 8; ++i) {
        u16 hv, lv; splitf(v[i] * inv, hv, lv);
        oh[rb + tid + (i << 8)] = hv;
        ol[rb + tid + (i << 8)] = lv;
    }
}

__global__ void crossattn_kernel(const float* __restrict__ q, const float* __restrict__ kc,
                                 const float* __restrict__ vc,
                                 u16* __restrict__ oh, u16* __restrict__ ol) {
    int gw = blockIdx.x * (blockDim.x >> 5) + (threadIdx.x >> 5);
    int lane = threadIdx.x & 31;
    int t = gw % Tt;
    int rem = gw / Tt;
    int h = rem % Hh;
    int b = rem / Hh;
    const float* qp = q + ((long long)(b * Tt + t)) * Ii + h * Dh;
    const float* kb = kc + (long long)b * Ss * Ii + h * Dh;
    const float* vb = vc + (long long)b * Ss * Ii + h * Dh;
    float sj = -INFINITY;
    if (lane < Ss) {
        const float* kp = kb + lane * Ii;
        float acc = 0.f;
        #pragma unroll
        for (int d2 = 0; d2 < Dh; ++d2) acc = fmaf(qp[d2], kp[d2], acc);
        sj = acc * 0.125f;
    }
    float mx = sj;
    #pragma unroll
    for (int o = 16; o; o >>= 1) mx = fmaxf(mx, __shfl_xor_sync(0xffffffffu, mx, o));
    float p = (lane < Ss) ? expf(sj - mx) : 0.f;
    float sum = p;
    #pragma unroll
    for (int o = 16; o; o >>= 1) sum += __shfl_xor_sync(0xffffffffu, sum, o);
    p /= sum;
    float o0 = 0.f, o1 = 0.f;
    #pragma unroll
    for (int j = 0; j < Ss; ++j) {
        float pj = __shfl_sync(0xffffffffu, p, j);
        const float* vp = vb + j * Ii;
        o0 = fmaf(pj, vp[lane], o0);
        o1 = fmaf(pj, vp[lane + 32], o1);
    }
    long long ob = ((long long)(b * Tt + t)) * Ii + h * Dh;
    u16 hv, lv;
    splitf(o0, hv, lv); oh[ob + lane] = hv; ol[ob + lane] = lv;
    splitf(o1, hv, lv); oh[ob + lane + 32] = hv; ol[ob + lane + 32] = lv;
}

// per-head transpose of split V (src row stride ld, col offset off)
__global__ void transposeV_kernel(const u16* __restrict__ vh, const u16* __restrict__ vl,
                                  u16* __restrict__ oth, u16* __restrict__ otl,
                                  int ld, int off) {
    __shared__ u16 th[32][33], tl[32][33];
    int bh = blockIdx.z;
    int b = bh / Hh, h = bh % Hh;
    int t0 = blockIdx.x * 32, d0 = blockIdx.y * 32;
    #pragma unroll
    for (int i = 0; i < 32; i += 8) {
        long long src = ((long long)(b * Tt + t0 + threadIdx.y + i)) * ld + off + h * Dh + d0 + threadIdx.x;
        th[threadIdx.y + i][threadIdx.x] = vh[src];
        tl[threadIdx.y + i][threadIdx.x] = vl[src];
    }
    __syncthreads();
    #pragma unroll
    for (int i = 0; i < 32; i += 8) {
        long long dst = ((long long)((b * Hh + h) * Dh + d0 + threadIdx.y + i)) * Tt + t0 + threadIdx.x;
        oth[dst] = th[threadIdx.x][threadIdx.y + i];
        otl[dst] = tl[threadIdx.x][threadIdx.y + i];
    }
}

// elementwise split fp32 -> bf16 hi/lo
__global__ void split_ew(const float* __restrict__ w, u16* __restrict__ oh,
                         u16* __restrict__ ol, long long n) {
    long long i = (long long)blockIdx.x * 256 + threadIdx.x;
    if (i >= n) return;
    u16 hv, lv; splitf(w[i], hv, lv);
    oh[i] = hv; ol[i] = lv;
}

// transpose 768x768 [K][N] -> [N][K] + split
__global__ void splitT768(const float* __restrict__ w, u16* __restrict__ oh,
                          u16* __restrict__ ol) {
    __shared__ float t[32][33];
    int k0 = blockIdx.y * 32, n0 = blockIdx.x * 32;
    #pragma unroll
    for (int i = 0; i < 32; i += 8)
        t[threadIdx.y + i][threadIdx.x] = w[(long long)(k0 + threadIdx.y + i) * Ii + n0 + threadIdx.x];
    __syncthreads();
    #pragma unroll
    for (int i = 0; i < 32; i += 8) {
        long long o = (long long)(n0 + threadIdx.y + i) * Ii + k0 + threadIdx.x;
        u16 hv, lv; splitf(t[threadIdx.x][threadIdx.y + i], hv, lv);
        oh[o] = hv; ol[o] = lv;
    }
}

// conv weight reorder+split: out[o][k*Cin+c] = in[o][c*Ksz+k]
__global__ void reorder_split(const float* __restrict__ w, u16* __restrict__ oh,
                              u16* __restrict__ ol, long long total, int Cin) {
    long long i = (long long)blockIdx.x * 256 + threadIdx.x;
    if (i >= total) return;
    int rk = Cin * Ksz;
    long long oc = i / rk;
    int r = (int)(i - oc * rk);
    int k = r / Cin, c = r - k * Cin;
    u16 hv, lv; splitf(w[oc * rk + (long long)c * Ksz + k], hv, lv);
    oh[i] = hv; ol[i] = lv;
}

// ---------------- host wrapper ----------------
static void tc(const u16* Ah, const u16* Al, const u16* Bh, const u16* Bl,
               const float* bias, float* out, u16* oh, u16* ol,
               int gx, int gy, int gz, int K, int lda, int ldb, long long ldo,
               int ntile, int flags, float alpha, long long offA, long long flimA,
               int b2, long long sA1, long long sA2, long long sB1, long long sB2,
               long long sC1, long long sC2)
{
    dim3 g(gx, gy, gz);
    if (ntile == 64)
        tc_gemm<64><<<g, NTHREADS, TC_SMEM>>>(Ah, Al, Bh, Bl, bias, out, oh, ol, K, lda, ldb,
            ldo, flags, alpha, offA, flimA, b2, sA1, sA2, sB1, sB2, sC1, sC2);
    else
        tc_gemm<128><<<g, NTHREADS, TC_SMEM>>>(Ah, Al, Bh, Bl, bias, out, oh, ol, K, lda, ldb,
            ldo, flags, alpha, offA, flimA, b2, sA1, sA2, sB1, sB2, sC1, sC2);
}

extern "C" void kernel_launch(void* const* d_in, const int* in_sizes, int n_in,
                              void* d_out, int out_size) {
    const float* x      = (const float*)d_in[0];
    const float* ctx    = (const float*)d_in[1];
    const float* gn_s   = (const float*)d_in[2];
    const float* gn_b   = (const float*)d_in[3];
    const float* pin_w  = (const float*)d_in[4];
    const float* pin_b  = (const float*)d_in[5];
    const float* n1_s   = (const float*)d_in[6];
    const float* n1_b   = (const float*)d_in[7];
    const float* a1_wq  = (const float*)d_in[8];
    const float* a1_wk  = (const float*)d_in[9];
    const float* a1_wv  = (const float*)d_in[10];
    const float* a1_wo  = (const float*)d_in[11];
    const float* a1_bo  = (const float*)d_in[12];
    const float* n2_s   = (const float*)d_in[13];
    const float* n2_b   = (const float*)d_in[14];
    const float* a2_wq  = (const float*)d_in[15];
    const float* a2_wk  = (const float*)d_in[16];
    const float* a2_wv  = (const float*)d_in[17];
    const float* a2_wo  = (const float*)d_in[18];
    const float* a2_bo  = (const float*)d_in[19];
    const float* n3_s   = (const float*)d_in[20];
    const float* n3_b   = (const float*)d_in[21];
    const float* ff1_w  = (const float*)d_in[22];
    const float* ff1_b  = (const float*)d_in[23];
    const float* ff2_w  = (const float*)d_in[24];
    const float* ff2_b  = (const float*)d_in[25];
    const float* pout_w = (const float*)d_in[26];
    const float* pout_b = (const float*)d_in[27];
    float* out = (float*)d_out;

    cudaFuncSetAttribute(tc_gemm<128>, cudaFuncAttributeMaxDynamicSharedMemorySize, TC_SMEM);
    cudaFuncSetAttribute(tc_gemm<64>,  cudaFuncAttributeMaxDynamicSharedMemorySize, TC_SMEM);

    float *h, *q, *sc, *kcb, *vcb;
    u16 *gnh, *gnl, *yh, *yl, *qkvh, *qkvl, *vth_, *vtl_, *ath, *atl;
    u16 *hh, *hl, *ph, *pl, *ffh, *ffl, *w1h, *w1l, *w2h, *w2l, *wth, *wtl;
    cudaGetSymbolAddress((void**)&h,   g_h);
    cudaGetSymbolAddress((void**)&q,   g_q);
    cudaGetSymbolAddress((void**)&sc,  g_sc);
    cudaGetSymbolAddress((void**)&kcb, g_kc);
    cudaGetSymbolAddress((void**)&vcb, g_vc);
    cudaGetSymbolAddress((void**)&gnh, g_gnh); cudaGetSymbolAddress((void**)&gnl, g_gnl);
    cudaGetSymbolAddress((void**)&yh,  g_yh);  cudaGetSymbolAddress((void**)&yl,  g_yl);
    cudaGetSymbolAddress((void**)&qkvh, g_qkvh); cudaGetSymbolAddress((void**)&qkvl, g_qkvl);
    cudaGetSymbolAddress((void**)&vth_, g_vth); cudaGetSymbolAddress((void**)&vtl_, g_vtl);
    cudaGetSymbolAddress((void**)&ath, g_ath); cudaGetSymbolAddress((void**)&atl, g_atl);
    cudaGetSymbolAddress((void**)&hh,  g_hh);  cudaGetSymbolAddress((void**)&hl,  g_hl);
    cudaGetSymbolAddress((void**)&ph,  g_ph);  cudaGetSymbolAddress((void**)&pl,  g_pl);
    cudaGetSymbolAddress((void**)&ffh, g_ffh); cudaGetSymbolAddress((void**)&ffl, g_ffl);
    cudaGetSymbolAddress((void**)&w1h, g_w1h); cudaGetSymbolAddress((void**)&w1l, g_w1l);
    cudaGetSymbolAddress((void**)&w2h, g_w2h); cudaGetSymbolAddress((void**)&w2l, g_w2l);
    cudaGetSymbolAddress((void**)&wth, g_wth); cudaGetSymbolAddress((void**)&wtl, g_wtl);

    const long long BIG = 1LL << 62;
    const long long TI = (long long)Tt * Ii;
    const long long T3I = (long long)Tt * 3 * Ii;
    const long long WSZ = (long long)Ii * Ii;
    const unsigned WB = (unsigned)((WSZ + 255) / 256);

    split_ew<<<WB, 256>>>(pin_w,  wth + 6 * WSZ, wtl + 6 * WSZ, WSZ);
    split_ew<<<WB, 256>>>(pout_w, wth + 7 * WSZ, wtl + 7 * WSZ, WSZ);

    groupnorm_kernel<<<Bb * 32, 256>>>(x, gn_s, gn_b, gnh, gnl);  // writes gnT [b][t][c]

    // proj_in: h[b,t,:] = pin_w . gnT[b,t,:] + pin_b  (A now non-trans, cp.async)
    tc(gnh, gnl, wth + 6 * WSZ, wtl + 6 * WSZ, pin_b, h, 0, 0,
       Ii / 128, Tt / 128, Bb, Cc, Cc, Cc, Ii, 128, FBN | FOUT, 1.f,
       0, BIG, 1, (long long)Tt * Cc, 0, 0, 0, TI, 0);

    for (int d = 0; d < Dd; ++d) {
        long long wofs = (long long)d * WSZ;
        dim3 tg(24, 24), tb(32, 8);
        splitT768<<<tg, tb>>>(a1_wq + wofs, wth + 0 * WSZ, wtl + 0 * WSZ);
        splitT768<<<tg, tb>>>(a1_wk + wofs, wth + 1 * WSZ, wtl + 1 * WSZ);
        splitT768<<<tg, tb>>>(a1_wv + wofs, wth + 2 * WSZ, wtl + 2 * WSZ);
        splitT768<<<tg, tb>>>(a1_wo + wofs, wth + 3 * WSZ, wtl + 3 * WSZ);
        splitT768<<<tg, tb>>>(a2_wq + wofs, wth + 4 * WSZ, wtl + 4 * WSZ);
        splitT768<<<tg, tb>>>(a2_wo + wofs, wth + 5 * WSZ, wtl + 5 * WSZ);
        {
            long long t1 = (long long)Fi * Ii * Ksz;
            reorder_split<<<(unsigned)((t1 + 255) / 256), 256>>>(ff1_w + d * t1, w1h, w1l, t1, Ii);
            long long t2 = (long long)Ii * Fi * Ksz;
            reorder_split<<<(unsigned)((t2 + 255) / 256), 256>>>(ff2_w + d * t2, w2h, w2l, t2, Fi);
        }

        // --- self attention ---
        layernorm_kernel<<<Bb * Tt, 256>>>(h, n1_s + d * Ii, n1_b + d * Ii, yh, yl);
        // fused QKV
        tc(yh, yl, wth, wtl, 0, sc, qkvh, qkvl, (3 * Ii) / 128, (Bb * Tt) / 128, 1,
           Ii, Ii, Ii, 3 * Ii, 128, FSPL, 1.f, 0, BIG, 1, 0, 0, 0, 0, 0, 0);
        {
            dim3 g(Tt / 32, Dh / 32, Bb * Hh);
            transposeV_kernel<<<g, dim3(32, 8)>>>(qkvh, qkvl, vth_, vtl_, 3 * Ii, 2 * Ii);
        }
        // scores = 0.125 q k^T per (b,h)
        tc(qkvh, qkvl, qkvh + Ii, qkvl + Ii, 0, sc, 0, 0,
           Tt / 128, Tt / 128, Bb * Hh, Dh, 3 * Ii, 3 * Ii, Tt, 128,
           FOUT, 0.125f, 0, BIG, Hh, T3I, Dh, T3I, Dh,
           (long long)Hh * Tt * Tt, (long long)Tt * Tt);
        softmax_kernel<<<Bb * Hh * Tt, 256>>>(sc, ph, pl);
        // att = P @ V per (b,h)
        tc(ph, pl, vth_, vtl_, 0, sc, ath, atl, 1, Tt / 128, Bb * Hh, Tt, Tt, Tt, Ii, 64,
           FSPL, 1.f, 0, BIG, Hh,
           (long long)Hh * Tt * Tt, (long long)Tt * Tt,
           (long long)Hh * Dh * Tt, (long long)Dh * Tt, TI, Dh);
        // h += att @ wo + bo
        tc(ath, atl, wth + 3 * WSZ, wtl + 3 * WSZ, a1_bo + d * Ii, h, 0, 0,
           Ii / 128, (Bb * Tt) / 128, 1, Ii, Ii, Ii, Ii, 128,
           FBN | FADD, 1.f, 0, BIG, 1, 0, 0, 0, 0, 0, 0);

        // --- cross attention ---
        layernorm_kernel<<<Bb * Tt, 256>>>(h, n2_s + d * Ii, n2_b + d * Ii, yh, yl);
        tc(yh, yl, wth + 4 * WSZ, wtl + 4 * WSZ, 0, q, 0, 0, Ii / 128, (Bb * Tt) / 128, 1,
           Ii, Ii, Ii, Ii, 128, FOUT, 1.f, 0, BIG, 1, 0, 0, 0, 0, 0, 0);
        {
            dim3 g((Ii + 63) / 64, (Bb * Ss + 63) / 64);
            gemm_kernel<<<g, 256>>>(ctx, a2_wk + (long long)d * Cx * Ii, kcb,
                                    Bb * Ss, Ii, Cx, Cx, Ii, Ii);
            gemm_kernel<<<g, 256>>>(ctx, a2_wv + (long long)d * Cx * Ii, vcb,
                                    Bb * Ss, Ii, Cx, Cx, Ii, Ii);
        }
        crossattn_kernel<<<Bb * Hh * Tt / 8, 256>>>(q, kcb, vcb, ath, atl);
        tc(ath, atl, wth + 5 * WSZ, wtl + 5 * WSZ, a2_bo + d * Ii, h, 0, 0,
           Ii / 128, (Bb * Tt) / 128, 1, Ii, Ii, Ii, Ii, 128,
           FBN | FADD, 1.f, 0, BIG, 1, 0, 0, 0, 0, 0, 0);

        // --- feed-forward ---
        layernorm_kernel<<<Bb * Tt, 256>>>(h, n3_s + d * Ii, n3_b + d * Ii, yh, yl);
        tc(yh, yl, w1h, w1l, ff1_b + d * Fi, sc, ffh, ffl, Fi / 128, Tt / 128, Bb,
           Ii * Ksz, Ii, Ii * Ksz, Fi, 128, FBN | FGELU | FSPL, 1.f,
           -(long long)4 * Ii, TI, 1, TI, 0, 0, 0, (long long)Tt * Fi, 0);
        tc(ffh, ffl, w2h, w2l, ff2_b + d * Ii, h, hh, hl, Ii / 128, Tt / 128, Bb,
           Fi * Ksz, Fi, Fi * Ksz, Ii, 128,
           FBN | FADD | (d == Dd - 1 ? FSPL : 0), 1.f,
           -(long long)4 * Fi, (long long)Tt * Fi, 1,
           (long long)Tt * Fi, 0, 0, 0, TI, 0);
    }

    // out = x + pout_w @ h^T + pout_b
    cudaMemcpyAsync(out, x, (size_t)Bb * Cc * Tt * sizeof(float),
                    cudaMemcpyDeviceToDevice);
    tc(wth + 7 * WSZ, wtl + 7 * WSZ, hh, hl, pout_b, out, 0, 0,
       Tt / 128, Cc / 128, Bb, Ii, Ii, Ii, Tt, 128, FBM | FADD, 1.f,
       0, BIG, 1, 0, 0, TI, 0, (long long)Cc * Tt, 0);
}

// round 12
// speedup vs baseline: 3.0347x; 1.0146x over previous
#include <cuda_runtime.h>
#include <cuda_bf16.h>
#include <math.h>
#include <stdint.h>

#define Bb 2
#define Cc 768
#define Tt 2048
#define Ii 768
#define Hh 12
#define Dh 64
#define Ss 16
#define Cx 512
#define Fi 3072
#define Dd 2
#define Ksz 9

typedef __nv_bfloat16 bf16;
typedef unsigned short u16;

// ---------------- scratch ----------------
__device__ float g_h  [(long long)Bb*Tt*Ii];
__device__ float g_q  [(long long)Bb*Tt*Ii];
__device__ float g_sc [(long long)Bb*Hh*Tt*Tt];
__device__ float g_kc [(long long)Bb*Ss*Ii];
__device__ float g_vc [(long long)Bb*Ss*Ii];

__device__ u16 g_gnh[(long long)Bb*Cc*Tt], g_gnl[(long long)Bb*Cc*Tt];  // TRANSPOSED [b][t][c]
__device__ u16 g_yh [(long long)Bb*Tt*Ii], g_yl [(long long)Bb*Tt*Ii];
__device__ u16 g_qkvh[(long long)Bb*Tt*3*Ii], g_qkvl[(long long)Bb*Tt*3*Ii];
__device__ u16 g_vth[(long long)Bb*Ii*Tt], g_vtl[(long long)Bb*Ii*Tt];
__device__ u16 g_ath[(long long)Bb*Tt*Ii], g_atl[(long long)Bb*Tt*Ii];
__device__ u16 g_hh [(long long)Bb*Tt*Ii], g_hl [(long long)Bb*Tt*Ii];
__device__ u16 g_ph [(long long)Bb*Hh*Tt*Tt], g_pl [(long long)Bb*Hh*Tt*Tt];
__device__ u16 g_ffh[(long long)Bb*Tt*Fi], g_ffl[(long long)Bb*Tt*Fi];
__device__ u16 g_w1h[(long long)Fi*Ii*Ksz], g_w1l[(long long)Fi*Ii*Ksz];
__device__ u16 g_w2h[(long long)Ii*Fi*Ksz], g_w2l[(long long)Ii*Fi*Ksz];
__device__ u16 g_wth[8ll*Ii*Ii], g_wtl[8ll*Ii*Ii];

// ---------------- helpers ----------------
__device__ __forceinline__ uint32_t smem_u32(const void* p) {
    uint32_t a;
    asm("{ .reg .u64 t; cvta.to.shared.u64 t, %1; cvt.u32.u64 %0, t; }" : "=r"(a) : "l"(p));
    return a;
}
#define SWZ(x) ((x) ^ ((((uint32_t)(x)) >> 3) & 0x70))
#define CP16(dst, src) asm volatile("cp.async.cg.shared.global [%0], [%1], 16;" :: "r"(dst), "l"(src))
#define CPCOMMIT() asm volatile("cp.async.commit_group;" ::: "memory")
#define CPWAIT1() asm volatile("cp.async.wait_group 1;" ::: "memory")
#define CPWAIT0() asm volatile("cp.async.wait_group 0;" ::: "memory")

__device__ __forceinline__ void ldsm4(uint32_t* r, uint32_t addr) {
    asm volatile("ldmatrix.sync.aligned.m8n8.x4.shared.b16 {%0,%1,%2,%3}, [%4];"
        : "=r"(r[0]), "=r"(r[1]), "=r"(r[2]), "=r"(r[3]) : "r"(addr));
}
__device__ __forceinline__ void mma16816(float* c, const uint32_t* a, const uint32_t* b) {
    asm volatile("mma.sync.aligned.m16n8k16.row.col.f32.bf16.bf16.f32 "
        "{%0,%1,%2,%3}, {%4,%5,%6,%7}, {%8,%9}, {%0,%1,%2,%3};"
        : "+f"(c[0]), "+f"(c[1]), "+f"(c[2]), "+f"(c[3])
        : "r"(a[0]), "r"(a[1]), "r"(a[2]), "r"(a[3]), "r"(b[0]), "r"(b[1]));
}
__device__ __forceinline__ void splitf(float x, u16& h, u16& l) {
    bf16 hb = __float2bfloat16(x);
    bf16 lb = __float2bfloat16(x - __bfloat162float(hb));
    h = __bfloat16_as_ushort(hb);
    l = __bfloat16_as_ushort(lb);
}

// flags
#define FTA   1
#define FTB   2
#define FBN   4
#define FBM   8
#define FGELU 16
#define FADD  32
#define FOUT  64
#define FSPL  128

#define TC_SMEM (3*65536 + 1024)
#define NTHREADS 512

// stage 16B segments via cp.async (non-trans): op[r][k] = G[off0 + r*ld + k]
__device__ __forceinline__ void stage_nt(const u16* __restrict__ Gh, const u16* __restrict__ Gl,
        long long off0, long long flim, int ld, int k0, int rows,
        uint32_t smh, uint32_t sml) {
    int nseg = rows * 8;
    for (int idx = threadIdx.x; idx < nseg; idx += NTHREADS) {
        int r = idx >> 3, s = idx & 7;
        long long f = off0 + (long long)r * ld + k0 + s * 8;
        uint32_t d = SWZ((uint32_t)(r * 128 + s * 16));
        if (f >= 0 && f + 8 <= flim) {
            CP16(smh + d, Gh + f);
            CP16(sml + d, Gl + f);
        } else {
            asm volatile("st.shared.v4.u32 [%0], {%1,%1,%1,%1};" :: "r"(smh + d), "r"(0));
            asm volatile("st.shared.v4.u32 [%0], {%1,%1,%1,%1};" :: "r"(sml + d), "r"(0));
        }
    }
}

// ===== tensor-core GEMM: 512 threads, 4x4 warp grid, 3-stage pipeline =====
template<int NT>
__global__ void __launch_bounds__(NTHREADS, 1)
tc_gemm(const u16* __restrict__ Ah, const u16* __restrict__ Al,
        const u16* __restrict__ Bh, const u16* __restrict__ Bl,
        const float* __restrict__ bias, float* __restrict__ out,
        u16* __restrict__ oh, u16* __restrict__ ol,
        int K, int lda, int ldb, long long ldo, int flags, float alpha,
        long long offA, long long flimA, int b2,
        long long sA1, long long sA2, long long sB1, long long sB2,
        long long sC1, long long sC2)
{
    extern __shared__ char dynsm[];
    long long z1 = blockIdx.z / b2, z2 = blockIdx.z % b2;
    Ah += z1 * sA1 + z2 * sA2;  Al += z1 * sA1 + z2 * sA2;
    Bh += z1 * sB1 + z2 * sB2;  Bl += z1 * sB1 + z2 * sB2;
    long long zc = z1 * sC1 + z2 * sC2;
    out += zc;
    if (flags & FSPL) { oh += zc; ol += zc; }

    const int tid = threadIdx.x;
    const int lane = tid & 31;
    const int wid = tid >> 5;                 // 0..15
    const int wm = (wid & 3) * 32;            // 4 M-warps * 32 rows
    constexpr int WN = NT / 4;                // warp N extent (32 or 16)
    const int wn = (wid >> 2) * WN;           // 4 N-warps
    const int ksrot = (wid >> 2) & 3;         // phase stagger per SMSP
    const int m0 = blockIdx.y * 128;
    const int n0 = blockIdx.x * NT;
    constexpr int NTW = WN / 8;               // n8 tiles per warp (4 or 2)
    constexpr int NB = NTW / 2;               // 16-col pairs (2 or 1)
    constexpr int ASZ = 32768;                // A hi+lo bytes
    constexpr int BSZ = NT * 128 * 2;         // B hi+lo bytes
    constexpr int STG = ASZ + BSZ;

    uint32_t smBase = smem_u32(dynsm);
    smBase = (smBase + 1023) & ~1023u;

    const long long aoff = offA + (long long)m0 * lda;
    const long long boff = (long long)n0 * ldb;
    const long long BIGL = 1LL << 62;
    const int nc = K / 64;

    float acc[2][NTW][4];
    #pragma unroll
    for (int i = 0; i < 2; ++i)
        #pragma unroll
        for (int j = 0; j < NTW; ++j)
            #pragma unroll
            for (int l = 0; l < 4; ++l) acc[i][j][l] = 0.f;

    const uint32_t aRow = wm + (lane & 15);
    const uint32_t aKof = (lane >> 4) << 3;
    const int bi = lane >> 3;
    const uint32_t bRowBase = wn + ((bi >> 1) << 3) + (lane & 7);
    const uint32_t bKof = (bi & 1) << 3;

    auto stage = [&](int c, int s) {
        uint32_t base = smBase + s * STG;
        stage_nt(Ah, Al, aoff, flimA, lda, c * 64, 128, base, base + 16384);
        stage_nt(Bh, Bl, boff, BIGL, ldb, c * 64, NT, base + ASZ, base + ASZ + BSZ / 2);
        CPCOMMIT();
    };

    // prologue: fill 2 stages, wait chunk 0, publish
    stage(0, 0);
    if (nc > 1) { stage(1, 1); CPWAIT1(); }
    else        { CPWAIT0(); }
    __syncthreads();

    for (int c = 0; c < nc; ++c) {
        int sb3 = c % 3;
        uint32_t base = smBase + sb3 * STG;
        const uint32_t aHi = base, aLo = base + 16384;
        const uint32_t bHi = base + ASZ, bLo = base + ASZ + BSZ / 2;
        #pragma unroll
        for (int ki = 0; ki < 4; ++ki) {
            const int ks = (ki + ksrot) & 3;
            const uint32_t kb = ks * 16;
            uint32_t ah[2][4], al[2][4], bh[NB][4], bl[NB][4];
            #pragma unroll
            for (int mt = 0; mt < 2; ++mt) {
                uint32_t off = SWZ((aRow + mt * 16) * 128 + (kb + aKof) * 2);
                ldsm4(ah[mt], aHi + off);
                ldsm4(al[mt], aLo + off);
            }
            #pragma unroll
            for (int bp = 0; bp < NB; ++bp) {
                uint32_t off = SWZ((bRowBase + bp * 16) * 128 + (kb + bKof) * 2);
                ldsm4(bh[bp], bHi + off);
                ldsm4(bl[bp], bLo + off);
            }
            #pragma unroll
            for (int bp = 0; bp < NB; ++bp)
                #pragma unroll
                for (int mt = 0; mt < 2; ++mt) {
                    mma16816(acc[mt][2 * bp],     ah[mt], bh[bp]);
                    mma16816(acc[mt][2 * bp + 1], ah[mt], bh[bp] + 2);
                }
            #pragma unroll
            for (int bp = 0; bp < NB; ++bp)
                #pragma unroll
                for (int mt = 0; mt < 2; ++mt) {
                    mma16816(acc[mt][2 * bp],     al[mt], bh[bp]);
                    mma16816(acc[mt][2 * bp + 1], al[mt], bh[bp] + 2);
                }
            #pragma unroll
            for (int bp = 0; bp < NB; ++bp)
                #pragma unroll
                for (int mt = 0; mt < 2; ++mt) {
                    mma16816(acc[mt][2 * bp],     ah[mt], bl[bp]);
                    mma16816(acc[mt][2 * bp + 1], ah[mt], bl[bp] + 2);
                }
            if (ki == 0 && c + 2 < nc) stage(c + 2, (c + 2) % 3);
        }
        // single barrier per chunk: publish chunk c+1, protect buffer (c+2)%3
        if (c + 2 < nc)      { CPWAIT1(); __syncthreads(); }
        else if (c + 1 < nc) { CPWAIT0(); __syncthreads(); }
    }

    // epilogue
    const int g = lane >> 2, tg = lane & 3;
    #pragma unroll
    for (int mt = 0; mt < 2; ++mt) {
        #pragma unroll
        for (int hf = 0; hf < 2; ++hf) {
            int m = m0 + wm + mt * 16 + g + hf * 8;
            float bm = (flags & FBM) ? bias[m] : 0.f;
            long long rbase = (long long)m * ldo;
            #pragma unroll
            for (int nt = 0; nt < NTW; ++nt) {
                int n = n0 + wn + nt * 8 + tg * 2;
                float v0 = alpha * acc[mt][nt][hf * 2 + 0];
                float v1 = alpha * acc[mt][nt][hf * 2 + 1];
                if (flags & FBN) { v0 += bias[n]; v1 += bias[n + 1]; }
                else if (flags & FBM) { v0 += bm; v1 += bm; }
                if (flags & FGELU) {
                    v0 = 0.5f * v0 * (1.f + erff(v0 * 0.70710678118654752f));
                    v1 = 0.5f * v1 * (1.f + erff(v1 * 0.70710678118654752f));
                }
                if (flags & FADD) { v0 += out[rbase + n]; v1 += out[rbase + n + 1]; }
                if (flags & (FOUT | FADD)) { out[rbase + n] = v0; out[rbase + n + 1] = v1; }
                if (flags & FSPL) {
                    u16 h0, l0, h1, l1;
                    splitf(v0, h0, l0);
                    splitf(v1, h1, l1);
                    oh[rbase + n] = h0; ol[rbase + n] = l0;
                    oh[rbase + n + 1] = h1; ol[rbase + n + 1] = l1;
                }
            }
        }
    }
}

// ---------------- reductions ----------------
__device__ __forceinline__ float blockReduceSum(float v) {
    __shared__ float sm[32];
    int lane = threadIdx.x & 31, wid = threadIdx.x >> 5;
    #pragma unroll
    for (int o = 16; o; o >>= 1) v += __shfl_xor_sync(0xffffffffu, v, o);
    if (lane == 0) sm[wid] = v;
    __syncthreads();
    if (wid == 0) {
        int nw = (blockDim.x + 31) >> 5;
        v = (lane < nw) ? sm[lane] : 0.f;
        #pragma unroll
        for (int o = 16; o; o >>= 1) v += __shfl_xor_sync(0xffffffffu, v, o);
        if (lane == 0) sm[0] = v;
    }
    __syncthreads();
    float r = sm[0];
    __syncthreads();
    return r;
}
__device__ __forceinline__ float blockReduceMax(float v) {
    __shared__ float sm[32];
    int lane = threadIdx.x & 31, wid = threadIdx.x >> 5;
    #pragma unroll
    for (int o = 16; o; o >>= 1) v = fmaxf(v, __shfl_xor_sync(0xffffffffu, v, o));
    if (lane == 0) sm[wid] = v;
    __syncthreads();
    if (wid == 0) {
        int nw = (blockDim.x + 31) >> 5;
        v = (lane < nw) ? sm[lane] : -INFINITY;
        #pragma unroll
        for (int o = 16; o; o >>= 1) v = fmaxf(v, __shfl_xor_sync(0xffffffffu, v, o));
        if (lane == 0) sm[0] = v;
    }
    __syncthreads();
    float r = sm[0];
    __syncthreads();
    return r;
}

// groupnorm: writes split output TRANSPOSED: gnT[b][t][c]
__global__ void groupnorm_kernel(const float* __restrict__ x, const float* __restrict__ sc,
                                 const float* __restrict__ bi,
                                 u16* __restrict__ oh, u16* __restrict__ ol) {
    const int CPG = Cc / 32;
    int b = blockIdx.x >> 5, g = blockIdx.x & 31;
    const long long base = ((long long)b * Cc + (long long)g * CPG) * Tt;
    const float* xp = x + base;
    const int n = CPG * Tt;
    float s = 0.f, ss = 0.f;
    for (int i = threadIdx.x; i < n; i += blockDim.x) {
        float v = xp[i]; s += v; ss = fmaf(v, v, ss);
    }
    s = blockReduceSum(s); ss = blockReduceSum(ss);
    float mean = s / n;
    float inv = rsqrtf(ss / n - mean * mean + 1e-6f);
    const long long obase = (long long)b * Tt * Cc + g * CPG;
    for (int j = threadIdx.x; j < n; j += blockDim.x) {
        int t = j / CPG, cc2 = j - t * CPG;
        float v = (xp[(long long)cc2 * Tt + t] - mean) * inv * sc[g * CPG + cc2] + bi[g * CPG + cc2];
        u16 hv, lv; splitf(v, hv, lv);
        long long o = obase + (long long)t * Cc + cc2;
        oh[o] = hv; ol[o] = lv;
    }
}

__global__ void layernorm_kernel(const float* __restrict__ x, const float* __restrict__ sc,
                                 const float* __restrict__ bi,
                                 u16* __restrict__ oh, u16* __restrict__ ol) {
    const long long rb = (long long)blockIdx.x * Ii;
    const float* row = x + rb;
    float s = 0.f, ss = 0.f;
    for (int i = threadIdx.x; i < Ii; i += blockDim.x) {
        float v = row[i]; s += v; ss = fmaf(v, v, ss);
    }
    s = blockReduceSum(s); ss = blockReduceSum(ss);
    float mean = s / (float)Ii;
    float inv = rsqrtf(ss / (float)Ii - mean * mean + 1e-5f);
    for (int i = threadIdx.x; i < Ii; i += blockDim.x) {
        float v = (row[i] - mean) * inv * sc[i] + bi[i];
        u16 hv, lv; splitf(v, hv, lv);
        oh[rb + i] = hv; ol[rb + i] = lv;
    }
}

// small fp32 gemm for tiny cross-attn K/V projections (M=32)
__global__ void __launch_bounds__(256) gemm_kernel(
    const float* __restrict__ A, const float* __restrict__ B, float* __restrict__ Cp,
    int M, int N, int K, int lda, int ldb, int ldc)
{
    __shared__ float As[16][65];
    __shared__ float Bs[16][65];
    int n0 = blockIdx.x * 64, m0 = blockIdx.y * 64;
    int tid = threadIdx.x;
    int tx = tid & 15, ty = tid >> 4;
    float acc[4][4] = {};
    for (int k0 = 0; k0 < K; k0 += 16) {
        #pragma unroll
        for (int u = 0; u < 4; ++u) {
            int i = tid + u * 256;
            int mm = i >> 4, kk = i & 15;
            int m = m0 + mm, k = k0 + kk;
            As[kk][mm] = (m < M && k < K) ? A[(long long)m * lda + k] : 0.f;
        }
        #pragma unroll
        for (int u = 0; u < 4; ++u) {
            int i = tid + u * 256;
            int kk = i >> 6, nn = i & 63;
            int k = k0 + kk, n = n0 + nn;
            Bs[kk][nn] = (k < K && n < N) ? B[(long long)k * ldb + n] : 0.f;
        }
        __syncthreads();
        #pragma unroll
        for (int kk = 0; kk < 16; ++kk) {
            float a[4], bb[4];
            #pragma unroll
            for (int i = 0; i < 4; ++i) a[i] = As[kk][ty * 4 + i];
            #pragma unroll
            for (int j = 0; j < 4; ++j) bb[j] = Bs[kk][tx * 4 + j];
            #pragma unroll
            for (int i = 0; i < 4; ++i)
                #pragma unroll
                for (int j = 0; j < 4; ++j)
                    acc[i][j] = fmaf(a[i], bb[j], acc[i][j]);
        }
        __syncthreads();
    }
    #pragma unroll
    for (int i = 0; i < 4; ++i) {
        int m = m0 + ty * 4 + i;
        if (m >= M) continue;
        #pragma unroll
        for (int j = 0; j < 4; ++j) {
            int n = n0 + tx * 4 + j;
            if (n < N) Cp[(long long)m * ldc + n] = acc[i][j];
        }
    }
}

__global__ void softmax_kernel(const float* __restrict__ s,
                               u16* __restrict__ oh, u16* __restrict__ ol) {
    const long long rb = (long long)blockIdx.x * Tt;
    const float* row = s + rb;
    int tid = threadIdx.x;
    float v[8];
    float mx = -INFINITY;
    #pragma unroll
    for (int i = 0; i < 8; ++i) { v[i] = row[tid + (i << 8)]; mx = fmaxf(mx, v[i]); }
    mx = blockReduceMax(mx);
    float sum = 0.f;
    #pragma unroll
    for (int i = 0; i < 8; ++i) { v[i] = expf(v[i] - mx); sum += v[i]; }
    sum = blockReduceSum(sum);
    float inv = 1.f / sum;
    #pragma unroll
    for (int i = 0; i < 8; ++i) {
        u16 hv, lv; splitf(v[i] * inv, hv, lv);
        oh[rb + tid + (i << 8)] = hv;
        ol[rb + tid + (i << 8)] = lv;
    }
}

__global__ void crossattn_kernel(const float* __restrict__ q, const float* __restrict__ kc,
                                 const float* __restrict__ vc,
                                 u16* __restrict__ oh, u16* __restrict__ ol) {
    int gw = blockIdx.x * (blockDim.x >> 5) + (threadIdx.x >> 5);
    int lane = threadIdx.x & 31;
    int t = gw % Tt;
    int rem = gw / Tt;
    int h = rem % Hh;
    int b = rem / Hh;
    const float* qp = q + ((long long)(b * Tt + t)) * Ii + h * Dh;
    const float* kb = kc + (long long)b * Ss * Ii + h * Dh;
    const float* vb = vc + (long long)b * Ss * Ii + h * Dh;
    float sj = -INFINITY;
    if (lane < Ss) {
        const float* kp = kb + lane * Ii;
        float acc = 0.f;
        #pragma unroll
        for (int d2 = 0; d2 < Dh; ++d2) acc = fmaf(qp[d2], kp[d2], acc);
        sj = acc * 0.125f;
    }
    float mx = sj;
    #pragma unroll
    for (int o = 16; o; o >>= 1) mx = fmaxf(mx, __shfl_xor_sync(0xffffffffu, mx, o));
    float p = (lane < Ss) ? expf(sj - mx) : 0.f;
    float sum = p;
    #pragma unroll
    for (int o = 16; o; o >>= 1) sum += __shfl_xor_sync(0xffffffffu, sum, o);
    p /= sum;
    float o0 = 0.f, o1 = 0.f;
    #pragma unroll
    for (int j = 0; j < Ss; ++j) {
        float pj = __shfl_sync(0xffffffffu, p, j);
        const float* vp = vb + j * Ii;
        o0 = fmaf(pj, vp[lane], o0);
        o1 = fmaf(pj, vp[lane + 32], o1);
    }
    long long ob = ((long long)(b * Tt + t)) * Ii + h * Dh;
    u16 hv, lv;
    splitf(o0, hv, lv); oh[ob + lane] = hv; ol[ob + lane] = lv;
    splitf(o1, hv, lv); oh[ob + lane + 32] = hv; ol[ob + lane + 32] = lv;
}

// per-head transpose of split V (src row stride ld, col offset off)
__global__ void transposeV_kernel(const u16* __restrict__ vh, const u16* __restrict__ vl,
                                  u16* __restrict__ oth, u16* __restrict__ otl,
                                  int ld, int off) {
    __shared__ u16 th[32][33], tl[32][33];
    int bh = blockIdx.z;
    int b = bh / Hh, h = bh % Hh;
    int t0 = blockIdx.x * 32, d0 = blockIdx.y * 32;
    #pragma unroll
    for (int i = 0; i < 32; i += 8) {
        long long src = ((long long)(b * Tt + t0 + threadIdx.y + i)) * ld + off + h * Dh + d0 + threadIdx.x;
        th[threadIdx.y + i][threadIdx.x] = vh[src];
        tl[threadIdx.y + i][threadIdx.x] = vl[src];
    }
    __syncthreads();
    #pragma unroll
    for (int i = 0; i < 32; i += 8) {
        long long dst = ((long long)((b * Hh + h) * Dh + d0 + threadIdx.y + i)) * Tt + t0 + threadIdx.x;
        oth[dst] = th[threadIdx.x][threadIdx.y + i];
        otl[dst] = tl[threadIdx.x][threadIdx.y + i];
    }
}

// elementwise split fp32 -> bf16 hi/lo
__global__ void split_ew(const float* __restrict__ w, u16* __restrict__ oh,
                         u16* __restrict__ ol, long long n) {
    long long i = (long long)blockIdx.x * 256 + threadIdx.x;
    if (i >= n) return;
    u16 hv, lv; splitf(w[i], hv, lv);
    oh[i] = hv; ol[i] = lv;
}

// transpose 768x768 [K][N] -> [N][K] + split
__global__ void splitT768(const float* __restrict__ w, u16* __restrict__ oh,
                          u16* __restrict__ ol) {
    __shared__ float t[32][33];
    int k0 = blockIdx.y * 32, n0 = blockIdx.x * 32;
    #pragma unroll
    for (int i = 0; i < 32; i += 8)
        t[threadIdx.y + i][threadIdx.x] = w[(long long)(k0 + threadIdx.y + i) * Ii + n0 + threadIdx.x];
    __syncthreads();
    #pragma unroll
    for (int i = 0; i < 32; i += 8) {
        long long o = (long long)(n0 + threadIdx.y + i) * Ii + k0 + threadIdx.x;
        u16 hv, lv; splitf(t[threadIdx.x][threadIdx.y + i], hv, lv);
        oh[o] = hv; ol[o] = lv;
    }
}

// conv weight reorder+split: out[o][k*Cin+c] = in[o][c*Ksz+k]
__global__ void reorder_split(const float* __restrict__ w, u16* __restrict__ oh,
                              u16* __restrict__ ol, long long total, int Cin) {
    long long i = (long long)blockIdx.x * 256 + threadIdx.x;
    if (i >= total) return;
    int rk = Cin * Ksz;
    long long oc = i / rk;
    int r = (int)(i - oc * rk);
    int k = r / Cin, c = r - k * Cin;
    u16 hv, lv; splitf(w[oc * rk + (long long)c * Ksz + k], hv, lv);
    oh[i] = hv; ol[i] = lv;
}

// ---------------- host wrapper ----------------
static void tc(const u16* Ah, const u16* Al, const u16* Bh, const u16* Bl,
               const float* bias, float* out, u16* oh, u16* ol,
               int gx, int gy, int gz, int K, int lda, int ldb, long long ldo,
               int ntile, int flags, float alpha, long long offA, long long flimA,
               int b2, long long sA1, long long sA2, long long sB1, long long sB2,
               long long sC1, long long sC2)
{
    dim3 g(gx, gy, gz);
    if (ntile == 64)
        tc_gemm<64><<<g, NTHREADS, TC_SMEM>>>(Ah, Al, Bh, Bl, bias, out, oh, ol, K, lda, ldb,
            ldo, flags, alpha, offA, flimA, b2, sA1, sA2, sB1, sB2, sC1, sC2);
    else
        tc_gemm<128><<<g, NTHREADS, TC_SMEM>>>(Ah, Al, Bh, Bl, bias, out, oh, ol, K, lda, ldb,
            ldo, flags, alpha, offA, flimA, b2, sA1, sA2, sB1, sB2, sC1, sC2);
}

extern "C" void kernel_launch(void* const* d_in, const int* in_sizes, int n_in,
                              void* d_out, int out_size) {
    const float* x      = (const float*)d_in[0];
    const float* ctx    = (const float*)d_in[1];
    const float* gn_s   = (const float*)d_in[2];
    const float* gn_b   = (const float*)d_in[3];
    const float* pin_w  = (const float*)d_in[4];
    const float* pin_b  = (const float*)d_in[5];
    const float* n1_s   = (const float*)d_in[6];
    const float* n1_b   = (const float*)d_in[7];
    const float* a1_wq  = (const float*)d_in[8];
    const float* a1_wk  = (const float*)d_in[9];
    const float* a1_wv  = (const float*)d_in[10];
    const float* a1_wo  = (const float*)d_in[11];
    const float* a1_bo  = (const float*)d_in[12];
    const float* n2_s   = (const float*)d_in[13];
    const float* n2_b   = (const float*)d_in[14];
    const float* a2_wq  = (const float*)d_in[15];
    const float* a2_wk  = (const float*)d_in[16];
    const float* a2_wv  = (const float*)d_in[17];
    const float* a2_wo  = (const float*)d_in[18];
    const float* a2_bo  = (const float*)d_in[19];
    const float* n3_s   = (const float*)d_in[20];
    const float* n3_b   = (const float*)d_in[21];
    const float* ff1_w  = (const float*)d_in[22];
    const float* ff1_b  = (const float*)d_in[23];
    const float* ff2_w  = (const float*)d_in[24];
    const float* ff2_b  = (const float*)d_in[25];
    const float* pout_w = (const float*)d_in[26];
    const float* pout_b = (const float*)d_in[27];
    float* out = (float*)d_out;

    cudaFuncSetAttribute(tc_gemm<128>, cudaFuncAttributeMaxDynamicSharedMemorySize, TC_SMEM);
    cudaFuncSetAttribute(tc_gemm<64>,  cudaFuncAttributeMaxDynamicSharedMemorySize, TC_SMEM);

    float *h, *q, *sc, *kcb, *vcb;
    u16 *gnh, *gnl, *yh, *yl, *qkvh, *qkvl, *vth_, *vtl_, *ath, *atl;
    u16 *hh, *hl, *ph, *pl, *ffh, *ffl, *w1h, *w1l, *w2h, *w2l, *wth, *wtl;
    cudaGetSymbolAddress((void**)&h,   g_h);
    cudaGetSymbolAddress((void**)&q,   g_q);
    cudaGetSymbolAddress((void**)&sc,  g_sc);
    cudaGetSymbolAddress((void**)&kcb, g_kc);
    cudaGetSymbolAddress((void**)&vcb, g_vc);
    cudaGetSymbolAddress((void**)&gnh, g_gnh); cudaGetSymbolAddress((void**)&gnl, g_gnl);
    cudaGetSymbolAddress((void**)&yh,  g_yh);  cudaGetSymbolAddress((void**)&yl,  g_yl);
    cudaGetSymbolAddress((void**)&qkvh, g_qkvh); cudaGetSymbolAddress((void**)&qkvl, g_qkvl);
    cudaGetSymbolAddress((void**)&vth_, g_vth); cudaGetSymbolAddress((void**)&vtl_, g_vtl);
    cudaGetSymbolAddress((void**)&ath, g_ath); cudaGetSymbolAddress((void**)&atl, g_atl);
    cudaGetSymbolAddress((void**)&hh,  g_hh);  cudaGetSymbolAddress((void**)&hl,  g_hl);
    cudaGetSymbolAddress((void**)&ph,  g_ph);  cudaGetSymbolAddress((void**)&pl,  g_pl);
    cudaGetSymbolAddress((void**)&ffh, g_ffh); cudaGetSymbolAddress((void**)&ffl, g_ffl);
    cudaGetSymbolAddress((void**)&w1h, g_w1h); cudaGetSymbolAddress((void**)&w1l, g_w1l);
    cudaGetSymbolAddress((void**)&w2h, g_w2h); cudaGetSymbolAddress((void**)&w2l, g_w2l);
    cudaGetSymbolAddress((void**)&wth, g_wth); cudaGetSymbolAddress((void**)&wtl, g_wtl);

    const long long BIG = 1LL << 62;
    const long long TI = (long long)Tt * Ii;
    const long long T3I = (long long)Tt * 3 * Ii;
    const long long WSZ = (long long)Ii * Ii;
    const unsigned WB = (unsigned)((WSZ + 255) / 256);

    split_ew<<<WB, 256>>>(pin_w,  wth + 6 * WSZ, wtl + 6 * WSZ, WSZ);
    split_ew<<<WB, 256>>>(pout_w, wth + 7 * WSZ, wtl + 7 * WSZ, WSZ);

    groupnorm_kernel<<<Bb * 32, 256>>>(x, gn_s, gn_b, gnh, gnl);  // writes gnT [b][t][c]

    // proj_in: h[b,t,:] = pin_w . gnT[b,t,:] + pin_b  (NT=64: 384 blocks)
    tc(gnh, gnl, wth + 6 * WSZ, wtl + 6 * WSZ, pin_b, h, 0, 0,
       Ii / 64, Tt / 128, Bb, Cc, Cc, Cc, Ii, 64, FBN | FOUT, 1.f,
       0, BIG, 1, (long long)Tt * Cc, 0, 0, 0, TI, 0);

    for (int d = 0; d < Dd; ++d) {
        long long wofs = (long long)d * WSZ;
        dim3 tg(24, 24), tb(32, 8);
        splitT768<<<tg, tb>>>(a1_wq + wofs, wth + 0 * WSZ, wtl + 0 * WSZ);
        splitT768<<<tg, tb>>>(a1_wk + wofs, wth + 1 * WSZ, wtl + 1 * WSZ);
        splitT768<<<tg, tb>>>(a1_wv + wofs, wth + 2 * WSZ, wtl + 2 * WSZ);
        splitT768<<<tg, tb>>>(a1_wo + wofs, wth + 3 * WSZ, wtl + 3 * WSZ);
        splitT768<<<tg, tb>>>(a2_wq + wofs, wth + 4 * WSZ, wtl + 4 * WSZ);
        splitT768<<<tg, tb>>>(a2_wo + wofs, wth + 5 * WSZ, wtl + 5 * WSZ);
        {
            long long t1 = (long long)Fi * Ii * Ksz;
            reorder_split<<<(unsigned)((t1 + 255) / 256), 256>>>(ff1_w + d * t1, w1h, w1l, t1, Ii);
            long long t2 = (long long)Ii * Fi * Ksz;
            reorder_split<<<(unsigned)((t2 + 255) / 256), 256>>>(ff2_w + d * t2, w2h, w2l, t2, Fi);
        }

        // --- self attention ---
        layernorm_kernel<<<Bb * Tt, 256>>>(h, n1_s + d * Ii, n1_b + d * Ii, yh, yl);
        // fused QKV (576 blocks, NT=128)
        tc(yh, yl, wth, wtl, 0, sc, qkvh, qkvl, (3 * Ii) / 128, (Bb * Tt) / 128, 1,
           Ii, Ii, Ii, 3 * Ii, 128, FSPL, 1.f, 0, BIG, 1, 0, 0, 0, 0, 0, 0);
        {
            dim3 g(Tt / 32, Dh / 32, Bb * Hh);
            transposeV_kernel<<<g, dim3(32, 8)>>>(qkvh, qkvl, vth_, vtl_, 3 * Ii, 2 * Ii);
        }
        // scores = 0.125 q k^T per (b,h)
        tc(qkvh, qkvl, qkvh + Ii, qkvl + Ii, 0, sc, 0, 0,
           Tt / 128, Tt / 128, Bb * Hh, Dh, 3 * Ii, 3 * Ii, Tt, 128,
           FOUT, 0.125f, 0, BIG, Hh, T3I, Dh, T3I, Dh,
           (long long)Hh * Tt * Tt, (long long)Tt * Tt);
        softmax_kernel<<<Bb * Hh * Tt, 256>>>(sc, ph, pl);
        // att = P @ V per (b,h)
        tc(ph, pl, vth_, vtl_, 0, sc, ath, atl, 1, Tt / 128, Bb * Hh, Tt, Tt, Tt, Ii, 64,
           FSPL, 1.f, 0, BIG, Hh,
           (long long)Hh * Tt * Tt, (long long)Tt * Tt,
           (long long)Hh * Dh * Tt, (long long)Dh * Tt, TI, Dh);
        // h += att @ wo + bo (NT=64: 384 blocks)
        tc(ath, atl, wth + 3 * WSZ, wtl + 3 * WSZ, a1_bo + d * Ii, h, 0, 0,
           Ii / 64, (Bb * Tt) / 128, 1, Ii, Ii, Ii, Ii, 64,
           FBN | FADD, 1.f, 0, BIG, 1, 0, 0, 0, 0, 0, 0);

        // --- cross attention ---
        layernorm_kernel<<<Bb * Tt, 256>>>(h, n2_s + d * Ii, n2_b + d * Ii, yh, yl);
        tc(yh, yl, wth + 4 * WSZ, wtl + 4 * WSZ, 0, q, 0, 0, Ii / 64, (Bb * Tt) / 128, 1,
           Ii, Ii, Ii, Ii, 64, FOUT, 1.f, 0, BIG, 1, 0, 0, 0, 0, 0, 0);
        {
            dim3 g((Ii + 63) / 64, (Bb * Ss + 63) / 64);
            gemm_kernel<<<g, 256>>>(ctx, a2_wk + (long long)d * Cx * Ii, kcb,
                                    Bb * Ss, Ii, Cx, Cx, Ii, Ii);
            gemm_kernel<<<g, 256>>>(ctx, a2_wv + (long long)d * Cx * Ii, vcb,
                                    Bb * Ss, Ii, Cx, Cx, Ii, Ii);
        }
        crossattn_kernel<<<Bb * Hh * Tt / 8, 256>>>(q, kcb, vcb, ath, atl);
        tc(ath, atl, wth + 5 * WSZ, wtl + 5 * WSZ, a2_bo + d * Ii, h, 0, 0,
           Ii / 64, (Bb * Tt) / 128, 1, Ii, Ii, Ii, Ii, 64,
           FBN | FADD, 1.f, 0, BIG, 1, 0, 0, 0, 0, 0, 0);

        // --- feed-forward ---
        layernorm_kernel<<<Bb * Tt, 256>>>(h, n3_s + d * Ii, n3_b + d * Ii, yh, yl);
        // conv1: NT=128 (768 blocks, 5.2 waves)
        tc(yh, yl, w1h, w1l, ff1_b + d * Fi, sc, ffh, ffl, Fi / 128, Tt / 128, Bb,
           Ii * Ksz, Ii, Ii * Ksz, Fi, 128, FBN | FGELU | FSPL, 1.f,
           -(long long)4 * Ii, TI, 1, TI, 0, 0, 0, (long long)Tt * Fi, 0);
        // conv2: NT=64 (384 blocks, 2.6 waves instead of 1.3)
        tc(ffh, ffl, w2h, w2l, ff2_b + d * Ii, h, hh, hl, Ii / 64, Tt / 128, Bb,
           Fi * Ksz, Fi, Fi * Ksz, Ii, 64,
           FBN | FADD | (d == Dd - 1 ? FSPL : 0), 1.f,
           -(long long)4 * Fi, (long long)Tt * Fi, 1,
           (long long)Tt * Fi, 0, 0, 0, TI, 0);
    }

    // out = x + pout_w @ h^T + pout_b (NT=64: 384 blocks)
    cudaMemcpyAsync(out, x, (size_t)Bb * Cc * Tt * sizeof(float),
                    cudaMemcpyDeviceToDevice);
    tc(wth + 7 * WSZ, wtl + 7 * WSZ, hh, hl, pout_b, out, 0, 0,
       Tt / 64, Cc / 128, Bb, Ii, Ii, Ii, Tt, 64, FBM | FADD, 1.f,
       0, BIG, 1, 0, 0, TI, 0, (long long)Cc * Tt, 0);
}

// round 13
// speedup vs baseline: 3.3721x; 1.1112x over previous
#include <cuda_runtime.h>
#include <cuda_bf16.h>
#include <math.h>
#include <stdint.h>

#define Bb 2
#define Cc 768
#define Tt 2048
#define Ii 768
#define Hh 12
#define Dh 64
#define Ss 16
#define Cx 512
#define Fi 3072
#define Dd 2
#define Ksz 9

typedef __nv_bfloat16 bf16;
typedef unsigned short u16;

// ---------------- scratch ----------------
__device__ float g_h  [(long long)Bb*Tt*Ii];
__device__ float g_q  [(long long)Bb*Tt*Ii];
__device__ float g_sc [(long long)Bb*Hh*Tt*Tt];
__device__ float g_kc [(long long)Bb*Ss*Ii];
__device__ float g_vc [(long long)Bb*Ss*Ii];

__device__ u16 g_gnh[(long long)Bb*Cc*Tt], g_gnl[(long long)Bb*Cc*Tt];  // TRANSPOSED [b][t][c]
__device__ u16 g_yh [(long long)Bb*Tt*Ii], g_yl [(long long)Bb*Tt*Ii];
__device__ u16 g_qkvh[(long long)Bb*Tt*3*Ii], g_qkvl[(long long)Bb*Tt*3*Ii];
__device__ u16 g_vth[(long long)Bb*Ii*Tt], g_vtl[(long long)Bb*Ii*Tt];
__device__ u16 g_ath[(long long)Bb*Tt*Ii], g_atl[(long long)Bb*Tt*Ii];
__device__ u16 g_hh [(long long)Bb*Tt*Ii], g_hl [(long long)Bb*Tt*Ii];
__device__ u16 g_ph [(long long)Bb*Hh*Tt*Tt], g_pl [(long long)Bb*Hh*Tt*Tt];
__device__ u16 g_ffh[(long long)Bb*Tt*Fi], g_ffl[(long long)Bb*Tt*Fi];
__device__ u16 g_w1h[(long long)Fi*Ii*Ksz], g_w1l[(long long)Fi*Ii*Ksz];
__device__ u16 g_w2h[(long long)Ii*Fi*Ksz], g_w2l[(long long)Ii*Fi*Ksz];
__device__ u16 g_wth[8ll*Ii*Ii], g_wtl[8ll*Ii*Ii];

// ---------------- helpers ----------------
__device__ __forceinline__ uint32_t smem_u32(const void* p) {
    uint32_t a;
    asm("{ .reg .u64 t; cvta.to.shared.u64 t, %1; cvt.u32.u64 %0, t; }" : "=r"(a) : "l"(p));
    return a;
}
#define SWZ(x) ((x) ^ ((((uint32_t)(x)) >> 3) & 0x70))
#define CP16(dst, src) asm volatile("cp.async.cg.shared.global [%0], [%1], 16;" :: "r"(dst), "l"(src))
#define CPCOMMIT() asm volatile("cp.async.commit_group;" ::: "memory")
#define CPWAIT0() asm volatile("cp.async.wait_group 0;" ::: "memory")

__device__ __forceinline__ void ldsm4(uint32_t* r, uint32_t addr) {
    asm volatile("ldmatrix.sync.aligned.m8n8.x4.shared.b16 {%0,%1,%2,%3}, [%4];"
        : "=r"(r[0]), "=r"(r[1]), "=r"(r[2]), "=r"(r[3]) : "r"(addr));
}
__device__ __forceinline__ void mma16816(float* c, const uint32_t* a, const uint32_t* b) {
    asm volatile("mma.sync.aligned.m16n8k16.row.col.f32.bf16.bf16.f32 "
        "{%0,%1,%2,%3}, {%4,%5,%6,%7}, {%8,%9}, {%0,%1,%2,%3};"
        : "+f"(c[0]), "+f"(c[1]), "+f"(c[2]), "+f"(c[3])
        : "r"(a[0]), "r"(a[1]), "r"(a[2]), "r"(a[3]), "r"(b[0]), "r"(b[1]));
}
__device__ __forceinline__ void splitf(float x, u16& h, u16& l) {
    bf16 hb = __float2bfloat16(x);
    bf16 lb = __float2bfloat16(x - __bfloat162float(hb));
    h = __bfloat16_as_ushort(hb);
    l = __bfloat16_as_ushort(lb);
}

// flags
#define FBN   4
#define FBM   8
#define FGELU 16
#define FADD  32
#define FOUT  64
#define FSPL  128

#define NTHREADS 256
// stage: A 32KB (hi+lo) + B 16KB (hi+lo) = 48KB; 2 stages = 96KB
#define STG_BYTES (49152)
#define TC_SMEM (2*STG_BYTES + 1024)

// stage 16B segments via cp.async (non-trans): op[r][k] = G[off0 + r*ld + k]
__device__ __forceinline__ void stage_nt(const u16* __restrict__ Gh, const u16* __restrict__ Gl,
        long long off0, long long flim, int ld, int k0, int rows,
        uint32_t smh, uint32_t sml) {
    int nseg = rows * 8;
    for (int idx = threadIdx.x; idx < nseg; idx += NTHREADS) {
        int r = idx >> 3, s = idx & 7;
        long long f = off0 + (long long)r * ld + k0 + s * 8;
        uint32_t d = SWZ((uint32_t)(r * 128 + s * 16));
        if (f >= 0 && f + 8 <= flim) {
            CP16(smh + d, Gh + f);
            CP16(sml + d, Gl + f);
        } else {
            asm volatile("st.shared.v4.u32 [%0], {%1,%1,%1,%1};" :: "r"(smh + d), "r"(0));
            asm volatile("st.shared.v4.u32 [%0], {%1,%1,%1,%1};" :: "r"(sml + d), "r"(0));
        }
    }
}

// ===== tensor-core GEMM: 256 threads, 4x2 warp grid, 2-stage, 2 CTAs/SM =====
// tile 128 x 64, warp tile 32 x 32
__global__ void __launch_bounds__(NTHREADS, 2)
tc_gemm(const u16* __restrict__ Ah, const u16* __restrict__ Al,
        const u16* __restrict__ Bh, const u16* __restrict__ Bl,
        const float* __restrict__ bias, float* __restrict__ out,
        u16* __restrict__ oh, u16* __restrict__ ol,
        int K, int lda, int ldb, long long ldo, int flags, float alpha,
        long long offA, long long flimA, int b2,
        long long sA1, long long sA2, long long sB1, long long sB2,
        long long sC1, long long sC2)
{
    extern __shared__ char dynsm[];
    long long z1 = blockIdx.z / b2, z2 = blockIdx.z % b2;
    Ah += z1 * sA1 + z2 * sA2;  Al += z1 * sA1 + z2 * sA2;
    Bh += z1 * sB1 + z2 * sB2;  Bl += z1 * sB1 + z2 * sB2;
    long long zc = z1 * sC1 + z2 * sC2;
    out += zc;
    if (flags & FSPL) { oh += zc; ol += zc; }

    const int tid = threadIdx.x;
    const int lane = tid & 31;
    const int wid = tid >> 5;                 // 0..7
    const int wm = (wid & 3) * 32;            // 4 M-warps
    const int wn = (wid >> 2) * 32;           // 2 N-warps
    const int ksrot = (wid >> 2) << 1;        // phase stagger (0 / 2)
    const int m0 = blockIdx.y * 128;
    const int n0 = blockIdx.x * 64;
    constexpr int NTW = 4;                    // n8 tiles per warp
    constexpr int NB = 2;                     // 16-col pairs
    constexpr int ASZ = 32768;                // A hi+lo bytes

    uint32_t smBase = smem_u32(dynsm);
    smBase = (smBase + 1023) & ~1023u;

    const long long aoff = offA + (long long)m0 * lda;
    const long long boff = (long long)n0 * ldb;
    const long long BIGL = 1LL << 62;
    const int nc = K / 64;

    float acc[2][NTW][4];
    #pragma unroll
    for (int i = 0; i < 2; ++i)
        #pragma unroll
        for (int j = 0; j < NTW; ++j)
            #pragma unroll
            for (int l = 0; l < 4; ++l) acc[i][j][l] = 0.f;

    const uint32_t aRow = wm + (lane & 15);
    const uint32_t aKof = (lane >> 4) << 3;
    const int bi = lane >> 3;
    const uint32_t bRowBase = wn + ((bi >> 1) << 3) + (lane & 7);
    const uint32_t bKof = (bi & 1) << 3;

    auto stage = [&](int c, int s) {
        uint32_t base = smBase + s * STG_BYTES;
        stage_nt(Ah, Al, aoff, flimA, lda, c * 64, 128, base, base + 16384);
        stage_nt(Bh, Bl, boff, BIGL, ldb, c * 64, 64, base + ASZ, base + ASZ + 8192);
        CPCOMMIT();
    };

    // prologue: chunk 0
    stage(0, 0);
    CPWAIT0();
    __syncthreads();

    for (int c = 0; c < nc; ++c) {
        if (c + 1 < nc) stage(c + 1, (c + 1) & 1);   // issued at top, waited at bottom
        uint32_t base = smBase + (c & 1) * STG_BYTES;
        const uint32_t aHi = base, aLo = base + 16384;
        const uint32_t bHi = base + ASZ, bLo = base + ASZ + 8192;
        #pragma unroll
        for (int ki = 0; ki < 4; ++ki) {
            const int ks = (ki + ksrot) & 3;
            const uint32_t kb = ks * 16;
            uint32_t ah[2][4], al[2][4], bh[NB][4], bl[NB][4];
            #pragma unroll
            for (int mt = 0; mt < 2; ++mt) {
                uint32_t off = SWZ((aRow + mt * 16) * 128 + (kb + aKof) * 2);
                ldsm4(ah[mt], aHi + off);
                ldsm4(al[mt], aLo + off);
            }
            #pragma unroll
            for (int bp = 0; bp < NB; ++bp) {
                uint32_t off = SWZ((bRowBase + bp * 16) * 128 + (kb + bKof) * 2);
                ldsm4(bh[bp], bHi + off);
                ldsm4(bl[bp], bLo + off);
            }
            #pragma unroll
            for (int bp = 0; bp < NB; ++bp)
                #pragma unroll
                for (int mt = 0; mt < 2; ++mt) {
                    mma16816(acc[mt][2 * bp],     ah[mt], bh[bp]);
                    mma16816(acc[mt][2 * bp + 1], ah[mt], bh[bp] + 2);
                }
            #pragma unroll
            for (int bp = 0; bp < NB; ++bp)
                #pragma unroll
                for (int mt = 0; mt < 2; ++mt) {
                    mma16816(acc[mt][2 * bp],     al[mt], bh[bp]);
                    mma16816(acc[mt][2 * bp + 1], al[mt], bh[bp] + 2);
                }
            #pragma unroll
            for (int bp = 0; bp < NB; ++bp)
                #pragma unroll
                for (int mt = 0; mt < 2; ++mt) {
                    mma16816(acc[mt][2 * bp],     ah[mt], bl[bp]);
                    mma16816(acc[mt][2 * bp + 1], ah[mt], bl[bp] + 2);
                }
        }
        if (c + 1 < nc) { CPWAIT0(); __syncthreads(); }
    }

    // epilogue
    const int g = lane >> 2, tg = lane & 3;
    #pragma unroll
    for (int mt = 0; mt < 2; ++mt) {
        #pragma unroll
        for (int hf = 0; hf < 2; ++hf) {
            int m = m0 + wm + mt * 16 + g + hf * 8;
            float bm = (flags & FBM) ? bias[m] : 0.f;
            long long rbase = (long long)m * ldo;
            #pragma unroll
            for (int nt = 0; nt < NTW; ++nt) {
                int n = n0 + wn + nt * 8 + tg * 2;
                float v0 = alpha * acc[mt][nt][hf * 2 + 0];
                float v1 = alpha * acc[mt][nt][hf * 2 + 1];
                if (flags & FBN) { v0 += bias[n]; v1 += bias[n + 1]; }
                else if (flags & FBM) { v0 += bm; v1 += bm; }
                if (flags & FGELU) {
                    v0 = 0.5f * v0 * (1.f + erff(v0 * 0.70710678118654752f));
                    v1 = 0.5f * v1 * (1.f + erff(v1 * 0.70710678118654752f));
                }
                if (flags & FADD) { v0 += out[rbase + n]; v1 += out[rbase + n + 1]; }
                if (flags & (FOUT | FADD)) { out[rbase + n] = v0; out[rbase + n + 1] = v1; }
                if (flags & FSPL) {
                    u16 h0, l0, h1, l1;
                    splitf(v0, h0, l0);
                    splitf(v1, h1, l1);
                    oh[rbase + n] = h0; ol[rbase + n] = l0;
                    oh[rbase + n + 1] = h1; ol[rbase + n + 1] = l1;
                }
            }
        }
    }
}

// ---------------- reductions ----------------
__device__ __forceinline__ float blockReduceSum(float v) {
    __shared__ float sm[32];
    int lane = threadIdx.x & 31, wid = threadIdx.x >> 5;
    #pragma unroll
    for (int o = 16; o; o >>= 1) v += __shfl_xor_sync(0xffffffffu, v, o);
    if (lane == 0) sm[wid] = v;
    __syncthreads();
    if (wid == 0) {
        int nw = (blockDim.x + 31) >> 5;
        v = (lane < nw) ? sm[lane] : 0.f;
        #pragma unroll
        for (int o = 16; o; o >>= 1) v += __shfl_xor_sync(0xffffffffu, v, o);
        if (lane == 0) sm[0] = v;
    }
    __syncthreads();
    float r = sm[0];
    __syncthreads();
    return r;
}
__device__ __forceinline__ float blockReduceMax(float v) {
    __shared__ float sm[32];
    int lane = threadIdx.x & 31, wid = threadIdx.x >> 5;
    #pragma unroll
    for (int o = 16; o; o >>= 1) v = fmaxf(v, __shfl_xor_sync(0xffffffffu, v, o));
    if (lane == 0) sm[wid] = v;
    __syncthreads();
    if (wid == 0) {
        int nw = (blockDim.x + 31) >> 5;
        v = (lane < nw) ? sm[lane] : -INFINITY;
        #pragma unroll
        for (int o = 16; o; o >>= 1) v = fmaxf(v, __shfl_xor_sync(0xffffffffu, v, o));
        if (lane == 0) sm[0] = v;
    }
    __syncthreads();
    float r = sm[0];
    __syncthreads();
    return r;
}

// groupnorm: writes split output TRANSPOSED: gnT[b][t][c]
__global__ void groupnorm_kernel(const float* __restrict__ x, const float* __restrict__ sc,
                                 const float* __restrict__ bi,
                                 u16* __restrict__ oh, u16* __restrict__ ol) {
    const int CPG = Cc / 32;
    int b = blockIdx.x >> 5, g = blockIdx.x & 31;
    const long long base = ((long long)b * Cc + (long long)g * CPG) * Tt;
    const float* xp = x + base;
    const int n = CPG * Tt;
    float s = 0.f, ss = 0.f;
    for (int i = threadIdx.x; i < n; i += blockDim.x) {
        float v = xp[i]; s += v; ss = fmaf(v, v, ss);
    }
    s = blockReduceSum(s); ss = blockReduceSum(ss);
    float mean = s / n;
    float inv = rsqrtf(ss / n - mean * mean + 1e-6f);
    const long long obase = (long long)b * Tt * Cc + g * CPG;
    for (int j = threadIdx.x; j < n; j += blockDim.x) {
        int t = j / CPG, cc2 = j - t * CPG;
        float v = (xp[(long long)cc2 * Tt + t] - mean) * inv * sc[g * CPG + cc2] + bi[g * CPG + cc2];
        u16 hv, lv; splitf(v, hv, lv);
        long long o = obase + (long long)t * Cc + cc2;
        oh[o] = hv; ol[o] = lv;
    }
}

__global__ void layernorm_kernel(const float* __restrict__ x, const float* __restrict__ sc,
                                 const float* __restrict__ bi,
                                 u16* __restrict__ oh, u16* __restrict__ ol) {
    const long long rb = (long long)blockIdx.x * Ii;
    const float* row = x + rb;
    float s = 0.f, ss = 0.f;
    for (int i = threadIdx.x; i < Ii; i += blockDim.x) {
        float v = row[i]; s += v; ss = fmaf(v, v, ss);
    }
    s = blockReduceSum(s); ss = blockReduceSum(ss);
    float mean = s / (float)Ii;
    float inv = rsqrtf(ss / (float)Ii - mean * mean + 1e-5f);
    for (int i = threadIdx.x; i < Ii; i += blockDim.x) {
        float v = (row[i] - mean) * inv * sc[i] + bi[i];
        u16 hv, lv; splitf(v, hv, lv);
        oh[rb + i] = hv; ol[rb + i] = lv;
    }
}

// small fp32 gemm for tiny cross-attn K/V projections (M=32)
__global__ void __launch_bounds__(256) gemm_kernel(
    const float* __restrict__ A, const float* __restrict__ B, float* __restrict__ Cp,
    int M, int N, int K, int lda, int ldb, int ldc)
{
    __shared__ float As[16][65];
    __shared__ float Bs[16][65];
    int n0 = blockIdx.x * 64, m0 = blockIdx.y * 64;
    int tid = threadIdx.x;
    int tx = tid & 15, ty = tid >> 4;
    float acc[4][4] = {};
    for (int k0 = 0; k0 < K; k0 += 16) {
        #pragma unroll
        for (int u = 0; u < 4; ++u) {
            int i = tid + u * 256;
            int mm = i >> 4, kk = i & 15;
            int m = m0 + mm, k = k0 + kk;
            As[kk][mm] = (m < M && k < K) ? A[(long long)m * lda + k] : 0.f;
        }
        #pragma unroll
        for (int u = 0; u < 4; ++u) {
            int i = tid + u * 256;
            int kk = i >> 6, nn = i & 63;
            int k = k0 + kk, n = n0 + nn;
            Bs[kk][nn] = (k < K && n < N) ? B[(long long)k * ldb + n] : 0.f;
        }
        __syncthreads();
        #pragma unroll
        for (int kk = 0; kk < 16; ++kk) {
            float a[4], bb[4];
            #pragma unroll
            for (int i = 0; i < 4; ++i) a[i] = As[kk][ty * 4 + i];
            #pragma unroll
            for (int j = 0; j < 4; ++j) bb[j] = Bs[kk][tx * 4 + j];
            #pragma unroll
            for (int i = 0; i < 4; ++i)
                #pragma unroll
                for (int j = 0; j < 4; ++j)
                    acc[i][j] = fmaf(a[i], bb[j], acc[i][j]);
        }
        __syncthreads();
    }
    #pragma unroll
    for (int i = 0; i < 4; ++i) {
        int m = m0 + ty * 4 + i;
        if (m >= M) continue;
        #pragma unroll
        for (int j = 0; j < 4; ++j) {
            int n = n0 + tx * 4 + j;
            if (n < N) Cp[(long long)m * ldc + n] = acc[i][j];
        }
    }
}

__global__ void softmax_kernel(const float* __restrict__ s,
                               u16* __restrict__ oh, u16* __restrict__ ol) {
    const long long rb = (long long)blockIdx.x * Tt;
    const float* row = s + rb;
    int tid = threadIdx.x;
    float v[8];
    float mx = -INFINITY;
    #pragma unroll
    for (int i = 0; i < 8; ++i) { v[i] = row[tid + (i << 8)]; mx = fmaxf(mx, v[i]); }
    mx = blockReduceMax(mx);
    float sum = 0.f;
    #pragma unroll
    for (int i = 0; i < 8; ++i) { v[i] = expf(v[i] - mx); sum += v[i]; }
    sum = blockReduceSum(sum);
    float inv = 1.f / sum;
    #pragma unroll
    for (int i = 0; i < 8; ++i) {
        u16 hv, lv; splitf(v[i] * inv, hv, lv);
        oh[rb + tid + (i << 8)] = hv;
        ol[rb + tid + (i << 8)] = lv;
    }
}

__global__ void crossattn_kernel(const float* __restrict__ q, const float* __restrict__ kc,
                                 const float* __restrict__ vc,
                                 u16* __restrict__ oh, u16* __restrict__ ol) {
    int gw = blockIdx.x * (blockDim.x >> 5) + (threadIdx.x >> 5);
    int lane = threadIdx.x & 31;
    int t = gw % Tt;
    int rem = gw / Tt;
    int h = rem % Hh;
    int b = rem / Hh;
    const float* qp = q + ((long long)(b * Tt + t)) * Ii + h * Dh;
    const float* kb = kc + (long long)b * Ss * Ii + h * Dh;
    const float* vb = vc + (long long)b * Ss * Ii + h * Dh;
    float sj = -INFINITY;
    if (lane < Ss) {
        const float* kp = kb + lane * Ii;
        float acc = 0.f;
        #pragma unroll
        for (int d2 = 0; d2 < Dh; ++d2) acc = fmaf(qp[d2], kp[d2], acc);
        sj = acc * 0.125f;
    }
    float mx = sj;
    #pragma unroll
    for (int o = 16; o; o >>= 1) mx = fmaxf(mx, __shfl_xor_sync(0xffffffffu, mx, o));
    float p = (lane < Ss) ? expf(sj - mx) : 0.f;
    float sum = p;
    #pragma unroll
    for (int o = 16; o; o >>= 1) sum += __shfl_xor_sync(0xffffffffu, sum, o);
    p /= sum;
    float o0 = 0.f, o1 = 0.f;
    #pragma unroll
    for (int j = 0; j < Ss; ++j) {
        float pj = __shfl_sync(0xffffffffu, p, j);
        const float* vp = vb + j * Ii;
        o0 = fmaf(pj, vp[lane], o0);
        o1 = fmaf(pj, vp[lane + 32], o1);
    }
    long long ob = ((long long)(b * Tt + t)) * Ii + h * Dh;
    u16 hv, lv;
    splitf(o0, hv, lv); oh[ob + lane] = hv; ol[ob + lane] = lv;
    splitf(o1, hv, lv); oh[ob + lane + 32] = hv; ol[ob + lane + 32] = lv;
}

// per-head transpose of split V (src row stride ld, col offset off)
__global__ void transposeV_kernel(const u16* __restrict__ vh, const u16* __restrict__ vl,
                                  u16* __restrict__ oth, u16* __restrict__ otl,
                                  int ld, int off) {
    __shared__ u16 th[32][33], tl[32][33];
    int bh = blockIdx.z;
    int b = bh / Hh, h = bh % Hh;
    int t0 = blockIdx.x * 32, d0 = blockIdx.y * 32;
    #pragma unroll
    for (int i = 0; i < 32; i += 8) {
        long long src = ((long long)(b * Tt + t0 + threadIdx.y + i)) * ld + off + h * Dh + d0 + threadIdx.x;
        th[threadIdx.y + i][threadIdx.x] = vh[src];
        tl[threadIdx.y + i][threadIdx.x] = vl[src];
    }
    __syncthreads();
    #pragma unroll
    for (int i = 0; i < 32; i += 8) {
        long long dst = ((long long)((b * Hh + h) * Dh + d0 + threadIdx.y + i)) * Tt + t0 + threadIdx.x;
        oth[dst] = th[threadIdx.x][threadIdx.y + i];
        otl[dst] = tl[threadIdx.x][threadIdx.y + i];
    }
}

// elementwise split fp32 -> bf16 hi/lo
__global__ void split_ew(const float* __restrict__ w, u16* __restrict__ oh,
                         u16* __restrict__ ol, long long n) {
    long long i = (long long)blockIdx.x * 256 + threadIdx.x;
    if (i >= n) return;
    u16 hv, lv; splitf(w[i], hv, lv);
    oh[i] = hv; ol[i] = lv;
}

// transpose 768x768 [K][N] -> [N][K] + split
__global__ void splitT768(const float* __restrict__ w, u16* __restrict__ oh,
                          u16* __restrict__ ol) {
    __shared__ float t[32][33];
    int k0 = blockIdx.y * 32, n0 = blockIdx.x * 32;
    #pragma unroll
    for (int i = 0; i < 32; i += 8)
        t[threadIdx.y + i][threadIdx.x] = w[(long long)(k0 + threadIdx.y + i) * Ii + n0 + threadIdx.x];
    __syncthreads();
    #pragma unroll
    for (int i = 0; i < 32; i += 8) {
        long long o = (long long)(n0 + threadIdx.y + i) * Ii + k0 + threadIdx.x;
        u16 hv, lv; splitf(t[threadIdx.x][threadIdx.y + i], hv, lv);
        oh[o] = hv; ol[o] = lv;
    }
}

// conv weight reorder+split: out[o][k*Cin+c] = in[o][c*Ksz+k]
__global__ void reorder_split(const float* __restrict__ w, u16* __restrict__ oh,
                              u16* __restrict__ ol, long long total, int Cin) {
    long long i = (long long)blockIdx.x * 256 + threadIdx.x;
    if (i >= total) return;
    int rk = Cin * Ksz;
    long long oc = i / rk;
    int r = (int)(i - oc * rk);
    int k = r / Cin, c = r - k * Cin;
    u16 hv, lv; splitf(w[oc * rk + (long long)c * Ksz + k], hv, lv);
    oh[i] = hv; ol[i] = lv;
}

// ---------------- host wrapper ----------------
static void tc(const u16* Ah, const u16* Al, const u16* Bh, const u16* Bl,
               const float* bias, float* out, u16* oh, u16* ol,
               int gx, int gy, int gz, int K, int lda, int ldb, long long ldo,
               int flags, float alpha, long long offA, long long flimA,
               int b2, long long sA1, long long sA2, long long sB1, long long sB2,
               long long sC1, long long sC2)
{
    dim3 g(gx, gy, gz);
    tc_gemm<<<g, NTHREADS, TC_SMEM>>>(Ah, Al, Bh, Bl, bias, out, oh, ol, K, lda, ldb,
        ldo, flags, alpha, offA, flimA, b2, sA1, sA2, sB1, sB2, sC1, sC2);
}

extern "C" void kernel_launch(void* const* d_in, const int* in_sizes, int n_in,
                              void* d_out, int out_size) {
    const float* x      = (const float*)d_in[0];
    const float* ctx    = (const float*)d_in[1];
    const float* gn_s   = (const float*)d_in[2];
    const float* gn_b   = (const float*)d_in[3];
    const float* pin_w  = (const float*)d_in[4];
    const float* pin_b  = (const float*)d_in[5];
    const float* n1_s   = (const float*)d_in[6];
    const float* n1_b   = (const float*)d_in[7];
    const float* a1_wq  = (const float*)d_in[8];
    const float* a1_wk  = (const float*)d_in[9];
    const float* a1_wv  = (const float*)d_in[10];
    const float* a1_wo  = (const float*)d_in[11];
    const float* a1_bo  = (const float*)d_in[12];
    const float* n2_s   = (const float*)d_in[13];
    const float* n2_b   = (const float*)d_in[14];
    const float* a2_wq  = (const float*)d_in[15];
    const float* a2_wk  = (const float*)d_in[16];
    const float* a2_wv  = (const float*)d_in[17];
    const float* a2_wo  = (const float*)d_in[18];
    const float* a2_bo  = (const float*)d_in[19];
    const float* n3_s   = (const float*)d_in[20];
    const float* n3_b   = (const float*)d_in[21];
    const float* ff1_w  = (const float*)d_in[22];
    const float* ff1_b  = (const float*)d_in[23];
    const float* ff2_w  = (const float*)d_in[24];
    const float* ff2_b  = (const float*)d_in[25];
    const float* pout_w = (const float*)d_in[26];
    const float* pout_b = (const float*)d_in[27];
    float* out = (float*)d_out;

    cudaFuncSetAttribute(tc_gemm, cudaFuncAttributeMaxDynamicSharedMemorySize, TC_SMEM);

    float *h, *q, *sc, *kcb, *vcb;
    u16 *gnh, *gnl, *yh, *yl, *qkvh, *qkvl, *vth_, *vtl_, *ath, *atl;
    u16 *hh, *hl, *ph, *pl, *ffh, *ffl, *w1h, *w1l, *w2h, *w2l, *wth, *wtl;
    cudaGetSymbolAddress((void**)&h,   g_h);
    cudaGetSymbolAddress((void**)&q,   g_q);
    cudaGetSymbolAddress((void**)&sc,  g_sc);
    cudaGetSymbolAddress((void**)&kcb, g_kc);
    cudaGetSymbolAddress((void**)&vcb, g_vc);
    cudaGetSymbolAddress((void**)&gnh, g_gnh); cudaGetSymbolAddress((void**)&gnl, g_gnl);
    cudaGetSymbolAddress((void**)&yh,  g_yh);  cudaGetSymbolAddress((void**)&yl,  g_yl);
    cudaGetSymbolAddress((void**)&qkvh, g_qkvh); cudaGetSymbolAddress((void**)&qkvl, g_qkvl);
    cudaGetSymbolAddress((void**)&vth_, g_vth); cudaGetSymbolAddress((void**)&vtl_, g_vtl);
    cudaGetSymbolAddress((void**)&ath, g_ath); cudaGetSymbolAddress((void**)&atl, g_atl);
    cudaGetSymbolAddress((void**)&hh,  g_hh);  cudaGetSymbolAddress((void**)&hl,  g_hl);
    cudaGetSymbolAddress((void**)&ph,  g_ph);  cudaGetSymbolAddress((void**)&pl,  g_pl);
    cudaGetSymbolAddress((void**)&ffh, g_ffh); cudaGetSymbolAddress((void**)&ffl, g_ffl);
    cudaGetSymbolAddress((void**)&w1h, g_w1h); cudaGetSymbolAddress((void**)&w1l, g_w1l);
    cudaGetSymbolAddress((void**)&w2h, g_w2h); cudaGetSymbolAddress((void**)&w2l, g_w2l);
    cudaGetSymbolAddress((void**)&wth, g_wth); cudaGetSymbolAddress((void**)&wtl, g_wtl);

    const long long BIG = 1LL << 62;
    const long long TI = (long long)Tt * Ii;
    const long long T3I = (long long)Tt * 3 * Ii;
    const long long WSZ = (long long)Ii * Ii;
    const unsigned WB = (unsigned)((WSZ + 255) / 256);

    split_ew<<<WB, 256>>>(pin_w,  wth + 6 * WSZ, wtl + 6 * WSZ, WSZ);
    split_ew<<<WB, 256>>>(pout_w, wth + 7 * WSZ, wtl + 7 * WSZ, WSZ);

    groupnorm_kernel<<<Bb * 32, 256>>>(x, gn_s, gn_b, gnh, gnl);  // writes gnT [b][t][c]

    // proj_in
    tc(gnh, gnl, wth + 6 * WSZ, wtl + 6 * WSZ, pin_b, h, 0, 0,
       Ii / 64, Tt / 128, Bb, Cc, Cc, Cc, Ii, FBN | FOUT, 1.f,
       0, BIG, 1, (long long)Tt * Cc, 0, 0, 0, TI, 0);

    for (int d = 0; d < Dd; ++d) {
        long long wofs = (long long)d * WSZ;
        dim3 tg(24, 24), tb(32, 8);
        splitT768<<<tg, tb>>>(a1_wq + wofs, wth + 0 * WSZ, wtl + 0 * WSZ);
        splitT768<<<tg, tb>>>(a1_wk + wofs, wth + 1 * WSZ, wtl + 1 * WSZ);
        splitT768<<<tg, tb>>>(a1_wv + wofs, wth + 2 * WSZ, wtl + 2 * WSZ);
        splitT768<<<tg, tb>>>(a1_wo + wofs, wth + 3 * WSZ, wtl + 3 * WSZ);
        splitT768<<<tg, tb>>>(a2_wq + wofs, wth + 4 * WSZ, wtl + 4 * WSZ);
        splitT768<<<tg, tb>>>(a2_wo + wofs, wth + 5 * WSZ, wtl + 5 * WSZ);
        {
            long long t1 = (long long)Fi * Ii * Ksz;
            reorder_split<<<(unsigned)((t1 + 255) / 256), 256>>>(ff1_w + d * t1, w1h, w1l, t1, Ii);
            long long t2 = (long long)Ii * Fi * Ksz;
            reorder_split<<<(unsigned)((t2 + 255) / 256), 256>>>(ff2_w + d * t2, w2h, w2l, t2, Fi);
        }

        // --- self attention ---
        layernorm_kernel<<<Bb * Tt, 256>>>(h, n1_s + d * Ii, n1_b + d * Ii, yh, yl);
        // fused QKV
        tc(yh, yl, wth, wtl, 0, sc, qkvh, qkvl, (3 * Ii) / 64, (Bb * Tt) / 128, 1,
           Ii, Ii, Ii, 3 * Ii, FSPL, 1.f, 0, BIG, 1, 0, 0, 0, 0, 0, 0);
        {
            dim3 g(Tt / 32, Dh / 32, Bb * Hh);
            transposeV_kernel<<<g, dim3(32, 8)>>>(qkvh, qkvl, vth_, vtl_, 3 * Ii, 2 * Ii);
        }
        // scores = 0.125 q k^T per (b,h)
        tc(qkvh, qkvl, qkvh + Ii, qkvl + Ii, 0, sc, 0, 0,
           Tt / 64, Tt / 128, Bb * Hh, Dh, 3 * Ii, 3 * Ii, Tt,
           FOUT, 0.125f, 0, BIG, Hh, T3I, Dh, T3I, Dh,
           (long long)Hh * Tt * Tt, (long long)Tt * Tt);
        softmax_kernel<<<Bb * Hh * Tt, 256>>>(sc, ph, pl);
        // att = P @ V per (b,h)
        tc(ph, pl, vth_, vtl_, 0, sc, ath, atl, 1, Tt / 128, Bb * Hh, Tt, Tt, Tt, Ii,
           FSPL, 1.f, 0, BIG, Hh,
           (long long)Hh * Tt * Tt, (long long)Tt * Tt,
           (long long)Hh * Dh * Tt, (long long)Dh * Tt, TI, Dh);
        // h += att @ wo + bo
        tc(ath, atl, wth + 3 * WSZ, wtl + 3 * WSZ, a1_bo + d * Ii, h, 0, 0,
           Ii / 64, (Bb * Tt) / 128, 1, Ii, Ii, Ii, Ii,
           FBN | FADD, 1.f, 0, BIG, 1, 0, 0, 0, 0, 0, 0);

        // --- cross attention ---
        layernorm_kernel<<<Bb * Tt, 256>>>(h, n2_s + d * Ii, n2_b + d * Ii, yh, yl);
        tc(yh, yl, wth + 4 * WSZ, wtl + 4 * WSZ, 0, q, 0, 0, Ii / 64, (Bb * Tt) / 128, 1,
           Ii, Ii, Ii, Ii, FOUT, 1.f, 0, BIG, 1, 0, 0, 0, 0, 0, 0);
        {
            dim3 g((Ii + 63) / 64, (Bb * Ss + 63) / 64);
            gemm_kernel<<<g, 256>>>(ctx, a2_wk + (long long)d * Cx * Ii, kcb,
                                    Bb * Ss, Ii, Cx, Cx, Ii, Ii);
            gemm_kernel<<<g, 256>>>(ctx, a2_wv + (long long)d * Cx * Ii, vcb,
                                    Bb * Ss, Ii, Cx, Cx, Ii, Ii);
        }
        crossattn_kernel<<<Bb * Hh * Tt / 8, 256>>>(q, kcb, vcb, ath, atl);
        tc(ath, atl, wth + 5 * WSZ, wtl + 5 * WSZ, a2_bo + d * Ii, h, 0, 0,
           Ii / 64, (Bb * Tt) / 128, 1, Ii, Ii, Ii, Ii,
           FBN | FADD, 1.f, 0, BIG, 1, 0, 0, 0, 0, 0, 0);

        // --- feed-forward ---
        layernorm_kernel<<<Bb * Tt, 256>>>(h, n3_s + d * Ii, n3_b + d * Ii, yh, yl);
        tc(yh, yl, w1h, w1l, ff1_b + d * Fi, sc, ffh, ffl, Fi / 64, Tt / 128, Bb,
           Ii * Ksz, Ii, Ii * Ksz, Fi, FBN | FGELU | FSPL, 1.f,
           -(long long)4 * Ii, TI, 1, TI, 0, 0, 0, (long long)Tt * Fi, 0);
        tc(ffh, ffl, w2h, w2l, ff2_b + d * Ii, h, hh, hl, Ii / 64, Tt / 128, Bb,
           Fi * Ksz, Fi, Fi * Ksz, Ii,
           FBN | FADD | (d == Dd - 1 ? FSPL : 0), 1.f,
           -(long long)4 * Fi, (long long)Tt * Fi, 1,
           (long long)Tt * Fi, 0, 0, 0, TI, 0);
    }

    // out = x + pout_w @ h^T + pout_b
    cudaMemcpyAsync(out, x, (size_t)Bb * Cc * Tt * sizeof(float),
                    cudaMemcpyDeviceToDevice);
    tc(wth + 7 * WSZ, wtl + 7 * WSZ, hh, hl, pout_b, out, 0, 0,
       Tt / 64, Cc / 128, Bb, Ii, Ii, Ii, Tt, FBM | FADD, 1.f,
       0, BIG, 1, 0, 0, TI, 0, (long long)Cc * Tt, 0);
}